// round 5
// baseline (speedup 1.0000x reference)
#include <cuda_runtime.h>
#include <cstdint>

#define NB 8
#define NT 2048
#define NE 1024
#define ND 1024

constexpr size_t SZ_X = (size_t)NB * NT * NE;   // 16.7M elems
constexpr size_t SZ_W = (size_t)NE * ND;
constexpr size_t SZ_S = (size_t)NB * NT * NT;

// ---- static scratch pool ----
constexpr size_t OFF_X0  = 0;
constexpr size_t OFF_X1  = OFF_X0  + SZ_X;
constexpr size_t OFF_SX  = OFF_X1  + SZ_X;
constexpr size_t OFF_WTF = OFF_SX  + 16384 * 4;
constexpr size_t OFF_WQ0 = OFF_WTF + SZ_W * 4;
constexpr size_t OFF_WQ1 = OFF_WQ0 + SZ_W;
constexpr size_t OFF_SWQ = OFF_WQ1 + SZ_W;
constexpr size_t OFF_WK0 = OFF_SWQ + ND * 4;
constexpr size_t OFF_WK1 = OFF_WK0 + SZ_W;
constexpr size_t OFF_SWK = OFF_WK1 + SZ_W;
constexpr size_t OFF_WV0 = OFF_SWK + ND * 4;
constexpr size_t OFF_WV1 = OFF_WV0 + SZ_W;
constexpr size_t OFF_SWV = OFF_WV1 + SZ_W;
constexpr size_t OFF_QF  = OFF_SWV + ND * 4;
constexpr size_t OFF_KF  = OFF_QF  + SZ_X * 4;
constexpr size_t OFF_VTF = OFF_KF  + SZ_X * 4;
constexpr size_t OFF_Q0  = OFF_VTF + SZ_X * 4;
constexpr size_t OFF_Q1  = OFF_Q0  + SZ_X;
constexpr size_t OFF_SQ  = OFF_Q1  + SZ_X;
constexpr size_t OFF_K0  = OFF_SQ  + 16384 * 4;
constexpr size_t OFF_K1  = OFF_K0  + SZ_X;
constexpr size_t OFF_SK  = OFF_K1  + SZ_X;
constexpr size_t OFF_V0  = OFF_SK  + 16384 * 4;
constexpr size_t OFF_V1  = OFF_V0  + SZ_X;
constexpr size_t OFF_SV  = OFF_V1  + SZ_X;
constexpr size_t OFF_S   = OFF_SV  + 8192 * 4;
constexpr size_t OFF_P0  = OFF_S   + SZ_S * 4;
constexpr size_t OFF_P1  = OFF_P0  + SZ_S;
constexpr size_t OFF_SP  = OFF_P1  + SZ_S;
constexpr size_t POOL_SZ = OFF_SP  + 16384 * 4;

__device__ __align__(256) unsigned char g_pool[POOL_SZ];
__device__ int g_len[NB];

// ---------------------------------------------------------------------------
__device__ __forceinline__ void cp_async16(uint32_t dst, const void* src) {
    asm volatile("cp.async.cg.shared.global [%0], [%1], 16;\n"
                 :: "r"(dst), "l"(src) : "memory");
}

__device__ __forceinline__ uint32_t swz(uint32_t off) {
    return off ^ ((off >> 3) & 0x70);
}

__device__ __forceinline__ void ldm4(uint32_t* r, uint32_t a) {
    asm volatile("ldmatrix.sync.aligned.m8n8.x4.shared.b16 {%0,%1,%2,%3}, [%4];"
                 : "=r"(r[0]), "=r"(r[1]), "=r"(r[2]), "=r"(r[3]) : "r"(a));
}

__device__ __forceinline__ void mma_s8(int* c, const uint32_t* a, const uint32_t* b) {
    asm volatile(
        "mma.sync.aligned.m16n8k32.row.col.s32.s8.s8.s32 "
        "{%0,%1,%2,%3}, {%4,%5,%6,%7}, {%8,%9}, {%0,%1,%2,%3};\n"
        : "+r"(c[0]), "+r"(c[1]), "+r"(c[2]), "+r"(c[3])
        : "r"(a[0]), "r"(a[1]), "r"(a[2]), "r"(a[3]), "r"(b[0]), "r"(b[1]));
}

// ---------------------------------------------------------------------------
// per-batch valid length = number of nonzero rows of x[b]
// ---------------------------------------------------------------------------
__global__ __launch_bounds__(256) void len_k(const float* __restrict__ x)
{
    const int b = blockIdx.x;
    __shared__ int cnt;
    if (threadIdx.x == 0) cnt = 0;
    __syncthreads();
    int local = 0;
    for (int t = threadIdx.x; t < NT; t += blockDim.x) {
        const float4* row = (const float4*)(x + ((size_t)b * NT + t) * NE);
        bool nz = false;
        #pragma unroll 4
        for (int e = 0; e < NE / 4; e++) {
            float4 v = row[e];
            if (v.x != 0.f || v.y != 0.f || v.z != 0.f || v.w != 0.f) { nz = true; break; }
        }
        if (nz) local++;
    }
    atomicAdd(&cnt, local);
    __syncthreads();
    if (threadIdx.x == 0) g_len[b] = cnt;
}

// ---------------------------------------------------------------------------
// per-row int8 2-limb quantization. valid = lens[row >> rpb_shift] if lens
// else K; elements >= valid treated as zero.
// ---------------------------------------------------------------------------
__global__ __launch_bounds__(256) void quant_k(
    const float* __restrict__ in, int8_t* __restrict__ o0, int8_t* __restrict__ o1,
    float* __restrict__ sc, int K, const int* __restrict__ lens, int rpb_shift)
{
    const int row = blockIdx.x;
    const int valid = lens ? lens[row >> rpb_shift] : K;
    const float* p = in + (size_t)row * K;
    const int tid = threadIdx.x;
    __shared__ float red[256];

    float m = 0.f;
    for (int s4 = tid * 4; s4 < K; s4 += 1024) {
        float4 v = *(const float4*)(p + s4);
        if (s4 + 3 < valid) {
            m = fmaxf(m, fmaxf(fmaxf(fabsf(v.x), fabsf(v.y)), fmaxf(fabsf(v.z), fabsf(v.w))));
        } else {
            if (s4 + 0 < valid) m = fmaxf(m, fabsf(v.x));
            if (s4 + 1 < valid) m = fmaxf(m, fabsf(v.y));
            if (s4 + 2 < valid) m = fmaxf(m, fabsf(v.z));
            if (s4 + 3 < valid) m = fmaxf(m, fabsf(v.w));
        }
    }
    red[tid] = m; __syncthreads();
    #pragma unroll
    for (int off = 128; off > 0; off >>= 1) {
        if (tid < off) red[tid] = fmaxf(red[tid], red[tid + off]);
        __syncthreads();
    }
    const float s_ = fmaxf(red[0], 1e-30f);
    if (tid == 0) sc[row] = s_;
    const float inv = 127.f / s_;

    for (int s4 = tid * 4; s4 < K; s4 += 1024) {
        float4 v = *(const float4*)(p + s4);
        float vv[4] = {v.x, v.y, v.z, v.w};
        char q0[4], q1[4];
        #pragma unroll
        for (int j = 0; j < 4; j++) {
            float f = (s4 + j < valid) ? vv[j] * inv : 0.f;
            int i0 = __float2int_rn(f);
            int i1 = __float2int_rn((f - (float)i0) * 128.f);
            q0[j] = (char)i0; q1[j] = (char)i1;
        }
        *(char4*)(o0 + (size_t)row * K + s4) = make_char4(q0[0], q0[1], q0[2], q0[3]);
        *(char4*)(o1 + (size_t)row * K + s4) = make_char4(q1[0], q1[1], q1[2], q1[3]);
    }
}

// ---------------------------------------------------------------------------
// W [NE][ND] fp32 -> Wt [ND][NE] fp32
// ---------------------------------------------------------------------------
__global__ void tr_k(const float* __restrict__ W, float* __restrict__ Wt)
{
    __shared__ float tile[32][33];
    const int bn = blockIdx.x * 32;
    const int be = blockIdx.y * 32;
    const int tx = threadIdx.x, ty = threadIdx.y;   // 32 x 8
    #pragma unroll
    for (int r = 0; r < 4; r++)
        tile[ty + r * 8][tx] = W[(size_t)(be + ty + r * 8) * ND + bn + tx];
    __syncthreads();
    #pragma unroll
    for (int r = 0; r < 4; r++)
        Wt[(size_t)(bn + ty + r * 8) * NE + be + tx] = tile[tx][ty + r * 8];
}

// ---------------------------------------------------------------------------
// int8 limb TN GEMM. C[m][n] = sA[m]*sB[n]*(acc0 + acc1/128)/127^2 where
// acc0 = sum A0*B0, acc1 = sum (A0*B1 + A1*B0). Tile 128x128x128, k32 MMAs.
// EPI 0: fp32 C. EPI 2: V-transpose fp32 via smem staging.
// mode: 1 skip col block n0>=len[z]; 2 K bounded by len[z]; 4 skip row m0>=len[z];
//       8 skip row block if (m0&2047) >= len[m0>>11]
// ---------------------------------------------------------------------------
constexpr int SUBI = 128 * 128;           // 16 KB per limb subtile
constexpr int STAGEI = 4 * SUBI;          // 64 KB per stage
constexpr int SMEMI = 2 * STAGEI;         // 131072

template<int EPI>
__global__ __launch_bounds__(256, 1) void gemm_i8(
    const int8_t* __restrict__ A0, const int8_t* __restrict__ A1,
    const int8_t* __restrict__ B0, const int8_t* __restrict__ B1,
    const float* __restrict__ sA, const float* __restrict__ sB,
    float* __restrict__ C,
    int Kdim, int ldC, size_t strA, size_t strB, size_t strC,
    int ssA, int ssB, const int* __restrict__ lens, int mode)
{
    extern __shared__ __align__(128) char sm[];
    const int z = blockIdx.z;
    const int m0 = blockIdx.y * 128, n0 = blockIdx.x * 128;

    if (mode & 1) { if (n0 >= lens[z]) return; }
    if (mode & 4) { if (m0 >= lens[z]) return; }
    if (mode & 8) { if ((m0 & (NT - 1)) >= lens[m0 >> 11]) return; }

    int nkt = Kdim >> 7;
    if (mode & 2) nkt = (lens[z] + 127) >> 7;

    A0 += z * strA; A1 += z * strA;
    B0 += z * strB; B1 += z * strB;
    sA += (size_t)z * ssA; sB += (size_t)z * ssB;

    const int tid = threadIdx.x;
    const int wid = tid >> 5, lane = tid & 31;
    const int wm = (wid & 1) * 64;
    const int wn = (wid >> 1) * 32;

    const int a_row = (lane & 7) + ((lane >> 3) & 1) * 8;
    const int a_chk = lane >> 4;
    const int b_row = (lane & 7) + (lane >> 4) * 8;
    const int b_chk = (lane >> 3) & 1;

    const uint32_t smb = (uint32_t)__cvta_generic_to_shared(sm);

    int acc0[4][4][4], acc1[4][4][4];
    #pragma unroll
    for (int i = 0; i < 4; i++)
        #pragma unroll
        for (int j = 0; j < 4; j++)
            #pragma unroll
            for (int t = 0; t < 4; t++) { acc0[i][j][t] = 0; acc1[i][j][t] = 0; }

    const int r = tid >> 1;
    const int c0 = (tid & 1) * 4;
    const size_t arow = (size_t)(m0 + r) * Kdim;
    const size_t brow = (size_t)(n0 + r) * Kdim;

    auto load_stage = [&](int buf, int k0) {
        const uint32_t sbase = smb + buf * STAGEI;
        #pragma unroll
        for (int j = 0; j < 4; j++) {
            const int cc = c0 + j;
            const uint32_t so = swz(r * 128 + cc * 16);
            const size_t ko = (size_t)k0 + cc * 16;
            cp_async16(sbase + so,            A0 + arow + ko);
            cp_async16(sbase + SUBI + so,     A1 + arow + ko);
            cp_async16(sbase + 2 * SUBI + so, B0 + brow + ko);
            cp_async16(sbase + 3 * SUBI + so, B1 + brow + ko);
        }
        asm volatile("cp.async.commit_group;" ::: "memory");
    };

    load_stage(0, 0);

    for (int i = 0; i < nkt; i++) {
        if (i + 1 < nkt) {
            load_stage((i + 1) & 1, (i + 1) * 128);
            asm volatile("cp.async.wait_group 1;" ::: "memory");
        } else {
            asm volatile("cp.async.wait_group 0;" ::: "memory");
        }
        __syncthreads();

        const uint32_t a0b = smb + (i & 1) * STAGEI;
        const uint32_t a1b = a0b + SUBI;
        const uint32_t b0b = a0b + 2 * SUBI;
        const uint32_t b1b = a0b + 3 * SUBI;

        #pragma unroll
        for (int kc = 0; kc < 8; kc += 2) {        // 4 steps of k=32
            uint32_t b0f[8], b1f[8], af[4][4];
            {
                const uint32_t off0 = swz((wn + b_row) * 128 + (kc + b_chk) * 16);
                const uint32_t off1 = swz((wn + 16 + b_row) * 128 + (kc + b_chk) * 16);
                ldm4(b0f + 0, b0b + off0); ldm4(b0f + 4, b0b + off1);
                ldm4(b1f + 0, b1b + off0); ldm4(b1f + 4, b1b + off1);
            }
            #pragma unroll
            for (int mt = 0; mt < 4; mt++) {
                const uint32_t off = swz((wm + mt * 16 + a_row) * 128 + (kc + a_chk) * 16);
                ldm4(af[mt], a0b + off);
            }
            #pragma unroll
            for (int mt = 0; mt < 4; mt++)
                #pragma unroll
                for (int nt = 0; nt < 4; nt++) {
                    mma_s8(acc0[mt][nt], af[mt], &b0f[nt * 2]);
                    mma_s8(acc1[mt][nt], af[mt], &b1f[nt * 2]);
                }
            #pragma unroll
            for (int mt = 0; mt < 4; mt++) {
                const uint32_t off = swz((wm + mt * 16 + a_row) * 128 + (kc + a_chk) * 16);
                ldm4(af[mt], a1b + off);
            }
            #pragma unroll
            for (int mt = 0; mt < 4; mt++)
                #pragma unroll
                for (int nt = 0; nt < 4; nt++)
                    mma_s8(acc1[mt][nt], af[mt], &b0f[nt * 2]);
        }
        __syncthreads();
    }

    // ----- dequant epilogue -----
    const int g = lane >> 2, tg = lane & 3;
    constexpr float C1 = 1.f / 16129.f;     // 1/127^2
    constexpr float C2 = 1.f / 128.f;

    if (EPI == 0) {
        float* Cz = C + z * strC;
        #pragma unroll
        for (int mt = 0; mt < 4; mt++) {
            const int rr = wm + mt * 16 + g;
            const float ra = sA[m0 + rr] * C1;
            const float rb = sA[m0 + rr + 8] * C1;
            #pragma unroll
            for (int nt = 0; nt < 4; nt++) {
                const int cc = wn + nt * 8 + tg * 2;
                const float cs0 = sB[n0 + cc], cs1 = sB[n0 + cc + 1];
                const int* q0 = acc0[mt][nt];
                const int* q1 = acc1[mt][nt];
                float v0 = ra * cs0 * ((float)q0[0] + (float)q1[0] * C2);
                float v1 = ra * cs1 * ((float)q0[1] + (float)q1[1] * C2);
                float v2 = rb * cs0 * ((float)q0[2] + (float)q1[2] * C2);
                float v3 = rb * cs1 * ((float)q0[3] + (float)q1[3] * C2);
                *(float2*)(Cz + (size_t)(m0 + rr) * ldC + n0 + cc)     = make_float2(v0, v1);
                *(float2*)(Cz + (size_t)(m0 + rr + 8) * ldC + n0 + cc) = make_float2(v2, v3);
            }
        }
    } else {
        // EPI 2: dequant -> smem transpose -> coalesced fp32 stores to Vt[b][d][t]
        float* smf = (float*)sm;   // 128 x 132
        #pragma unroll
        for (int mt = 0; mt < 4; mt++) {
            const int rr = wm + mt * 16 + g;
            const float ra = sA[m0 + rr] * C1;
            const float rb = sA[m0 + rr + 8] * C1;
            #pragma unroll
            for (int nt = 0; nt < 4; nt++) {
                const int cc = wn + nt * 8 + tg * 2;
                const float cs0 = sB[n0 + cc], cs1 = sB[n0 + cc + 1];
                const int* q0 = acc0[mt][nt];
                const int* q1 = acc1[mt][nt];
                smf[(size_t)cc * 132 + rr]           = ra * cs0 * ((float)q0[0] + (float)q1[0] * C2);
                smf[(size_t)(cc + 1) * 132 + rr]     = ra * cs1 * ((float)q0[1] + (float)q1[1] * C2);
                smf[(size_t)cc * 132 + rr + 8]       = rb * cs0 * ((float)q0[2] + (float)q1[2] * C2);
                smf[(size_t)(cc + 1) * 132 + rr + 8] = rb * cs1 * ((float)q0[3] + (float)q1[3] * C2);
            }
        }
        __syncthreads();
        const int b = m0 >> 11, t0 = m0 & (NT - 1);
        float* Vb = C + (size_t)b * ND * NT;
        const int dsub = tid >> 6;
        const int tcol = tid & 63;
        #pragma unroll
        for (int it = 0; it < 32; it++) {
            const int d = it * 4 + dsub;
            float2 v = *(float2*)(smf + (size_t)d * 132 + tcol * 2);
            *(float2*)(Vb + (size_t)(n0 + d) * NT + t0 + tcol * 2) = v;
        }
    }
}

// ---------------------------------------------------------------------------
// masked softmax emitting int8 limbs directly: p = sc * (q0/127 + q1/(127*128)),
// sc[row] = 1/sum(e). Rows t >= len: exact uniform 1/len.
// ---------------------------------------------------------------------------
__global__ __launch_bounds__(256) void softmax_q_k(
    const float* __restrict__ S, int8_t* __restrict__ P0, int8_t* __restrict__ P1,
    float* __restrict__ sc, const int* __restrict__ lens)
{
    __shared__ float cache[NT];
    __shared__ float red[256];
    const int row = blockIdx.x;
    const int b = row >> 11;
    const int t = row & (NT - 1);
    const int len = lens[b];
    int8_t* p0 = P0 + (size_t)row * NT;
    int8_t* p1 = P1 + (size_t)row * NT;
    const int tid = threadIdx.x;

    if (t >= len) {
        if (tid == 0) sc[row] = 1.f / (float)len;
        for (int s4 = tid * 4; s4 < NT; s4 += 1024) {
            char q0[4];
            #pragma unroll
            for (int j = 0; j < 4; j++) q0[j] = (s4 + j < len) ? (char)127 : (char)0;
            *(char4*)(p0 + s4) = make_char4(q0[0], q0[1], q0[2], q0[3]);
            *(char4*)(p1 + s4) = make_char4(0, 0, 0, 0);
        }
        return;
    }

    const float* p = S + (size_t)row * NT;

    float m = -1e30f;
    for (int s = tid; s < len; s += 256) {
        float v = p[s];
        cache[s] = v;
        m = fmaxf(m, v);
    }
    red[tid] = m; __syncthreads();
    #pragma unroll
    for (int off = 128; off > 0; off >>= 1) {
        if (tid < off) red[tid] = fmaxf(red[tid], red[tid + off]);
        __syncthreads();
    }
    m = red[0]; __syncthreads();

    float sum = 0.f;
    for (int s = tid; s < len; s += 256) {
        float e = __expf((cache[s] - m) * 0.125f);
        cache[s] = e;
        sum += e;
    }
    red[tid] = sum; __syncthreads();
    #pragma unroll
    for (int off = 128; off > 0; off >>= 1) {
        if (tid < off) red[tid] += red[tid + off];
        __syncthreads();
    }
    if (tid == 0) sc[row] = 1.f / red[0];
    __syncthreads();

    for (int s4 = tid * 4; s4 < NT; s4 += 1024) {
        char q0[4], q1[4];
        #pragma unroll
        for (int j = 0; j < 4; j++) {
            const int s = s4 + j;
            if (s < len) {
                float f = cache[s] * 127.f;          // e in [0,1]
                int i0 = __float2int_rn(f);
                int i1 = __float2int_rn((f - (float)i0) * 128.f);
                q0[j] = (char)i0; q1[j] = (char)i1;
            } else { q0[j] = 0; q1[j] = 0; }
        }
        *(char4*)(p0 + s4) = make_char4(q0[0], q0[1], q0[2], q0[3]);
        *(char4*)(p1 + s4) = make_char4(q1[0], q1[1], q1[2], q1[3]);
    }
}

// ---------------------------------------------------------------------------
extern "C" void kernel_launch(void* const* d_in, const int* in_sizes, int n_in,
                              void* d_out, int out_size)
{
    const float* x  = (const float*)d_in[0];
    const float* Wq = (const float*)d_in[1];
    const float* Wk = (const float*)d_in[2];
    const float* Wv = (const float*)d_in[3];
    float* out = (float*)d_out;

    unsigned char* pool;
    int* lens;
    cudaGetSymbolAddress((void**)&pool, g_pool);
    cudaGetSymbolAddress((void**)&lens, g_len);

    int8_t* X0  = (int8_t*)(pool + OFF_X0);
    int8_t* X1  = (int8_t*)(pool + OFF_X1);
    float*  SX  = (float*)(pool + OFF_SX);
    float*  WTF = (float*)(pool + OFF_WTF);
    int8_t* WQ0 = (int8_t*)(pool + OFF_WQ0);
    int8_t* WQ1 = (int8_t*)(pool + OFF_WQ1);
    float*  SWQ = (float*)(pool + OFF_SWQ);
    int8_t* WK0 = (int8_t*)(pool + OFF_WK0);
    int8_t* WK1 = (int8_t*)(pool + OFF_WK1);
    float*  SWK = (float*)(pool + OFF_SWK);
    int8_t* WV0 = (int8_t*)(pool + OFF_WV0);
    int8_t* WV1 = (int8_t*)(pool + OFF_WV1);
    float*  SWV = (float*)(pool + OFF_SWV);
    float*  QF  = (float*)(pool + OFF_QF);
    float*  KF  = (float*)(pool + OFF_KF);
    float*  VTF = (float*)(pool + OFF_VTF);
    int8_t* Q0  = (int8_t*)(pool + OFF_Q0);
    int8_t* Q1  = (int8_t*)(pool + OFF_Q1);
    float*  SQ  = (float*)(pool + OFF_SQ);
    int8_t* K0  = (int8_t*)(pool + OFF_K0);
    int8_t* K1  = (int8_t*)(pool + OFF_K1);
    float*  SK  = (float*)(pool + OFF_SK);
    int8_t* V0  = (int8_t*)(pool + OFF_V0);
    int8_t* V1  = (int8_t*)(pool + OFF_V1);
    float*  SV  = (float*)(pool + OFF_SV);
    float*  S   = (float*)(pool + OFF_S);
    int8_t* P0  = (int8_t*)(pool + OFF_P0);
    int8_t* P1  = (int8_t*)(pool + OFF_P1);
    float*  SP  = (float*)(pool + OFF_SP);

    cudaFuncSetAttribute(gemm_i8<0>, cudaFuncAttributeMaxDynamicSharedMemorySize, SMEMI);
    cudaFuncSetAttribute(gemm_i8<2>, cudaFuncAttributeMaxDynamicSharedMemorySize, SMEMI);

    // 1) lengths + input quantization
    len_k<<<NB, 256>>>(x);
    quant_k<<<NB * NT, 256>>>(x, X0, X1, SX, NE, nullptr, 0);
    dim3 tg(ND / 32, NE / 32), tb(32, 8);
    tr_k<<<tg, tb>>>(Wq, WTF);
    quant_k<<<ND, 256>>>(WTF, WQ0, WQ1, SWQ, NE, nullptr, 0);
    tr_k<<<tg, tb>>>(Wk, WTF);
    quant_k<<<ND, 256>>>(WTF, WK0, WK1, SWK, NE, nullptr, 0);
    tr_k<<<tg, tb>>>(Wv, WTF);
    quant_k<<<ND, 256>>>(WTF, WV0, WV1, SWV, NE, nullptr, 0);

    // 2) QKV projections (skip fully-padded row blocks)
    dim3 blk(256);
    dim3 gq(ND / 128, (NB * NT) / 128, 1);
    gemm_i8<0><<<gq, blk, SMEMI>>>(X0, X1, WQ0, WQ1, SX, SWQ, QF,
                                   NE, ND, 0, 0, 0, 0, 0, lens, 8);
    gemm_i8<0><<<gq, blk, SMEMI>>>(X0, X1, WK0, WK1, SX, SWK, KF,
                                   NE, ND, 0, 0, 0, 0, 0, lens, 8);
    gemm_i8<2><<<gq, blk, SMEMI>>>(X0, X1, WV0, WV1, SX, SWV, VTF,
                                   NE, ND, 0, 0, 0, 0, 0, lens, 8);

    // 3) re-quantize Q, K, Vt
    quant_k<<<NB * NT, 256>>>(QF, Q0, Q1, SQ, ND, nullptr, 0);
    quant_k<<<NB * NT, 256>>>(KF, K0, K1, SK, ND, nullptr, 0);
    quant_k<<<NB * ND, 256>>>(VTF, V0, V1, SV, NT, lens, 10);   // row>>10 = batch

    // 4) energy = Q K^T (skip masked row/col blocks)
    dim3 ge(NT / 128, NT / 128, NB);
    gemm_i8<0><<<ge, blk, SMEMI>>>(Q0, Q1, K0, K1, SQ, SK, S,
                                   ND, NT,
                                   (size_t)NT * ND, (size_t)NT * ND, (size_t)NT * NT,
                                   NT, NT, lens, 1 | 4);

    // 5) masked softmax -> P limbs
    softmax_q_k<<<NB * NT, 256>>>(S, P0, P1, SP, lens);

    // 6) out = P V (K bounded by len)
    dim3 go(ND / 128, NT / 128, NB);
    gemm_i8<0><<<go, blk, SMEMI>>>(P0, P1, V0, V1, SP, SV, out,
                                   NT, ND,
                                   (size_t)NT * NT, (size_t)ND * NT, (size_t)NT * ND,
                                   NT, ND, lens, 2);
}

// round 6
// speedup vs baseline: 2.1806x; 2.1806x over previous
#include <cuda_runtime.h>
#include <cuda_bf16.h>
#include <cstdint>

using bf16 = __nv_bfloat16;
using bf162 = __nv_bfloat162;

#define NB 8
#define NT 2048
#define NE 1024
#define ND 1024

constexpr size_t SZ_X = (size_t)NB * NT * NE;
constexpr size_t SZ_W = (size_t)NE * ND;
constexpr size_t SZ_S = (size_t)NB * NT * NT;

// ---- static scratch pool ----
constexpr size_t OFF_XH  = 0;
constexpr size_t OFF_XL  = OFF_XH  + SZ_X * 2;
constexpr size_t OFF_WQH = OFF_XL  + SZ_X * 2;
constexpr size_t OFF_WQL = OFF_WQH + SZ_W * 2;
constexpr size_t OFF_WKH = OFF_WQL + SZ_W * 2;
constexpr size_t OFF_WKL = OFF_WKH + SZ_W * 2;
constexpr size_t OFF_WVH = OFF_WKL + SZ_W * 2;
constexpr size_t OFF_WVL = OFF_WVH + SZ_W * 2;
constexpr size_t OFF_QH  = OFF_WVL + SZ_W * 2;
constexpr size_t OFF_QL  = OFF_QH  + SZ_X * 2;
constexpr size_t OFF_KH  = OFF_QL  + SZ_X * 2;
constexpr size_t OFF_KL  = OFF_KH  + SZ_X * 2;
constexpr size_t OFF_VTH = OFF_KL  + SZ_X * 2;
constexpr size_t OFF_VTL = OFF_VTH + SZ_X * 2;
constexpr size_t OFF_S   = OFF_VTL + SZ_X * 2;
constexpr size_t OFF_PH  = OFF_S   + SZ_S * 4;
constexpr size_t OFF_PL  = OFF_PH  + SZ_S * 2;
constexpr size_t POOL_SZ = OFF_PL  + SZ_S * 2;

__device__ __align__(256) unsigned char g_pool[POOL_SZ];
__device__ int g_len[NB];

// ---------------------------------------------------------------------------
__device__ __forceinline__ void split2(float v, bf16& h, bf16& l) {
    h = __float2bfloat16(v);
    l = __float2bfloat16(v - __bfloat162float(h));
}

__device__ __forceinline__ void cp_async16(uint32_t dst, const void* src) {
    asm volatile("cp.async.cg.shared.global [%0], [%1], 16;\n"
                 :: "r"(dst), "l"(src) : "memory");
}

__device__ __forceinline__ uint32_t swz(uint32_t off) {
    return off ^ ((off >> 3) & 0x70);
}

__device__ __forceinline__ void ldm4(uint32_t* r, uint32_t a) {
    asm volatile("ldmatrix.sync.aligned.m8n8.x4.shared.b16 {%0,%1,%2,%3}, [%4];"
                 : "=r"(r[0]), "=r"(r[1]), "=r"(r[2]), "=r"(r[3]) : "r"(a));
}

__device__ __forceinline__ void mma_bf16(float* c, const uint32_t* a, const uint32_t* b) {
    asm volatile(
        "mma.sync.aligned.m16n8k16.row.col.f32.bf16.bf16.f32 "
        "{%0,%1,%2,%3}, {%4,%5,%6,%7}, {%8,%9}, {%0,%1,%2,%3};\n"
        : "+f"(c[0]), "+f"(c[1]), "+f"(c[2]), "+f"(c[3])
        : "r"(a[0]), "r"(a[1]), "r"(a[2]), "r"(a[3]), "r"(b[0]), "r"(b[1]));
}

// ---------------------------------------------------------------------------
// per-batch valid length = number of nonzero rows of x[b]
// ---------------------------------------------------------------------------
__global__ __launch_bounds__(256) void len_k(const float* __restrict__ x)
{
    const int b = blockIdx.x;
    __shared__ int cnt;
    if (threadIdx.x == 0) cnt = 0;
    __syncthreads();
    int local = 0;
    for (int t = threadIdx.x; t < NT; t += blockDim.x) {
        const float4* row = (const float4*)(x + ((size_t)b * NT + t) * NE);
        bool nz = false;
        #pragma unroll 4
        for (int e = 0; e < NE / 4; e++) {
            float4 v = row[e];
            if (v.x != 0.f || v.y != 0.f || v.z != 0.f || v.w != 0.f) { nz = true; break; }
        }
        if (nz) local++;
    }
    atomicAdd(&cnt, local);
    __syncthreads();
    if (threadIdx.x == 0) g_len[b] = cnt;
}

// ---------------------------------------------------------------------------
__global__ __launch_bounds__(256) void split_k(const float* __restrict__ in,
                                               bf16* __restrict__ h, bf16* __restrict__ l,
                                               size_t n4)
{
    size_t i = (size_t)blockIdx.x * 256 + threadIdx.x;
    if (i >= n4) return;
    float4 v = ((const float4*)in)[i];
    bf16 h0, h1, h2, h3, l0, l1, l2, l3;
    split2(v.x, h0, l0); split2(v.y, h1, l1);
    split2(v.z, h2, l2); split2(v.w, h3, l3);
    bf162* hp = (bf162*)(h + i * 4);
    bf162* lp = (bf162*)(l + i * 4);
    bf162 a; a.x = h0; a.y = h1; hp[0] = a;
    a.x = h2; a.y = h3; hp[1] = a;
    a.x = l0; a.y = l1; lp[0] = a;
    a.x = l2; a.y = l3; lp[1] = a;
}

__global__ __launch_bounds__(256) void trsplit_k(const float* __restrict__ W,
                                                 bf16* __restrict__ Th, bf16* __restrict__ Tl)
{
    __shared__ float tile[32][33];
    const int bn = blockIdx.x * 32;
    const int be = blockIdx.y * 32;
    const int tx = threadIdx.x, ty = threadIdx.y;
    #pragma unroll
    for (int r = 0; r < 4; r++)
        tile[ty + r * 8][tx] = W[(size_t)(be + ty + r * 8) * ND + bn + tx];
    __syncthreads();
    #pragma unroll
    for (int r = 0; r < 4; r++) {
        float v = tile[tx][ty + r * 8];
        bf16 h, l; split2(v, h, l);
        size_t o = (size_t)(bn + ty + r * 8) * NE + be + tx;
        Th[o] = h; Tl[o] = l;
    }
}

// ---------------------------------------------------------------------------
// HMMA TN GEMM, 3-term bf16 hi/lo emulation, ldmatrix + SW128, Ktile 64.
// 3-stage cp.async pipeline, one __syncthreads per K-tile, MMA issued in
// three independent 16-MMA passes (no back-to-back accumulator RAW chains).
// C[m][n] = sum_k A[m][k]*B[n][k].
// EPI: 0 fp32 C; 1 split bf16 (Ch,Cl); 2 split V-transpose via smem staging.
// mode bits: 1 skip col block n0>=len[z]; 2 K bounded by len[z];
//            4 skip row m0>=len[z]; 8 skip row block if (m0&2047)>=len[m0>>11]
// ---------------------------------------------------------------------------
constexpr int SUB = 128 * 128;          // 16 KB per operand subtile
constexpr int STAGE = 4 * SUB;          // 64 KB per stage
constexpr int NSTAGE = 3;
constexpr int SMEM_TOTAL = NSTAGE * STAGE;   // 196608

template<int EPI>
__global__ __launch_bounds__(256, 1) void gemm4(
    const bf16* __restrict__ Ah, const bf16* __restrict__ Al,
    const bf16* __restrict__ Bh, const bf16* __restrict__ Bl,
    float* __restrict__ C, bf16* __restrict__ Ch, bf16* __restrict__ Cl,
    int Kdim, int ldC, size_t sA, size_t sB, size_t sC,
    const int* __restrict__ lens, int mode)
{
    extern __shared__ __align__(128) char sm[];
    const int z = blockIdx.z;
    const int m0 = blockIdx.y * 128, n0 = blockIdx.x * 128;

    if (mode & 1) { if (n0 >= lens[z]) return; }
    if (mode & 4) { if (m0 >= lens[z]) return; }
    if (mode & 8) { if ((m0 & (NT - 1)) >= lens[m0 >> 11]) return; }

    int nkt = Kdim / 64;
    if (mode & 2) nkt = (lens[z] + 63) >> 6;

    Ah += z * sA; Al += z * sA;
    Bh += z * sB; Bl += z * sB;

    const int tid = threadIdx.x;
    const int wid = tid >> 5, lane = tid & 31;
    const int wm = (wid & 1) * 64;
    const int wn = (wid >> 1) * 32;

    // ldmatrix lane decode
    const int a_row = (lane & 7) + ((lane >> 3) & 1) * 8;
    const int a_chk = lane >> 4;
    const int b_row = (lane & 7) + (lane >> 4) * 8;
    const int b_chk = (lane >> 3) & 1;

    const uint32_t smb = (uint32_t)__cvta_generic_to_shared(sm);

    float c[4][4][4];
    #pragma unroll
    for (int i = 0; i < 4; i++)
        #pragma unroll
        for (int j = 0; j < 4; j++)
            #pragma unroll
            for (int t = 0; t < 4; t++) c[i][j][t] = 0.f;

    // cp.async roles: thread -> row (tid>>1), 4 chunks of 16B
    const int r = tid >> 1;
    const int c0 = (tid & 1) * 4;
    const size_t arow = (size_t)(m0 + r) * Kdim;
    const size_t brow = (size_t)(n0 + r) * Kdim;

    auto load_stage = [&](int buf, int k0) {
        const uint32_t sbase = smb + buf * STAGE;
        #pragma unroll
        for (int j = 0; j < 4; j++) {
            const int cc = c0 + j;
            const uint32_t so = swz(r * 128 + cc * 16);
            const size_t ko = (size_t)k0 + cc * 8;
            cp_async16(sbase + so,           Ah + arow + ko);
            cp_async16(sbase + SUB + so,     Al + arow + ko);
            cp_async16(sbase + 2 * SUB + so, Bh + brow + ko);
            cp_async16(sbase + 3 * SUB + so, Bl + brow + ko);
        }
        asm volatile("cp.async.commit_group;" ::: "memory");
    };

    // prologue: stages 0 and 1 (nkt >= 8 always for this problem)
    load_stage(0, 0);
    load_stage(1, 64);

    int buf = 0;
    for (int i = 0; i < nkt; i++) {
        if (i + 1 < nkt) {
            asm volatile("cp.async.wait_group 1;" ::: "memory");
        } else {
            asm volatile("cp.async.wait_group 0;" ::: "memory");
        }
        __syncthreads();   // stage i visible to all; everyone done reading stage i-1

        if (i + 2 < nkt) {
            int nb = buf + 2; if (nb >= NSTAGE) nb -= NSTAGE;
            load_stage(nb, (i + 2) * 64);
        }

        const uint32_t ahb = smb + buf * STAGE;
        const uint32_t alb = ahb + SUB;
        const uint32_t bhb = ahb + 2 * SUB;
        const uint32_t blb = ahb + 3 * SUB;

        #pragma unroll
        for (int kc = 0; kc < 8; kc += 2) {        // 4 k16 steps
            uint32_t bh[8], bl[8], a[4][4];
            {
                const uint32_t off0 = swz((wn + b_row) * 128 + (kc + b_chk) * 16);
                const uint32_t off1 = swz((wn + 16 + b_row) * 128 + (kc + b_chk) * 16);
                ldm4(bh + 0, bhb + off0); ldm4(bh + 4, bhb + off1);
                ldm4(bl + 0, blb + off0); ldm4(bl + 4, blb + off1);
            }
            #pragma unroll
            for (int mt = 0; mt < 4; mt++) {
                const uint32_t off = swz((wm + mt * 16 + a_row) * 128 + (kc + a_chk) * 16);
                ldm4(a[mt], ahb + off);
            }
            // pass 1: hi*hi (16 independent MMAs)
            #pragma unroll
            for (int mt = 0; mt < 4; mt++)
                #pragma unroll
                for (int nt = 0; nt < 4; nt++)
                    mma_bf16(c[mt][nt], a[mt], &bh[nt * 2]);
            // pass 2: hi*lo
            #pragma unroll
            for (int mt = 0; mt < 4; mt++)
                #pragma unroll
                for (int nt = 0; nt < 4; nt++)
                    mma_bf16(c[mt][nt], a[mt], &bl[nt * 2]);
            // reload A as lo limb
            #pragma unroll
            for (int mt = 0; mt < 4; mt++) {
                const uint32_t off = swz((wm + mt * 16 + a_row) * 128 + (kc + a_chk) * 16);
                ldm4(a[mt], alb + off);
            }
            // pass 3: lo*hi
            #pragma unroll
            for (int mt = 0; mt < 4; mt++)
                #pragma unroll
                for (int nt = 0; nt < 4; nt++)
                    mma_bf16(c[mt][nt], a[mt], &bh[nt * 2]);
        }

        if (++buf >= NSTAGE) buf = 0;
    }
    __syncthreads();   // protect smem reuse by EPI 2 staging

    // ----- epilogue -----
    const int g = lane >> 2, tg = lane & 3;
    if (EPI == 0) {
        float* Cz = C + z * sC;
        #pragma unroll
        for (int mt = 0; mt < 4; mt++) {
            const int row = m0 + wm + mt * 16 + g;
            #pragma unroll
            for (int nt = 0; nt < 4; nt++) {
                const int col = n0 + wn + nt * 8 + tg * 2;
                *(float2*)(Cz + (size_t)row * ldC + col)       = make_float2(c[mt][nt][0], c[mt][nt][1]);
                *(float2*)(Cz + (size_t)(row + 8) * ldC + col) = make_float2(c[mt][nt][2], c[mt][nt][3]);
            }
        }
    } else if (EPI == 1) {
        #pragma unroll
        for (int mt = 0; mt < 4; mt++) {
            const int row = m0 + wm + mt * 16 + g;
            #pragma unroll
            for (int nt = 0; nt < 4; nt++) {
                const int col = n0 + wn + nt * 8 + tg * 2;
                bf16 h0, h1, l0, l1;
                split2(c[mt][nt][0], h0, l0); split2(c[mt][nt][1], h1, l1);
                bf162 hv; hv.x = h0; hv.y = h1;
                bf162 lv; lv.x = l0; lv.y = l1;
                *(bf162*)(Ch + (size_t)row * ldC + col) = hv;
                *(bf162*)(Cl + (size_t)row * ldC + col) = lv;
                split2(c[mt][nt][2], h0, l0); split2(c[mt][nt][3], h1, l1);
                hv.x = h0; hv.y = h1; lv.x = l0; lv.y = l1;
                *(bf162*)(Ch + (size_t)(row + 8) * ldC + col) = hv;
                *(bf162*)(Cl + (size_t)(row + 8) * ldC + col) = lv;
            }
        }
    } else {
        // EPI 2: transpose through smem, then coalesced split stores.
        float* smf = (float*)sm;                 // 128 x 132 fp32 (67.6 KB)
        #pragma unroll
        for (int mt = 0; mt < 4; mt++) {
            const int rr = wm + mt * 16 + g;
            #pragma unroll
            for (int nt = 0; nt < 4; nt++) {
                const int cc = wn + nt * 8 + tg * 2;
                smf[(size_t)cc * 132 + rr]           = c[mt][nt][0];
                smf[(size_t)(cc + 1) * 132 + rr]     = c[mt][nt][1];
                smf[(size_t)cc * 132 + rr + 8]       = c[mt][nt][2];
                smf[(size_t)(cc + 1) * 132 + rr + 8] = c[mt][nt][3];
            }
        }
        __syncthreads();
        const int b = m0 >> 11, t0 = m0 & (NT - 1);
        bf16* Hb = Ch + (size_t)b * ND * NT;
        bf16* Lb = Cl + (size_t)b * ND * NT;
        const int dsub = tid >> 6;           // 0..3
        const int tcol = tid & 63;           // 0..63
        #pragma unroll
        for (int it = 0; it < 32; it++) {
            const int d = it * 4 + dsub;
            float2 v = *(float2*)(smf + (size_t)d * 132 + tcol * 2);
            bf16 h0, h1, l0, l1;
            split2(v.x, h0, l0); split2(v.y, h1, l1);
            bf162 hv; hv.x = h0; hv.y = h1;
            bf162 lv; lv.x = l0; lv.y = l1;
            *(bf162*)(Hb + (size_t)(n0 + d) * NT + t0 + tcol * 2) = hv;
            *(bf162*)(Lb + (size_t)(n0 + d) * NT + t0 + tcol * 2) = lv;
        }
    }
}

// ---------------------------------------------------------------------------
// masked row softmax with smem row cache: S fp32 -> split bf16 P.
// Rows t >= len get the exact uniform 1/len over s<len (zero Q row case).
// ---------------------------------------------------------------------------
__global__ __launch_bounds__(256) void softmax_split_k(const float* __restrict__ S,
                                                       bf16* __restrict__ Ph,
                                                       bf16* __restrict__ Pl,
                                                       const int* __restrict__ lens)
{
    __shared__ float cache[NT];
    __shared__ float red[256];
    const int row = blockIdx.x;
    const int b = row >> 11;
    const int t = row & (NT - 1);
    const int len = lens[b];
    bf16* ph = Ph + (size_t)row * NT;
    bf16* pl = Pl + (size_t)row * NT;
    const int tid = threadIdx.x;
    const bf16 z0 = __float2bfloat16(0.f);

    if (t >= len) {
        const float v = 1.f / (float)len;
        bf16 h, l; split2(v, h, l);
        for (int s = tid; s < len; s += 256) { ph[s] = h; pl[s] = l; }
        for (int s = len + tid; s < NT; s += 256) { ph[s] = z0; pl[s] = z0; }
        return;
    }

    const float* p = S + (size_t)row * NT;

    float m = -1e30f;
    for (int s = tid; s < len; s += 256) {
        float v = p[s];
        cache[s] = v;
        m = fmaxf(m, v);
    }
    red[tid] = m; __syncthreads();
    #pragma unroll
    for (int off = 128; off > 0; off >>= 1) {
        if (tid < off) red[tid] = fmaxf(red[tid], red[tid + off]);
        __syncthreads();
    }
    m = red[0]; __syncthreads();

    float sum = 0.f;
    for (int s = tid; s < len; s += 256) {
        float e = __expf((cache[s] - m) * 0.125f);
        cache[s] = e;
        sum += e;
    }
    red[tid] = sum; __syncthreads();
    #pragma unroll
    for (int off = 128; off > 0; off >>= 1) {
        if (tid < off) red[tid] += red[tid + off];
        __syncthreads();
    }
    const float inv = 1.f / red[0];

    for (int s = tid; s < len; s += 256) {
        bf16 h, l; split2(cache[s] * inv, h, l);
        ph[s] = h; pl[s] = l;
    }
    for (int s = len + tid; s < NT; s += 256) { ph[s] = z0; pl[s] = z0; }
}

// ---------------------------------------------------------------------------
extern "C" void kernel_launch(void* const* d_in, const int* in_sizes, int n_in,
                              void* d_out, int out_size)
{
    const float* x  = (const float*)d_in[0];
    const float* Wq = (const float*)d_in[1];
    const float* Wk = (const float*)d_in[2];
    const float* Wv = (const float*)d_in[3];
    float* out = (float*)d_out;

    unsigned char* pool;
    int* lens;
    cudaGetSymbolAddress((void**)&pool, g_pool);
    cudaGetSymbolAddress((void**)&lens, g_len);

    bf16* xh  = (bf16*)(pool + OFF_XH);
    bf16* xl  = (bf16*)(pool + OFF_XL);
    bf16* wqh = (bf16*)(pool + OFF_WQH);
    bf16* wql = (bf16*)(pool + OFF_WQL);
    bf16* wkh = (bf16*)(pool + OFF_WKH);
    bf16* wkl = (bf16*)(pool + OFF_WKL);
    bf16* wvh = (bf16*)(pool + OFF_WVH);
    bf16* wvl = (bf16*)(pool + OFF_WVL);
    bf16* Qh  = (bf16*)(pool + OFF_QH);
    bf16* Ql  = (bf16*)(pool + OFF_QL);
    bf16* Kh  = (bf16*)(pool + OFF_KH);
    bf16* Kl  = (bf16*)(pool + OFF_KL);
    bf16* Vth = (bf16*)(pool + OFF_VTH);
    bf16* Vtl = (bf16*)(pool + OFF_VTL);
    float* S  = (float*)(pool + OFF_S);
    bf16* Ph  = (bf16*)(pool + OFF_PH);
    bf16* Pl  = (bf16*)(pool + OFF_PL);

    cudaFuncSetAttribute(gemm4<0>, cudaFuncAttributeMaxDynamicSharedMemorySize, SMEM_TOTAL);
    cudaFuncSetAttribute(gemm4<1>, cudaFuncAttributeMaxDynamicSharedMemorySize, SMEM_TOTAL);
    cudaFuncSetAttribute(gemm4<2>, cudaFuncAttributeMaxDynamicSharedMemorySize, SMEM_TOTAL);

    // 1) lengths + splits
    len_k<<<NB, 256>>>(x);
    split_k<<<(int)(SZ_X / 4 / 256), 256>>>(x, xh, xl, SZ_X / 4);
    dim3 tg(32, 32), tb(32, 8);
    trsplit_k<<<tg, tb>>>(Wq, wqh, wql);
    trsplit_k<<<tg, tb>>>(Wk, wkh, wkl);
    trsplit_k<<<tg, tb>>>(Wv, wvh, wvl);

    // 2) QKV projections: skip fully-padded row blocks (mode 8)
    dim3 blk(256);
    dim3 gq(ND / 128, (NB * NT) / 128, 1);
    gemm4<1><<<gq, blk, SMEM_TOTAL>>>(xh, xl, wqh, wql, nullptr, Qh, Ql,
                                      NE, ND, 0, 0, 0, lens, 8);
    gemm4<1><<<gq, blk, SMEM_TOTAL>>>(xh, xl, wkh, wkl, nullptr, Kh, Kl,
                                      NE, ND, 0, 0, 0, lens, 8);
    gemm4<2><<<gq, blk, SMEM_TOTAL>>>(xh, xl, wvh, wvl, nullptr, Vth, Vtl,
                                      NE, ND, 0, 0, 0, lens, 8);

    // 3) energy = Q K^T per batch; skip masked row blocks (4) and col blocks (1)
    dim3 ge(NT / 128, NT / 128, NB);
    gemm4<0><<<ge, blk, SMEM_TOTAL>>>(Qh, Ql, Kh, Kl, S, nullptr, nullptr,
                                      ND, NT,
                                      (size_t)NT * ND, (size_t)NT * ND, (size_t)NT * NT,
                                      lens, 1 | 4);

    // 4) masked softmax -> split P (uniform rows for t >= len)
    softmax_split_k<<<NB * NT, 256>>>(S, Ph, Pl, lens);

    // 5) out = P V per batch, K-loop bounded by len (mode 2)
    dim3 go(ND / 128, NT / 128, NB);
    gemm4<0><<<go, blk, SMEM_TOTAL>>>(Ph, Pl, Vth, Vtl, out, nullptr, nullptr,
                                      NT, ND,
                                      (size_t)NT * NT, (size_t)ND * NT, (size_t)NT * ND,
                                      lens, 2);
}

// round 7
// speedup vs baseline: 2.2730x; 1.0424x over previous
#include <cuda_runtime.h>
#include <cuda_bf16.h>
#include <cstdint>

using bf16 = __nv_bfloat16;
using bf162 = __nv_bfloat162;

#define NB 8
#define NT 2048
#define NE 1024
#define ND 1024

constexpr size_t SZ_X = (size_t)NB * NT * NE;
constexpr size_t SZ_W = (size_t)NE * ND;
constexpr size_t SZ_S = (size_t)NB * NT * NT;

// ---- static scratch pool ----
constexpr size_t OFF_XH  = 0;
constexpr size_t OFF_XL  = OFF_XH  + SZ_X * 2;
constexpr size_t OFF_WQH = OFF_XL  + SZ_X * 2;
constexpr size_t OFF_WQL = OFF_WQH + SZ_W * 2;
constexpr size_t OFF_WKH = OFF_WQL + SZ_W * 2;
constexpr size_t OFF_WKL = OFF_WKH + SZ_W * 2;
constexpr size_t OFF_WVH = OFF_WKL + SZ_W * 2;
constexpr size_t OFF_WVL = OFF_WVH + SZ_W * 2;
constexpr size_t OFF_QH  = OFF_WVL + SZ_W * 2;
constexpr size_t OFF_QL  = OFF_QH  + SZ_X * 2;
constexpr size_t OFF_KH  = OFF_QL  + SZ_X * 2;
constexpr size_t OFF_KL  = OFF_KH  + SZ_X * 2;
constexpr size_t OFF_VTH = OFF_KL  + SZ_X * 2;
constexpr size_t OFF_VTL = OFF_VTH + SZ_X * 2;
constexpr size_t OFF_S   = OFF_VTL + SZ_X * 2;
constexpr size_t OFF_PH  = OFF_S   + SZ_S * 4;
constexpr size_t OFF_PL  = OFF_PH  + SZ_S * 2;
constexpr size_t OFF_BC  = OFF_PL  + SZ_S * 2;
constexpr size_t POOL_SZ = OFF_BC  + (size_t)NB * ND * 4;

__device__ __align__(256) unsigned char g_pool[POOL_SZ];
__device__ int g_len[NB];

// ---------------------------------------------------------------------------
__device__ __forceinline__ void split2(float v, bf16& h, bf16& l) {
    h = __float2bfloat16(v);
    l = __float2bfloat16(v - __bfloat162float(h));
}

__device__ __forceinline__ void cp_async16(uint32_t dst, const void* src) {
    asm volatile("cp.async.cg.shared.global [%0], [%1], 16;\n"
                 :: "r"(dst), "l"(src) : "memory");
}

__device__ __forceinline__ uint32_t swz(uint32_t off) {
    return off ^ ((off >> 3) & 0x70);
}

__device__ __forceinline__ void ldm4(uint32_t* r, uint32_t a) {
    asm volatile("ldmatrix.sync.aligned.m8n8.x4.shared.b16 {%0,%1,%2,%3}, [%4];"
                 : "=r"(r[0]), "=r"(r[1]), "=r"(r[2]), "=r"(r[3]) : "r"(a));
}

__device__ __forceinline__ void mma_bf16(float* c, const uint32_t* a, const uint32_t* b) {
    asm volatile(
        "mma.sync.aligned.m16n8k16.row.col.f32.bf16.bf16.f32 "
        "{%0,%1,%2,%3}, {%4,%5,%6,%7}, {%8,%9}, {%0,%1,%2,%3};\n"
        : "+f"(c[0]), "+f"(c[1]), "+f"(c[2]), "+f"(c[3])
        : "r"(a[0]), "r"(a[1]), "r"(a[2]), "r"(a[3]), "r"(b[0]), "r"(b[1]));
}

// ---------------------------------------------------------------------------
// per-batch valid length = number of nonzero rows of x[b]
// ---------------------------------------------------------------------------
__global__ __launch_bounds__(256) void len_k(const float* __restrict__ x)
{
    const int b = blockIdx.x;
    __shared__ int cnt;
    if (threadIdx.x == 0) cnt = 0;
    __syncthreads();
    int local = 0;
    for (int t = threadIdx.x; t < NT; t += blockDim.x) {
        const float4* row = (const float4*)(x + ((size_t)b * NT + t) * NE);
        bool nz = false;
        #pragma unroll 4
        for (int e = 0; e < NE / 4; e++) {
            float4 v = row[e];
            if (v.x != 0.f || v.y != 0.f || v.z != 0.f || v.w != 0.f) { nz = true; break; }
        }
        if (nz) local++;
    }
    atomicAdd(&cnt, local);
    __syncthreads();
    if (threadIdx.x == 0) g_len[b] = cnt;
}

// ---------------------------------------------------------------------------
__global__ __launch_bounds__(256) void split_k(const float* __restrict__ in,
                                               bf16* __restrict__ h, bf16* __restrict__ l,
                                               size_t n4)
{
    size_t i = (size_t)blockIdx.x * 256 + threadIdx.x;
    if (i >= n4) return;
    float4 v = ((const float4*)in)[i];
    bf16 h0, h1, h2, h3, l0, l1, l2, l3;
    split2(v.x, h0, l0); split2(v.y, h1, l1);
    split2(v.z, h2, l2); split2(v.w, h3, l3);
    bf162* hp = (bf162*)(h + i * 4);
    bf162* lp = (bf162*)(l + i * 4);
    bf162 a; a.x = h0; a.y = h1; hp[0] = a;
    a.x = h2; a.y = h3; hp[1] = a;
    a.x = l0; a.y = l1; lp[0] = a;
    a.x = l2; a.y = l3; lp[1] = a;
}

__global__ __launch_bounds__(256) void trsplit_k(const float* __restrict__ W,
                                                 bf16* __restrict__ Th, bf16* __restrict__ Tl)
{
    __shared__ float tile[32][33];
    const int bn = blockIdx.x * 32;
    const int be = blockIdx.y * 32;
    const int tx = threadIdx.x, ty = threadIdx.y;
    #pragma unroll
    for (int r = 0; r < 4; r++)
        tile[ty + r * 8][tx] = W[(size_t)(be + ty + r * 8) * ND + bn + tx];
    __syncthreads();
    #pragma unroll
    for (int r = 0; r < 4; r++) {
        float v = tile[tx][ty + r * 8];
        bf16 h, l; split2(v, h, l);
        size_t o = (size_t)(bn + ty + r * 8) * NE + be + tx;
        Th[o] = h; Tl[o] = l;
    }
}

// ---------------------------------------------------------------------------
// Shared HMMA mainloop: 3-term bf16 hi/lo, ldmatrix + SW128, Ktile 64,
// 3-stage cp.async pipeline. Accumulates into c[4][4][4].
// ---------------------------------------------------------------------------
constexpr int SUB = 128 * 128;
constexpr int STAGE = 4 * SUB;
constexpr int NSTAGE = 3;
constexpr int SMEM_TOTAL = NSTAGE * STAGE;   // 196608

__device__ __forceinline__ void gemm_core(
    const bf16* __restrict__ Ah, const bf16* __restrict__ Al,
    const bf16* __restrict__ Bh, const bf16* __restrict__ Bl,
    int Kdim, int nkt, int m0, int n0, char* sm, float (&c)[4][4][4])
{
    const int tid = threadIdx.x;
    const int wid = tid >> 5, lane = tid & 31;
    const int wm = (wid & 1) * 64;
    const int wn = (wid >> 1) * 32;

    const int a_row = (lane & 7) + ((lane >> 3) & 1) * 8;
    const int a_chk = lane >> 4;
    const int b_row = (lane & 7) + (lane >> 4) * 8;
    const int b_chk = (lane >> 3) & 1;

    const uint32_t smb = (uint32_t)__cvta_generic_to_shared(sm);

    #pragma unroll
    for (int i = 0; i < 4; i++)
        #pragma unroll
        for (int j = 0; j < 4; j++)
            #pragma unroll
            for (int t = 0; t < 4; t++) c[i][j][t] = 0.f;

    const int r = tid >> 1;
    const int c0 = (tid & 1) * 4;
    const size_t arow = (size_t)(m0 + r) * Kdim;
    const size_t brow = (size_t)(n0 + r) * Kdim;

    auto load_stage = [&](int buf, int k0) {
        const uint32_t sbase = smb + buf * STAGE;
        #pragma unroll
        for (int j = 0; j < 4; j++) {
            const int cc = c0 + j;
            const uint32_t so = swz(r * 128 + cc * 16);
            const size_t ko = (size_t)k0 + cc * 8;
            cp_async16(sbase + so,           Ah + arow + ko);
            cp_async16(sbase + SUB + so,     Al + arow + ko);
            cp_async16(sbase + 2 * SUB + so, Bh + brow + ko);
            cp_async16(sbase + 3 * SUB + so, Bl + brow + ko);
        }
        asm volatile("cp.async.commit_group;" ::: "memory");
    };

    load_stage(0, 0);
    load_stage(1, 64);

    int buf = 0;
    for (int i = 0; i < nkt; i++) {
        if (i + 1 < nkt) {
            asm volatile("cp.async.wait_group 1;" ::: "memory");
        } else {
            asm volatile("cp.async.wait_group 0;" ::: "memory");
        }
        __syncthreads();

        if (i + 2 < nkt) {
            int nb = buf + 2; if (nb >= NSTAGE) nb -= NSTAGE;
            load_stage(nb, (i + 2) * 64);
        }

        const uint32_t ahb = smb + buf * STAGE;
        const uint32_t alb = ahb + SUB;
        const uint32_t bhb = ahb + 2 * SUB;
        const uint32_t blb = ahb + 3 * SUB;

        #pragma unroll
        for (int kc = 0; kc < 8; kc += 2) {
            uint32_t bh[8], bl[8], a[4][4];
            {
                const uint32_t off0 = swz((wn + b_row) * 128 + (kc + b_chk) * 16);
                const uint32_t off1 = swz((wn + 16 + b_row) * 128 + (kc + b_chk) * 16);
                ldm4(bh + 0, bhb + off0); ldm4(bh + 4, bhb + off1);
                ldm4(bl + 0, blb + off0); ldm4(bl + 4, blb + off1);
            }
            #pragma unroll
            for (int mt = 0; mt < 4; mt++) {
                const uint32_t off = swz((wm + mt * 16 + a_row) * 128 + (kc + a_chk) * 16);
                ldm4(a[mt], ahb + off);
            }
            #pragma unroll
            for (int mt = 0; mt < 4; mt++)
                #pragma unroll
                for (int nt = 0; nt < 4; nt++)
                    mma_bf16(c[mt][nt], a[mt], &bh[nt * 2]);
            #pragma unroll
            for (int mt = 0; mt < 4; mt++)
                #pragma unroll
                for (int nt = 0; nt < 4; nt++)
                    mma_bf16(c[mt][nt], a[mt], &bl[nt * 2]);
            #pragma unroll
            for (int mt = 0; mt < 4; mt++) {
                const uint32_t off = swz((wm + mt * 16 + a_row) * 128 + (kc + a_chk) * 16);
                ldm4(a[mt], alb + off);
            }
            #pragma unroll
            for (int mt = 0; mt < 4; mt++)
                #pragma unroll
                for (int nt = 0; nt < 4; nt++)
                    mma_bf16(c[mt][nt], a[mt], &bh[nt * 2]);
        }

        if (++buf >= NSTAGE) buf = 0;
    }
    __syncthreads();   // smem safe for epilogue reuse
}

// ---- epilogues ----
__device__ __forceinline__ void epi_f32(float (&c)[4][4][4], float* Cz, int ldC,
                                        int m0, int n0)
{
    const int tid = threadIdx.x;
    const int wid = tid >> 5, lane = tid & 31;
    const int wm = (wid & 1) * 64, wn = (wid >> 1) * 32;
    const int g = lane >> 2, tg = lane & 3;
    #pragma unroll
    for (int mt = 0; mt < 4; mt++) {
        const int row = m0 + wm + mt * 16 + g;
        #pragma unroll
        for (int nt = 0; nt < 4; nt++) {
            const int col = n0 + wn + nt * 8 + tg * 2;
            *(float2*)(Cz + (size_t)row * ldC + col)       = make_float2(c[mt][nt][0], c[mt][nt][1]);
            *(float2*)(Cz + (size_t)(row + 8) * ldC + col) = make_float2(c[mt][nt][2], c[mt][nt][3]);
        }
    }
}

__device__ __forceinline__ void epi_split(float (&c)[4][4][4], bf16* Ch, bf16* Cl,
                                          int ldC, int m0, int n0)
{
    const int tid = threadIdx.x;
    const int wid = tid >> 5, lane = tid & 31;
    const int wm = (wid & 1) * 64, wn = (wid >> 1) * 32;
    const int g = lane >> 2, tg = lane & 3;
    #pragma unroll
    for (int mt = 0; mt < 4; mt++) {
        const int row = m0 + wm + mt * 16 + g;
        #pragma unroll
        for (int nt = 0; nt < 4; nt++) {
            const int col = n0 + wn + nt * 8 + tg * 2;
            bf16 h0, h1, l0, l1;
            split2(c[mt][nt][0], h0, l0); split2(c[mt][nt][1], h1, l1);
            bf162 hv; hv.x = h0; hv.y = h1;
            bf162 lv; lv.x = l0; lv.y = l1;
            *(bf162*)(Ch + (size_t)row * ldC + col) = hv;
            *(bf162*)(Cl + (size_t)row * ldC + col) = lv;
            split2(c[mt][nt][2], h0, l0); split2(c[mt][nt][3], h1, l1);
            hv.x = h0; hv.y = h1; lv.x = l0; lv.y = l1;
            *(bf162*)(Ch + (size_t)(row + 8) * ldC + col) = hv;
            *(bf162*)(Cl + (size_t)(row + 8) * ldC + col) = lv;
        }
    }
}

__device__ __forceinline__ void epi_vtrans(float (&c)[4][4][4], bf16* Ch, bf16* Cl,
                                           int m0, int n0, char* sm)
{
    const int tid = threadIdx.x;
    const int wid = tid >> 5, lane = tid & 31;
    const int wm = (wid & 1) * 64, wn = (wid >> 1) * 32;
    const int g = lane >> 2, tg = lane & 3;
    float* smf = (float*)sm;                 // 128 x 132 fp32
    #pragma unroll
    for (int mt = 0; mt < 4; mt++) {
        const int rr = wm + mt * 16 + g;
        #pragma unroll
        for (int nt = 0; nt < 4; nt++) {
            const int cc = wn + nt * 8 + tg * 2;
            smf[(size_t)cc * 132 + rr]           = c[mt][nt][0];
            smf[(size_t)(cc + 1) * 132 + rr]     = c[mt][nt][1];
            smf[(size_t)cc * 132 + rr + 8]       = c[mt][nt][2];
            smf[(size_t)(cc + 1) * 132 + rr + 8] = c[mt][nt][3];
        }
    }
    __syncthreads();
    const int b = m0 >> 11, t0 = m0 & (NT - 1);
    bf16* Hb = Ch + (size_t)b * ND * NT;
    bf16* Lb = Cl + (size_t)b * ND * NT;
    const int dsub = tid >> 6;
    const int tcol = tid & 63;
    #pragma unroll
    for (int it = 0; it < 32; it++) {
        const int d = it * 4 + dsub;
        float2 v = *(float2*)(smf + (size_t)d * 132 + tcol * 2);
        bf16 h0, h1, l0, l1;
        split2(v.x, h0, l0); split2(v.y, h1, l1);
        bf162 hv; hv.x = h0; hv.y = h1;
        bf162 lv; lv.x = l0; lv.y = l1;
        *(bf162*)(Hb + (size_t)(n0 + d) * NT + t0 + tcol * 2) = hv;
        *(bf162*)(Lb + (size_t)(n0 + d) * NT + t0 + tcol * 2) = lv;
    }
}

// ---------------------------------------------------------------------------
// Merged QKV projection: z = 0 Q, 1 K, 2 V(transposed). Skips padded rows.
// ---------------------------------------------------------------------------
__global__ __launch_bounds__(256, 1) void gemm_qkv(
    const bf16* __restrict__ xh, const bf16* __restrict__ xl,
    const bf16* __restrict__ wqh, const bf16* __restrict__ wql,
    const bf16* __restrict__ wkh, const bf16* __restrict__ wkl,
    const bf16* __restrict__ wvh, const bf16* __restrict__ wvl,
    bf16* __restrict__ Qh, bf16* __restrict__ Ql,
    bf16* __restrict__ Kh, bf16* __restrict__ Kl,
    bf16* __restrict__ Vth, bf16* __restrict__ Vtl,
    const int* __restrict__ lens)
{
    extern __shared__ __align__(128) char sm[];
    const int m0 = blockIdx.y * 128, n0 = blockIdx.x * 128;
    if ((m0 & (NT - 1)) >= lens[m0 >> 11]) return;
    const int z = blockIdx.z;

    const bf16 *Bh, *Bl;
    if (z == 0)      { Bh = wqh; Bl = wql; }
    else if (z == 1) { Bh = wkh; Bl = wkl; }
    else             { Bh = wvh; Bl = wvl; }

    float c[4][4][4];
    gemm_core(xh, xl, Bh, Bl, NE, NE / 64, m0, n0, sm, c);

    if (z == 0)      epi_split(c, Qh, Ql, ND, m0, n0);
    else if (z == 1) epi_split(c, Kh, Kl, ND, m0, n0);
    else             epi_vtrans(c, Vth, Vtl, m0, n0, sm);
}

// ---------------------------------------------------------------------------
// energy = Q K^T per batch (skip masked row/col blocks)
// ---------------------------------------------------------------------------
__global__ __launch_bounds__(256, 1) void gemm_qk(
    const bf16* __restrict__ Qh, const bf16* __restrict__ Ql,
    const bf16* __restrict__ Kh, const bf16* __restrict__ Kl,
    float* __restrict__ S, const int* __restrict__ lens)
{
    extern __shared__ __align__(128) char sm[];
    const int z = blockIdx.z;
    const int len = lens[z];
    const int m0 = blockIdx.y * 128, n0 = blockIdx.x * 128;
    if (m0 >= len || n0 >= len) return;

    const size_t off = (size_t)z * NT * ND;
    float c[4][4][4];
    gemm_core(Qh + off, Ql + off, Kh + off, Kl + off, ND, ND / 64, m0, n0, sm, c);
    epi_f32(c, S + (size_t)z * NT * NT, NT, m0, n0);
}

// ---------------------------------------------------------------------------
// out = P V per batch; skip rows >= len (filled by fill_pad_k), K bounded by len
// ---------------------------------------------------------------------------
__global__ __launch_bounds__(256, 1) void gemm_pv(
    const bf16* __restrict__ Ph, const bf16* __restrict__ Pl,
    const bf16* __restrict__ Vth, const bf16* __restrict__ Vtl,
    float* __restrict__ out, const int* __restrict__ lens)
{
    extern __shared__ __align__(128) char sm[];
    const int z = blockIdx.z;
    const int len = lens[z];
    const int m0 = blockIdx.y * 128, n0 = blockIdx.x * 128;
    if (m0 >= len) return;

    const int nkt = (len + 63) >> 6;
    const size_t offP = (size_t)z * NT * NT;
    const size_t offV = (size_t)z * ND * NT;
    float c[4][4][4];
    gemm_core(Ph + offP, Pl + offP, Vth + offV, Vtl + offV, NT, nkt, m0, n0, sm, c);
    epi_f32(c, out + (size_t)z * NT * ND, ND, m0, n0);
}

// ---------------------------------------------------------------------------
// masked row softmax -> split bf16 P, only rows t < ceil128(len); cols zeroed
// to ceil64(len). Rows in [len, ceil128(len)) get uniform 1/len.
// ---------------------------------------------------------------------------
__global__ __launch_bounds__(256) void softmax_split_k(const float* __restrict__ S,
                                                       bf16* __restrict__ Ph,
                                                       bf16* __restrict__ Pl,
                                                       const int* __restrict__ lens)
{
    __shared__ float cache[NT];
    __shared__ float red[256];
    const int row = blockIdx.x;
    const int b = row >> 11;
    const int t = row & (NT - 1);
    const int len = lens[b];
    const int rowmax = (len + 127) & ~127;
    if (t >= rowmax) return;
    const int colmax = (len + 63) & ~63;

    bf16* ph = Ph + (size_t)row * NT;
    bf16* pl = Pl + (size_t)row * NT;
    const int tid = threadIdx.x;
    const bf16 z0 = __float2bfloat16(0.f);

    if (t >= len) {
        const float v = 1.f / (float)len;
        bf16 h, l; split2(v, h, l);
        for (int s = tid; s < len; s += 256) { ph[s] = h; pl[s] = l; }
        for (int s = len + tid; s < colmax; s += 256) { ph[s] = z0; pl[s] = z0; }
        return;
    }

    const float* p = S + (size_t)row * NT;

    float m = -1e30f;
    for (int s = tid; s < len; s += 256) {
        float v = p[s];
        cache[s] = v;
        m = fmaxf(m, v);
    }
    red[tid] = m; __syncthreads();
    #pragma unroll
    for (int off = 128; off > 0; off >>= 1) {
        if (tid < off) red[tid] = fmaxf(red[tid], red[tid + off]);
        __syncthreads();
    }
    m = red[0]; __syncthreads();

    float sum = 0.f;
    for (int s = tid; s < len; s += 256) {
        float e = __expf((cache[s] - m) * 0.125f);
        cache[s] = e;
        sum += e;
    }
    red[tid] = sum; __syncthreads();
    #pragma unroll
    for (int off = 128; off > 0; off >>= 1) {
        if (tid < off) red[tid] += red[tid + off];
        __syncthreads();
    }
    const float inv = 1.f / red[0];

    for (int s = tid; s < len; s += 256) {
        bf16 h, l; split2(cache[s] * inv, h, l);
        ph[s] = h; pl[s] = l;
    }
    for (int s = len + tid; s < colmax; s += 256) { ph[s] = z0; pl[s] = z0; }
}

// ---------------------------------------------------------------------------
// bc[b][d] = (sum_{t<len} V[b][t][d]) / len   (from split transposed V)
// one warp per d
// ---------------------------------------------------------------------------
__global__ __launch_bounds__(256) void vsum_k(const bf16* __restrict__ Vth,
                                              const bf16* __restrict__ Vtl,
                                              float* __restrict__ bc,
                                              const int* __restrict__ lens)
{
    const int b = blockIdx.y;
    const int len = lens[b];
    const int d = blockIdx.x * 8 + (threadIdx.x >> 5);
    const int lane = threadIdx.x & 31;
    const bf16* ph = Vth + ((size_t)b * ND + d) * NT;
    const bf16* pl = Vtl + ((size_t)b * ND + d) * NT;
    float s = 0.f;
    for (int t = lane; t < len; t += 32)
        s += __bfloat162float(ph[t]) + __bfloat162float(pl[t]);
    #pragma unroll
    for (int o = 16; o > 0; o >>= 1) s += __shfl_xor_sync(0xffffffffu, s, o);
    if (lane == 0) bc[(size_t)b * ND + d] = s / (float)len;
}

// ---------------------------------------------------------------------------
// out[b][t][:] = bc[b][:] for t >= len
// ---------------------------------------------------------------------------
__global__ __launch_bounds__(256) void fill_pad_k(float* __restrict__ out,
                                                  const float* __restrict__ bc,
                                                  const int* __restrict__ lens)
{
    const int b = blockIdx.y;
    const int t = blockIdx.x;
    if (t < lens[b]) return;
    const float4* src = (const float4*)(bc + (size_t)b * ND);
    float4* dst = (float4*)(out + ((size_t)b * NT + t) * ND);
    for (int i = threadIdx.x; i < ND / 4; i += 256) dst[i] = src[i];
}

// ---------------------------------------------------------------------------
extern "C" void kernel_launch(void* const* d_in, const int* in_sizes, int n_in,
                              void* d_out, int out_size)
{
    const float* x  = (const float*)d_in[0];
    const float* Wq = (const float*)d_in[1];
    const float* Wk = (const float*)d_in[2];
    const float* Wv = (const float*)d_in[3];
    float* out = (float*)d_out;

    unsigned char* pool;
    int* lens;
    cudaGetSymbolAddress((void**)&pool, g_pool);
    cudaGetSymbolAddress((void**)&lens, g_len);

    bf16* xh  = (bf16*)(pool + OFF_XH);
    bf16* xl  = (bf16*)(pool + OFF_XL);
    bf16* wqh = (bf16*)(pool + OFF_WQH);
    bf16* wql = (bf16*)(pool + OFF_WQL);
    bf16* wkh = (bf16*)(pool + OFF_WKH);
    bf16* wkl = (bf16*)(pool + OFF_WKL);
    bf16* wvh = (bf16*)(pool + OFF_WVH);
    bf16* wvl = (bf16*)(pool + OFF_WVL);
    bf16* Qh  = (bf16*)(pool + OFF_QH);
    bf16* Ql  = (bf16*)(pool + OFF_QL);
    bf16* Kh  = (bf16*)(pool + OFF_KH);
    bf16* Kl  = (bf16*)(pool + OFF_KL);
    bf16* Vth = (bf16*)(pool + OFF_VTH);
    bf16* Vtl = (bf16*)(pool + OFF_VTL);
    float* S  = (float*)(pool + OFF_S);
    bf16* Ph  = (bf16*)(pool + OFF_PH);
    bf16* Pl  = (bf16*)(pool + OFF_PL);
    float* bc = (float*)(pool + OFF_BC);

    cudaFuncSetAttribute(gemm_qkv, cudaFuncAttributeMaxDynamicSharedMemorySize, SMEM_TOTAL);
    cudaFuncSetAttribute(gemm_qk,  cudaFuncAttributeMaxDynamicSharedMemorySize, SMEM_TOTAL);
    cudaFuncSetAttribute(gemm_pv,  cudaFuncAttributeMaxDynamicSharedMemorySize, SMEM_TOTAL);

    // 1) lengths + splits
    len_k<<<NB, 256>>>(x);
    split_k<<<(int)(SZ_X / 4 / 256), 256>>>(x, xh, xl, SZ_X / 4);
    dim3 tg(32, 32), tb(32, 8);
    trsplit_k<<<tg, tb>>>(Wq, wqh, wql);
    trsplit_k<<<tg, tb>>>(Wk, wkh, wkl);
    trsplit_k<<<tg, tb>>>(Wv, wvh, wvl);

    // 2) merged QKV projections (z = Q,K,V), padded row blocks skipped
    dim3 blk(256);
    dim3 gq(ND / 128, (NB * NT) / 128, 3);
    gemm_qkv<<<gq, blk, SMEM_TOTAL>>>(xh, xl, wqh, wql, wkh, wkl, wvh, wvl,
                                      Qh, Ql, Kh, Kl, Vth, Vtl, lens);

    // 2b) per-batch V column sums for padded output rows
    vsum_k<<<dim3(ND / 8, NB), 256>>>(Vth, Vtl, bc, lens);

    // 3) energy = Q K^T per batch
    dim3 ge(NT / 128, NT / 128, NB);
    gemm_qk<<<ge, blk, SMEM_TOTAL>>>(Qh, Ql, Kh, Kl, S, lens);

    // 4) masked softmax -> split P
    softmax_split_k<<<NB * NT, 256>>>(S, Ph, Pl, lens);

    // 5) out = P V per batch (valid rows only)
    dim3 go(ND / 128, NT / 128, NB);
    gemm_pv<<<go, blk, SMEM_TOTAL>>>(Ph, Pl, Vth, Vtl, out, lens);

    // 6) padded output rows = uniform average of valid V rows
    fill_pad_k<<<dim3(NT, NB), 256>>>(out, bc, lens);
}

// round 8
// speedup vs baseline: 2.7060x; 1.1905x over previous
#include <cuda_runtime.h>
#include <cuda_fp16.h>
#include <cstdint>

#define NB 8
#define NT 2048
#define NE 1024
#define ND 1024

constexpr size_t SZ_X = (size_t)NB * NT * NE;
constexpr size_t SZ_W = (size_t)NE * ND;
constexpr size_t SZ_S = (size_t)NB * NT * NT;

// ---- static scratch pool ----
constexpr size_t OFF_XH  = 0;
constexpr size_t OFF_XL  = OFF_XH  + SZ_X * 2;
constexpr size_t OFF_WQH = OFF_XL  + SZ_X * 2;
constexpr size_t OFF_WQL = OFF_WQH + SZ_W * 2;
constexpr size_t OFF_WKH = OFF_WQL + SZ_W * 2;
constexpr size_t OFF_WKL = OFF_WKH + SZ_W * 2;
constexpr size_t OFF_WVH = OFF_WKL + SZ_W * 2;
constexpr size_t OFF_QH  = OFF_WVH + SZ_W * 2;
constexpr size_t OFF_QL  = OFF_QH  + SZ_X * 2;
constexpr size_t OFF_KH  = OFF_QL  + SZ_X * 2;
constexpr size_t OFF_KL  = OFF_KH  + SZ_X * 2;
constexpr size_t OFF_VTH = OFF_KL  + SZ_X * 2;
constexpr size_t OFF_S   = OFF_VTH + SZ_X * 2;
constexpr size_t OFF_PH  = OFF_S   + SZ_S * 4;
constexpr size_t OFF_BC  = OFF_PH  + SZ_S * 2;
constexpr size_t POOL_SZ = OFF_BC  + (size_t)NB * ND * 4;

__device__ __align__(256) unsigned char g_pool[POOL_SZ];
__device__ int g_len[NB];

// ---------------------------------------------------------------------------
// fp16 hi + (scaled by 2048) lo split. Scaling keeps residuals in fp16
// normal range; the c2 accumulator is descaled by 1/2048 at fold time.
__device__ __forceinline__ void split2h(float v, __half& h, __half& l) {
    h = __float2half_rn(v);
    l = __float2half_rn((v - __half2float(h)) * 2048.f);
}

__device__ __forceinline__ void cp_async16(uint32_t dst, const void* src) {
    asm volatile("cp.async.cg.shared.global [%0], [%1], 16;\n"
                 :: "r"(dst), "l"(src) : "memory");
}

__device__ __forceinline__ uint32_t swz(uint32_t off) {
    return off ^ ((off >> 3) & 0x70);
}

__device__ __forceinline__ void ldm4(uint32_t* r, uint32_t a) {
    asm volatile("ldmatrix.sync.aligned.m8n8.x4.shared.b16 {%0,%1,%2,%3}, [%4];"
                 : "=r"(r[0]), "=r"(r[1]), "=r"(r[2]), "=r"(r[3]) : "r"(a));
}

__device__ __forceinline__ void mma_f16(float* c, const uint32_t* a, const uint32_t* b) {
    asm volatile(
        "mma.sync.aligned.m16n8k16.row.col.f32.f16.f16.f32 "
        "{%0,%1,%2,%3}, {%4,%5,%6,%7}, {%8,%9}, {%0,%1,%2,%3};\n"
        : "+f"(c[0]), "+f"(c[1]), "+f"(c[2]), "+f"(c[3])
        : "r"(a[0]), "r"(a[1]), "r"(a[2]), "r"(a[3]), "r"(b[0]), "r"(b[1]));
}

// ---------------------------------------------------------------------------
// per-batch valid length = number of nonzero rows of x[b]
// ---------------------------------------------------------------------------
__global__ __launch_bounds__(256) void len_k(const float* __restrict__ x)
{
    const int b = blockIdx.x;
    __shared__ int cnt;
    if (threadIdx.x == 0) cnt = 0;
    __syncthreads();
    int local = 0;
    for (int t = threadIdx.x; t < NT; t += blockDim.x) {
        const float4* row = (const float4*)(x + ((size_t)b * NT + t) * NE);
        bool nz = false;
        #pragma unroll 4
        for (int e = 0; e < NE / 4; e++) {
            float4 v = row[e];
            if (v.x != 0.f || v.y != 0.f || v.z != 0.f || v.w != 0.f) { nz = true; break; }
        }
        if (nz) local++;
    }
    atomicAdd(&cnt, local);
    __syncthreads();
    if (threadIdx.x == 0) g_len[b] = cnt;
}

// ---------------------------------------------------------------------------
__global__ __launch_bounds__(256) void split_k(const float* __restrict__ in,
                                               __half* __restrict__ h, __half* __restrict__ l,
                                               size_t n4)
{
    size_t i = (size_t)blockIdx.x * 256 + threadIdx.x;
    if (i >= n4) return;
    float4 v = ((const float4*)in)[i];
    __half h0, h1, h2, h3, l0, l1, l2, l3;
    split2h(v.x, h0, l0); split2h(v.y, h1, l1);
    split2h(v.z, h2, l2); split2h(v.w, h3, l3);
    __half2* hp = (__half2*)(h + i * 4);
    __half2* lp = (__half2*)(l + i * 4);
    hp[0] = __halves2half2(h0, h1); hp[1] = __halves2half2(h2, h3);
    lp[0] = __halves2half2(l0, l1); lp[1] = __halves2half2(l2, l3);
}

// W [E][N] fp32 -> transposed split Wt[n][e]; Tl may be null (hi-only)
__global__ __launch_bounds__(256) void trsplit_k(const float* __restrict__ W,
                                                 __half* __restrict__ Th, __half* __restrict__ Tl)
{
    __shared__ float tile[32][33];
    const int bn = blockIdx.x * 32;
    const int be = blockIdx.y * 32;
    const int tx = threadIdx.x, ty = threadIdx.y;
    #pragma unroll
    for (int r = 0; r < 4; r++)
        tile[ty + r * 8][tx] = W[(size_t)(be + ty + r * 8) * ND + bn + tx];
    __syncthreads();
    #pragma unroll
    for (int r = 0; r < 4; r++) {
        float v = tile[tx][ty + r * 8];
        __half h, l; split2h(v, h, l);
        size_t o = (size_t)(bn + ty + r * 8) * NE + be + tx;
        Th[o] = h;
        if (Tl) Tl[o] = l;
    }
}

// ---------------------------------------------------------------------------
// HMMA TN GEMM core, fp16 limbs, TERMS = 3 / 2 / 1:
//   3: c = Ah·Bh + (Ah·Bl + Al·Bh)/2048   (both operands hi + scaled-lo)
//   2: c = Ah·Bh + (Al·Bh)/2048           (A split, B hi only)
//   1: c = Ah·Bh
// ldmatrix + SW128, Ktile 64, 3-stage cp.async pipeline.
// ---------------------------------------------------------------------------
constexpr int SUB = 128 * 128;
constexpr int STAGE = 4 * SUB;
constexpr int NSTAGE = 3;
constexpr int SMEM_TOTAL = NSTAGE * STAGE;   // 196608

template<int TERMS>
__device__ __forceinline__ void gemm_core(
    const __half* __restrict__ Ah, const __half* __restrict__ Al,
    const __half* __restrict__ Bh, const __half* __restrict__ Bl,
    int Kdim, int nkt, int m0, int n0, char* sm, float (&c)[4][4][4])
{
    const int tid = threadIdx.x;
    const int wid = tid >> 5, lane = tid & 31;
    const int wm = (wid & 1) * 64;
    const int wn = (wid >> 1) * 32;

    const int a_row = (lane & 7) + ((lane >> 3) & 1) * 8;
    const int a_chk = lane >> 4;
    const int b_row = (lane & 7) + (lane >> 4) * 8;
    const int b_chk = (lane >> 3) & 1;

    const uint32_t smb = (uint32_t)__cvta_generic_to_shared(sm);

    float c2[4][4][4];
    #pragma unroll
    for (int i = 0; i < 4; i++)
        #pragma unroll
        for (int j = 0; j < 4; j++)
            #pragma unroll
            for (int t = 0; t < 4; t++) { c[i][j][t] = 0.f; if (TERMS >= 2) c2[i][j][t] = 0.f; }

    const int r = tid >> 1;
    const int c0 = (tid & 1) * 4;
    const size_t arow = (size_t)(m0 + r) * Kdim;
    const size_t brow = (size_t)(n0 + r) * Kdim;

    auto load_stage = [&](int buf, int k0) {
        const uint32_t sbase = smb + buf * STAGE;
        #pragma unroll
        for (int j = 0; j < 4; j++) {
            const int cc = c0 + j;
            const uint32_t so = swz(r * 128 + cc * 16);
            const size_t ko = (size_t)k0 + cc * 8;
            cp_async16(sbase + so,           Ah + arow + ko);
            if (TERMS >= 2) cp_async16(sbase + SUB + so, Al + arow + ko);
            cp_async16(sbase + 2 * SUB + so, Bh + brow + ko);
            if (TERMS == 3) cp_async16(sbase + 3 * SUB + so, Bl + brow + ko);
        }
        asm volatile("cp.async.commit_group;" ::: "memory");
    };

    load_stage(0, 0);
    load_stage(1, 64);

    int buf = 0;
    for (int i = 0; i < nkt; i++) {
        if (i + 1 < nkt) {
            asm volatile("cp.async.wait_group 1;" ::: "memory");
        } else {
            asm volatile("cp.async.wait_group 0;" ::: "memory");
        }
        __syncthreads();

        if (i + 2 < nkt) {
            int nb = buf + 2; if (nb >= NSTAGE) nb -= NSTAGE;
            load_stage(nb, (i + 2) * 64);
        }

        const uint32_t ahb = smb + buf * STAGE;
        const uint32_t alb = ahb + SUB;
        const uint32_t bhb = ahb + 2 * SUB;
        const uint32_t blb = ahb + 3 * SUB;

        #pragma unroll
        for (int kc = 0; kc < 8; kc += 2) {
            uint32_t bh[8], a[4][4];
            const uint32_t boff0 = swz((wn + b_row) * 128 + (kc + b_chk) * 16);
            const uint32_t boff1 = swz((wn + 16 + b_row) * 128 + (kc + b_chk) * 16);
            ldm4(bh + 0, bhb + boff0); ldm4(bh + 4, bhb + boff1);

            #pragma unroll
            for (int mt = 0; mt < 4; mt++) {
                const uint32_t off = swz((wm + mt * 16 + a_row) * 128 + (kc + a_chk) * 16);
                ldm4(a[mt], ahb + off);
            }
            // Ah * Bh -> c
            #pragma unroll
            for (int mt = 0; mt < 4; mt++)
                #pragma unroll
                for (int nt = 0; nt < 4; nt++)
                    mma_f16(c[mt][nt], a[mt], &bh[nt * 2]);

            if (TERMS == 3) {
                uint32_t bl[8];
                ldm4(bl + 0, blb + boff0); ldm4(bl + 4, blb + boff1);
                // Ah * Bl -> c2
                #pragma unroll
                for (int mt = 0; mt < 4; mt++)
                    #pragma unroll
                    for (int nt = 0; nt < 4; nt++)
                        mma_f16(c2[mt][nt], a[mt], &bl[nt * 2]);
            }
            if (TERMS >= 2) {
                #pragma unroll
                for (int mt = 0; mt < 4; mt++) {
                    const uint32_t off = swz((wm + mt * 16 + a_row) * 128 + (kc + a_chk) * 16);
                    ldm4(a[mt], alb + off);
                }
                // Al * Bh -> c2
                #pragma unroll
                for (int mt = 0; mt < 4; mt++)
                    #pragma unroll
                    for (int nt = 0; nt < 4; nt++)
                        mma_f16(c2[mt][nt], a[mt], &bh[nt * 2]);
            }
        }

        if (++buf >= NSTAGE) buf = 0;
    }

    if (TERMS >= 2) {
        constexpr float DS = 1.f / 2048.f;
        #pragma unroll
        for (int i = 0; i < 4; i++)
            #pragma unroll
            for (int j = 0; j < 4; j++)
                #pragma unroll
                for (int t = 0; t < 4; t++) c[i][j][t] += c2[i][j][t] * DS;
    }
    __syncthreads();   // smem safe for epilogue reuse
}

// ---- epilogues ----
__device__ __forceinline__ void epi_f32(float (&c)[4][4][4], float* Cz, int ldC,
                                        int m0, int n0)
{
    const int tid = threadIdx.x;
    const int wid = tid >> 5, lane = tid & 31;
    const int wm = (wid & 1) * 64, wn = (wid >> 1) * 32;
    const int g = lane >> 2, tg = lane & 3;
    #pragma unroll
    for (int mt = 0; mt < 4; mt++) {
        const int row = m0 + wm + mt * 16 + g;
        #pragma unroll
        for (int nt = 0; nt < 4; nt++) {
            const int col = n0 + wn + nt * 8 + tg * 2;
            *(float2*)(Cz + (size_t)row * ldC + col)       = make_float2(c[mt][nt][0], c[mt][nt][1]);
            *(float2*)(Cz + (size_t)(row + 8) * ldC + col) = make_float2(c[mt][nt][2], c[mt][nt][3]);
        }
    }
}

__device__ __forceinline__ void epi_split(float (&c)[4][4][4], __half* Ch, __half* Cl,
                                          int ldC, int m0, int n0)
{
    const int tid = threadIdx.x;
    const int wid = tid >> 5, lane = tid & 31;
    const int wm = (wid & 1) * 64, wn = (wid >> 1) * 32;
    const int g = lane >> 2, tg = lane & 3;
    #pragma unroll
    for (int mt = 0; mt < 4; mt++) {
        const int row = m0 + wm + mt * 16 + g;
        #pragma unroll
        for (int nt = 0; nt < 4; nt++) {
            const int col = n0 + wn + nt * 8 + tg * 2;
            __half h0, h1, l0, l1;
            split2h(c[mt][nt][0], h0, l0); split2h(c[mt][nt][1], h1, l1);
            *(__half2*)(Ch + (size_t)row * ldC + col) = __halves2half2(h0, h1);
            *(__half2*)(Cl + (size_t)row * ldC + col) = __halves2half2(l0, l1);
            split2h(c[mt][nt][2], h0, l0); split2h(c[mt][nt][3], h1, l1);
            *(__half2*)(Ch + (size_t)(row + 8) * ldC + col) = __halves2half2(h0, h1);
            *(__half2*)(Cl + (size_t)(row + 8) * ldC + col) = __halves2half2(l0, l1);
        }
    }
}

__device__ __forceinline__ void epi_vtrans(float (&c)[4][4][4], __half* Ch,
                                           int m0, int n0, char* sm)
{
    const int tid = threadIdx.x;
    const int wid = tid >> 5, lane = tid & 31;
    const int wm = (wid & 1) * 64, wn = (wid >> 1) * 32;
    const int g = lane >> 2, tg = lane & 3;
    float* smf = (float*)sm;                 // 128 x 132 fp32
    #pragma unroll
    for (int mt = 0; mt < 4; mt++) {
        const int rr = wm + mt * 16 + g;
        #pragma unroll
        for (int nt = 0; nt < 4; nt++) {
            const int cc = wn + nt * 8 + tg * 2;
            smf[(size_t)cc * 132 + rr]           = c[mt][nt][0];
            smf[(size_t)(cc + 1) * 132 + rr]     = c[mt][nt][1];
            smf[(size_t)cc * 132 + rr + 8]       = c[mt][nt][2];
            smf[(size_t)(cc + 1) * 132 + rr + 8] = c[mt][nt][3];
        }
    }
    __syncthreads();
    const int b = m0 >> 11, t0 = m0 & (NT - 1);
    __half* Hb = Ch + (size_t)b * ND * NT;
    const int dsub = tid >> 6;
    const int tcol = tid & 63;
    #pragma unroll
    for (int it = 0; it < 32; it++) {
        const int d = it * 4 + dsub;
        float2 v = *(float2*)(smf + (size_t)d * 132 + tcol * 2);
        *(__half2*)(Hb + (size_t)(n0 + d) * NT + t0 + tcol * 2) =
            __halves2half2(__float2half_rn(v.x), __float2half_rn(v.y));
    }
}

// ---------------------------------------------------------------------------
// Q/K projections (z = 0 Q, 1 K), TERMS=3, skip padded row blocks
// ---------------------------------------------------------------------------
__global__ __launch_bounds__(256, 1) void gemm_qkproj(
    const __half* __restrict__ xh, const __half* __restrict__ xl,
    const __half* __restrict__ wqh, const __half* __restrict__ wql,
    const __half* __restrict__ wkh, const __half* __restrict__ wkl,
    __half* __restrict__ Qh, __half* __restrict__ Ql,
    __half* __restrict__ Kh, __half* __restrict__ Kl,
    const int* __restrict__ lens)
{
    extern __shared__ __align__(128) char sm[];
    const int m0 = blockIdx.y * 128, n0 = blockIdx.x * 128;
    if ((m0 & (NT - 1)) >= lens[m0 >> 11]) return;
    const int z = blockIdx.z;

    float c[4][4][4];
    gemm_core<3>(xh, xl, z ? wkh : wqh, z ? wkl : wql, NE, NE / 64, m0, n0, sm, c);
    epi_split(c, z ? Kh : Qh, z ? Kl : Ql, ND, m0, n0);
}

// ---------------------------------------------------------------------------
// V projection, TERMS=2, transposed hi-only output
// ---------------------------------------------------------------------------
__global__ __launch_bounds__(256, 1) void gemm_vproj(
    const __half* __restrict__ xh, const __half* __restrict__ xl,
    const __half* __restrict__ wvh,
    __half* __restrict__ Vth, const int* __restrict__ lens)
{
    extern __shared__ __align__(128) char sm[];
    const int m0 = blockIdx.y * 128, n0 = blockIdx.x * 128;
    if ((m0 & (NT - 1)) >= lens[m0 >> 11]) return;

    float c[4][4][4];
    gemm_core<2>(xh, xl, wvh, wvh, NE, NE / 64, m0, n0, sm, c);
    epi_vtrans(c, Vth, m0, n0, sm);
}

// ---------------------------------------------------------------------------
// energy = Q K^T per batch, TERMS=3 (skip masked row/col blocks)
// ---------------------------------------------------------------------------
__global__ __launch_bounds__(256, 1) void gemm_qk(
    const __half* __restrict__ Qh, const __half* __restrict__ Ql,
    const __half* __restrict__ Kh, const __half* __restrict__ Kl,
    float* __restrict__ S, const int* __restrict__ lens)
{
    extern __shared__ __align__(128) char sm[];
    const int z = blockIdx.z;
    const int len = lens[z];
    const int m0 = blockIdx.y * 128, n0 = blockIdx.x * 128;
    if (m0 >= len || n0 >= len) return;

    const size_t off = (size_t)z * NT * ND;
    float c[4][4][4];
    gemm_core<3>(Qh + off, Ql + off, Kh + off, Kl + off, ND, ND / 64, m0, n0, sm, c);
    epi_f32(c, S + (size_t)z * NT * NT, NT, m0, n0);
}

// ---------------------------------------------------------------------------
// out = P V per batch, TERMS=1; rows >= len handled by fill_pad_k
// ---------------------------------------------------------------------------
__global__ __launch_bounds__(256, 1) void gemm_pv(
    const __half* __restrict__ Ph,
    const __half* __restrict__ Vth,
    float* __restrict__ out, const int* __restrict__ lens)
{
    extern __shared__ __align__(128) char sm[];
    const int z = blockIdx.z;
    const int len = lens[z];
    const int m0 = blockIdx.y * 128, n0 = blockIdx.x * 128;
    if (m0 >= len) return;

    const int nkt = (len + 63) >> 6;
    const __half* P = Ph + (size_t)z * NT * NT;
    const __half* V = Vth + (size_t)z * ND * NT;
    float c[4][4][4];
    gemm_core<1>(P, P, V, V, NT, nkt, m0, n0, sm, c);
    epi_f32(c, out + (size_t)z * NT * ND, ND, m0, n0);
}

// ---------------------------------------------------------------------------
// masked row softmax -> fp16 P (single limb); rows t in [len, ceil128(len))
// get uniform 1/len; columns zeroed to ceil64(len).
// ---------------------------------------------------------------------------
__global__ __launch_bounds__(256) void softmax_h_k(const float* __restrict__ S,
                                                   __half* __restrict__ Ph,
                                                   const int* __restrict__ lens)
{
    __shared__ float cache[NT];
    __shared__ float red[256];
    const int row = blockIdx.x;
    const int b = row >> 11;
    const int t = row & (NT - 1);
    const int len = lens[b];
    const int rowmax = (len + 127) & ~127;
    if (t >= rowmax) return;
    const int colmax = (len + 63) & ~63;

    __half* ph = Ph + (size_t)row * NT;
    const int tid = threadIdx.x;
    const __half z0 = __float2half_rn(0.f);

    if (t >= len) {
        const __half h = __float2half_rn(1.f / (float)len);
        for (int s = tid; s < len; s += 256) ph[s] = h;
        for (int s = len + tid; s < colmax; s += 256) ph[s] = z0;
        return;
    }

    const float* p = S + (size_t)row * NT;

    float m = -1e30f;
    for (int s = tid; s < len; s += 256) {
        float v = p[s];
        cache[s] = v;
        m = fmaxf(m, v);
    }
    red[tid] = m; __syncthreads();
    #pragma unroll
    for (int off = 128; off > 0; off >>= 1) {
        if (tid < off) red[tid] = fmaxf(red[tid], red[tid + off]);
        __syncthreads();
    }
    m = red[0]; __syncthreads();

    float sum = 0.f;
    for (int s = tid; s < len; s += 256) {
        float e = __expf((cache[s] - m) * 0.125f);
        cache[s] = e;
        sum += e;
    }
    red[tid] = sum; __syncthreads();
    #pragma unroll
    for (int off = 128; off > 0; off >>= 1) {
        if (tid < off) red[tid] += red[tid + off];
        __syncthreads();
    }
    const float inv = 1.f / red[0];

    for (int s = tid; s < len; s += 256)
        ph[s] = __float2half_rn(cache[s] * inv);
    for (int s = len + tid; s < colmax; s += 256) ph[s] = z0;
}

// ---------------------------------------------------------------------------
// bc[b][d] = (sum_{t<len} V[b][t][d]) / len
// ---------------------------------------------------------------------------
__global__ __launch_bounds__(256) void vsum_k(const __half* __restrict__ Vth,
                                              float* __restrict__ bc,
                                              const int* __restrict__ lens)
{
    const int b = blockIdx.y;
    const int len = lens[b];
    const int d = blockIdx.x * 8 + (threadIdx.x >> 5);
    const int lane = threadIdx.x & 31;
    const __half* ph = Vth + ((size_t)b * ND + d) * NT;
    float s = 0.f;
    for (int t = lane; t < len; t += 32)
        s += __half2float(ph[t]);
    #pragma unroll
    for (int o = 16; o > 0; o >>= 1) s += __shfl_xor_sync(0xffffffffu, s, o);
    if (lane == 0) bc[(size_t)b * ND + d] = s / (float)len;
}

// ---------------------------------------------------------------------------
__global__ __launch_bounds__(256) void fill_pad_k(float* __restrict__ out,
                                                  const float* __restrict__ bc,
                                                  const int* __restrict__ lens)
{
    const int b = blockIdx.y;
    const int t = blockIdx.x;
    if (t < lens[b]) return;
    const float4* src = (const float4*)(bc + (size_t)b * ND);
    float4* dst = (float4*)(out + ((size_t)b * NT + t) * ND);
    for (int i = threadIdx.x; i < ND / 4; i += 256) dst[i] = src[i];
}

// ---------------------------------------------------------------------------
extern "C" void kernel_launch(void* const* d_in, const int* in_sizes, int n_in,
                              void* d_out, int out_size)
{
    const float* x  = (const float*)d_in[0];
    const float* Wq = (const float*)d_in[1];
    const float* Wk = (const float*)d_in[2];
    const float* Wv = (const float*)d_in[3];
    float* out = (float*)d_out;

    unsigned char* pool;
    int* lens;
    cudaGetSymbolAddress((void**)&pool, g_pool);
    cudaGetSymbolAddress((void**)&lens, g_len);

    __half* xh  = (__half*)(pool + OFF_XH);
    __half* xl  = (__half*)(pool + OFF_XL);
    __half* wqh = (__half*)(pool + OFF_WQH);
    __half* wql = (__half*)(pool + OFF_WQL);
    __half* wkh = (__half*)(pool + OFF_WKH);
    __half* wkl = (__half*)(pool + OFF_WKL);
    __half* wvh = (__half*)(pool + OFF_WVH);
    __half* Qh  = (__half*)(pool + OFF_QH);
    __half* Ql  = (__half*)(pool + OFF_QL);
    __half* Kh  = (__half*)(pool + OFF_KH);
    __half* Kl  = (__half*)(pool + OFF_KL);
    __half* Vth = (__half*)(pool + OFF_VTH);
    float* S  = (float*)(pool + OFF_S);
    __half* Ph  = (__half*)(pool + OFF_PH);
    float* bc = (float*)(pool + OFF_BC);

    cudaFuncSetAttribute(gemm_qkproj, cudaFuncAttributeMaxDynamicSharedMemorySize, SMEM_TOTAL);
    cudaFuncSetAttribute(gemm_vproj,  cudaFuncAttributeMaxDynamicSharedMemorySize, SMEM_TOTAL);
    cudaFuncSetAttribute(gemm_qk,     cudaFuncAttributeMaxDynamicSharedMemorySize, SMEM_TOTAL);
    cudaFuncSetAttribute(gemm_pv,     cudaFuncAttributeMaxDynamicSharedMemorySize, SMEM_TOTAL);

    // 1) lengths + splits
    len_k<<<NB, 256>>>(x);
    split_k<<<(int)(SZ_X / 4 / 256), 256>>>(x, xh, xl, SZ_X / 4);
    dim3 tg(32, 32), tb(32, 8);
    trsplit_k<<<tg, tb>>>(Wq, wqh, wql);
    trsplit_k<<<tg, tb>>>(Wk, wkh, wkl);
    trsplit_k<<<tg, tb>>>(Wv, wvh, nullptr);

    // 2) projections
    dim3 blk(256);
    dim3 gq(ND / 128, (NB * NT) / 128, 2);
    gemm_qkproj<<<gq, blk, SMEM_TOTAL>>>(xh, xl, wqh, wql, wkh, wkl,
                                         Qh, Ql, Kh, Kl, lens);
    dim3 gv(ND / 128, (NB * NT) / 128, 1);
    gemm_vproj<<<gv, blk, SMEM_TOTAL>>>(xh, xl, wvh, Vth, lens);

    // 2b) per-batch V column means for padded output rows
    vsum_k<<<dim3(ND / 8, NB), 256>>>(Vth, bc, lens);

    // 3) energy = Q K^T per batch
    dim3 ge(NT / 128, NT / 128, NB);
    gemm_qk<<<ge, blk, SMEM_TOTAL>>>(Qh, Ql, Kh, Kl, S, lens);

    // 4) masked softmax -> fp16 P
    softmax_h_k<<<NB * NT, 256>>>(S, Ph, lens);

    // 5) out = P V per batch (valid rows only)
    dim3 go(ND / 128, NT / 128, NB);
    gemm_pv<<<go, blk, SMEM_TOTAL>>>(Ph, Vth, out, lens);

    // 6) padded output rows = uniform average of valid V rows
    fill_pad_k<<<dim3(NT, NB), 256>>>(out, bc, lens);
}

// round 11
// speedup vs baseline: 3.0314x; 1.1203x over previous
#include <cuda_runtime.h>
#include <cuda_fp16.h>
#include <cstdint>

#define NB 8
#define NT 2048
#define NE 1024
#define ND 1024

constexpr size_t SZ_X = (size_t)NB * NT * NE;
constexpr size_t SZ_W = (size_t)NE * ND;
constexpr size_t SZ_S = (size_t)NB * NT * NT;

// ---- static scratch pool ----
constexpr size_t OFF_XH  = 0;
constexpr size_t OFF_XL  = OFF_XH  + SZ_X * 2;
constexpr size_t OFF_WQH = OFF_XL  + SZ_X * 2;
constexpr size_t OFF_WQL = OFF_WQH + SZ_W * 2;
constexpr size_t OFF_WKH = OFF_WQL + SZ_W * 2;
constexpr size_t OFF_WKL = OFF_WKH + SZ_W * 2;
constexpr size_t OFF_WVH = OFF_WKL + SZ_W * 2;
constexpr size_t OFF_MTH = OFF_WVH + SZ_W * 2;
constexpr size_t OFF_MTL = OFF_MTH + SZ_W * 2;
constexpr size_t OFF_YH  = OFF_MTL + SZ_W * 2;
constexpr size_t OFF_YL  = OFF_YH  + SZ_X * 2;
constexpr size_t OFF_VTH = OFF_YL  + SZ_X * 2;
constexpr size_t OFF_S   = OFF_VTH + SZ_X * 2;
constexpr size_t OFF_PH  = OFF_S   + SZ_S * 4;
constexpr size_t OFF_BC  = OFF_PH  + SZ_S * 2;
constexpr size_t POOL_SZ = OFF_BC  + (size_t)NB * ND * 4;

__device__ __align__(256) unsigned char g_pool[POOL_SZ];
__device__ int g_len[NB];

// ---------------------------------------------------------------------------
// fp16 hi + (scaled by 2048) lo split.
__device__ __forceinline__ void split2h(float v, __half& h, __half& l) {
    h = __float2half_rn(v);
    l = __float2half_rn((v - __half2float(h)) * 2048.f);
}

__device__ __forceinline__ void cp_async16(uint32_t dst, const void* src) {
    asm volatile("cp.async.cg.shared.global [%0], [%1], 16;\n"
                 :: "r"(dst), "l"(src) : "memory");
}

__device__ __forceinline__ uint32_t swz(uint32_t off) {
    return off ^ ((off >> 3) & 0x70);
}

__device__ __forceinline__ void ldm4(uint32_t* r, uint32_t a) {
    asm volatile("ldmatrix.sync.aligned.m8n8.x4.shared.b16 {%0,%1,%2,%3}, [%4];"
                 : "=r"(r[0]), "=r"(r[1]), "=r"(r[2]), "=r"(r[3]) : "r"(a));
}

__device__ __forceinline__ void mma_f16(float* c, const uint32_t* a, const uint32_t* b) {
    asm volatile(
        "mma.sync.aligned.m16n8k16.row.col.f32.f16.f16.f32 "
        "{%0,%1,%2,%3}, {%4,%5,%6,%7}, {%8,%9}, {%0,%1,%2,%3};\n"
        : "+f"(c[0]), "+f"(c[1]), "+f"(c[2]), "+f"(c[3])
        : "r"(a[0]), "r"(a[1]), "r"(a[2]), "r"(a[3]), "r"(b[0]), "r"(b[1]));
}

// ---------------------------------------------------------------------------
__global__ __launch_bounds__(256) void len_k(const float* __restrict__ x)
{
    const int b = blockIdx.x;
    __shared__ int cnt;
    if (threadIdx.x == 0) cnt = 0;
    __syncthreads();
    int local = 0;
    for (int t = threadIdx.x; t < NT; t += blockDim.x) {
        const float4* row = (const float4*)(x + ((size_t)b * NT + t) * NE);
        bool nz = false;
        #pragma unroll 4
        for (int e = 0; e < NE / 4; e++) {
            float4 v = row[e];
            if (v.x != 0.f || v.y != 0.f || v.z != 0.f || v.w != 0.f) { nz = true; break; }
        }
        if (nz) local++;
    }
    atomicAdd(&cnt, local);
    __syncthreads();
    if (threadIdx.x == 0) g_len[b] = cnt;
}

// ---------------------------------------------------------------------------
__global__ __launch_bounds__(256) void split_k(const float* __restrict__ in,
                                               __half* __restrict__ h, __half* __restrict__ l,
                                               size_t n4)
{
    size_t i = (size_t)blockIdx.x * 256 + threadIdx.x;
    if (i >= n4) return;
    float4 v = ((const float4*)in)[i];
    __half h0, h1, h2, h3, l0, l1, l2, l3;
    split2h(v.x, h0, l0); split2h(v.y, h1, l1);
    split2h(v.z, h2, l2); split2h(v.w, h3, l3);
    __half2* hp = (__half2*)(h + i * 4);
    __half2* lp = (__half2*)(l + i * 4);
    hp[0] = __halves2half2(h0, h1); hp[1] = __halves2half2(h2, h3);
    lp[0] = __halves2half2(l0, l1); lp[1] = __halves2half2(l2, l3);
}

// W [E][N] fp32 -> transposed hi-only Wt[n][e]
__global__ __launch_bounds__(256) void trsplit_k(const float* __restrict__ W,
                                                 __half* __restrict__ Th)
{
    __shared__ float tile[32][33];
    const int bn = blockIdx.x * 32;
    const int be = blockIdx.y * 32;
    const int tx = threadIdx.x, ty = threadIdx.y;
    #pragma unroll
    for (int r = 0; r < 4; r++)
        tile[ty + r * 8][tx] = W[(size_t)(be + ty + r * 8) * ND + bn + tx];
    __syncthreads();
    #pragma unroll
    for (int r = 0; r < 4; r++) {
        float v = tile[tx][ty + r * 8];
        Th[(size_t)(bn + ty + r * 8) * NE + be + tx] = __float2half_rn(v);
    }
}

// ---------------------------------------------------------------------------
// HMMA TN GEMM core, fp16 limbs, TERMS = 3 / 2 / 1.
// ---------------------------------------------------------------------------
constexpr int SUB = 128 * 128;
constexpr int STAGE = 4 * SUB;
constexpr int NSTAGE = 3;
constexpr int SMEM_TOTAL = NSTAGE * STAGE;   // 196608

template<int TERMS>
__device__ __forceinline__ void gemm_core(
    const __half* __restrict__ Ah, const __half* __restrict__ Al,
    const __half* __restrict__ Bh, const __half* __restrict__ Bl,
    int Kdim, int nkt, int m0, int n0, char* sm, float (&c)[4][4][4])
{
    const int tid = threadIdx.x;
    const int wid = tid >> 5, lane = tid & 31;
    const int wm = (wid & 1) * 64;
    const int wn = (wid >> 1) * 32;

    const int a_row = (lane & 7) + ((lane >> 3) & 1) * 8;
    const int a_chk = lane >> 4;
    const int b_row = (lane & 7) + (lane >> 4) * 8;
    const int b_chk = (lane >> 3) & 1;

    const uint32_t smb = (uint32_t)__cvta_generic_to_shared(sm);

    float c2[4][4][4];
    #pragma unroll
    for (int i = 0; i < 4; i++)
        #pragma unroll
        for (int j = 0; j < 4; j++)
            #pragma unroll
            for (int t = 0; t < 4; t++) { c[i][j][t] = 0.f; if (TERMS >= 2) c2[i][j][t] = 0.f; }

    const int r = tid >> 1;
    const int c0 = (tid & 1) * 4;
    const size_t arow = (size_t)(m0 + r) * Kdim;
    const size_t brow = (size_t)(n0 + r) * Kdim;

    auto load_stage = [&](int buf, int k0) {
        const uint32_t sbase = smb + buf * STAGE;
        #pragma unroll
        for (int j = 0; j < 4; j++) {
            const int cc = c0 + j;
            const uint32_t so = swz(r * 128 + cc * 16);
            const size_t ko = (size_t)k0 + cc * 8;
            cp_async16(sbase + so,           Ah + arow + ko);
            if (TERMS >= 2) cp_async16(sbase + SUB + so, Al + arow + ko);
            cp_async16(sbase + 2 * SUB + so, Bh + brow + ko);
            if (TERMS == 3) cp_async16(sbase + 3 * SUB + so, Bl + brow + ko);
        }
        asm volatile("cp.async.commit_group;" ::: "memory");
    };

    load_stage(0, 0);
    load_stage(1, 64);

    int buf = 0;
    for (int i = 0; i < nkt; i++) {
        if (i + 1 < nkt) {
            asm volatile("cp.async.wait_group 1;" ::: "memory");
        } else {
            asm volatile("cp.async.wait_group 0;" ::: "memory");
        }
        __syncthreads();

        if (i + 2 < nkt) {
            int nb = buf + 2; if (nb >= NSTAGE) nb -= NSTAGE;
            load_stage(nb, (i + 2) * 64);
        }

        const uint32_t ahb = smb + buf * STAGE;
        const uint32_t alb = ahb + SUB;
        const uint32_t bhb = ahb + 2 * SUB;
        const uint32_t blb = ahb + 3 * SUB;

        #pragma unroll
        for (int kc = 0; kc < 8; kc += 2) {
            uint32_t bh[8], a[4][4];
            const uint32_t boff0 = swz((wn + b_row) * 128 + (kc + b_chk) * 16);
            const uint32_t boff1 = swz((wn + 16 + b_row) * 128 + (kc + b_chk) * 16);
            ldm4(bh + 0, bhb + boff0); ldm4(bh + 4, bhb + boff1);

            #pragma unroll
            for (int mt = 0; mt < 4; mt++) {
                const uint32_t off = swz((wm + mt * 16 + a_row) * 128 + (kc + a_chk) * 16);
                ldm4(a[mt], ahb + off);
            }
            #pragma unroll
            for (int mt = 0; mt < 4; mt++)
                #pragma unroll
                for (int nt = 0; nt < 4; nt++)
                    mma_f16(c[mt][nt], a[mt], &bh[nt * 2]);

            if (TERMS == 3) {
                uint32_t bl[8];
                ldm4(bl + 0, blb + boff0); ldm4(bl + 4, blb + boff1);
                #pragma unroll
                for (int mt = 0; mt < 4; mt++)
                    #pragma unroll
                    for (int nt = 0; nt < 4; nt++)
                        mma_f16(c2[mt][nt], a[mt], &bl[nt * 2]);
            }
            if (TERMS >= 2) {
                #pragma unroll
                for (int mt = 0; mt < 4; mt++) {
                    const uint32_t off = swz((wm + mt * 16 + a_row) * 128 + (kc + a_chk) * 16);
                    ldm4(a[mt], alb + off);
                }
                #pragma unroll
                for (int mt = 0; mt < 4; mt++)
                    #pragma unroll
                    for (int nt = 0; nt < 4; nt++)
                        mma_f16(c2[mt][nt], a[mt], &bh[nt * 2]);
            }
        }

        if (++buf >= NSTAGE) buf = 0;
    }

    if (TERMS >= 2) {
        constexpr float DS = 1.f / 2048.f;
        #pragma unroll
        for (int i = 0; i < 4; i++)
            #pragma unroll
            for (int j = 0; j < 4; j++)
                #pragma unroll
                for (int t = 0; t < 4; t++) c[i][j][t] += c2[i][j][t] * DS;
    }
    __syncthreads();
}

// ---- epilogues ----
__device__ __forceinline__ void epi_f32(float (&c)[4][4][4], float* Cz, int ldC,
                                        int m0, int n0)
{
    const int tid = threadIdx.x;
    const int wid = tid >> 5, lane = tid & 31;
    const int wm = (wid & 1) * 64, wn = (wid >> 1) * 32;
    const int g = lane >> 2, tg = lane & 3;
    #pragma unroll
    for (int mt = 0; mt < 4; mt++) {
        const int row = m0 + wm + mt * 16 + g;
        #pragma unroll
        for (int nt = 0; nt < 4; nt++) {
            const int col = n0 + wn + nt * 8 + tg * 2;
            *(float2*)(Cz + (size_t)row * ldC + col)       = make_float2(c[mt][nt][0], c[mt][nt][1]);
            *(float2*)(Cz + (size_t)(row + 8) * ldC + col) = make_float2(c[mt][nt][2], c[mt][nt][3]);
        }
    }
}

__device__ __forceinline__ void epi_split(float (&c)[4][4][4], __half* Ch, __half* Cl,
                                          int ldC, int m0, int n0)
{
    const int tid = threadIdx.x;
    const int wid = tid >> 5, lane = tid & 31;
    const int wm = (wid & 1) * 64, wn = (wid >> 1) * 32;
    const int g = lane >> 2, tg = lane & 3;
    #pragma unroll
    for (int mt = 0; mt < 4; mt++) {
        const int row = m0 + wm + mt * 16 + g;
        #pragma unroll
        for (int nt = 0; nt < 4; nt++) {
            const int col = n0 + wn + nt * 8 + tg * 2;
            __half h0, h1, l0, l1;
            split2h(c[mt][nt][0], h0, l0); split2h(c[mt][nt][1], h1, l1);
            *(__half2*)(Ch + (size_t)row * ldC + col) = __halves2half2(h0, h1);
            *(__half2*)(Cl + (size_t)row * ldC + col) = __halves2half2(l0, l1);
            split2h(c[mt][nt][2], h0, l0); split2h(c[mt][nt][3], h1, l1);
            *(__half2*)(Ch + (size_t)(row + 8) * ldC + col) = __halves2half2(h0, h1);
            *(__half2*)(Cl + (size_t)(row + 8) * ldC + col) = __halves2half2(l0, l1);
        }
    }
}

__device__ __forceinline__ void epi_vtrans(float (&c)[4][4][4], __half* Ch,
                                           int m0, int n0, char* sm)
{
    const int tid = threadIdx.x;
    const int wid = tid >> 5, lane = tid & 31;
    const int wm = (wid & 1) * 64, wn = (wid >> 1) * 32;
    const int g = lane >> 2, tg = lane & 3;
    float* smf = (float*)sm;                 // 128 x 132 fp32
    #pragma unroll
    for (int mt = 0; mt < 4; mt++) {
        const int rr = wm + mt * 16 + g;
        #pragma unroll
        for (int nt = 0; nt < 4; nt++) {
            const int cc = wn + nt * 8 + tg * 2;
            smf[(size_t)cc * 132 + rr]           = c[mt][nt][0];
            smf[(size_t)(cc + 1) * 132 + rr]     = c[mt][nt][1];
            smf[(size_t)cc * 132 + rr + 8]       = c[mt][nt][2];
            smf[(size_t)(cc + 1) * 132 + rr + 8] = c[mt][nt][3];
        }
    }
    __syncthreads();
    const int b = m0 >> 11, t0 = m0 & (NT - 1);
    __half* Hb = Ch + (size_t)b * ND * NT;
    const int dsub = tid >> 6;
    const int tcol = tid & 63;
    #pragma unroll
    for (int it = 0; it < 32; it++) {
        const int d = it * 4 + dsub;
        float2 v = *(float2*)(smf + (size_t)d * 132 + tcol * 2);
        *(__half2*)(Hb + (size_t)(n0 + d) * NT + t0 + tcol * 2) =
            __halves2half2(__float2half_rn(v.x), __float2half_rn(v.y));
    }
}

// ---------------------------------------------------------------------------
// MT = Wk * Wq^T  (TN, both row-major [e][d]), split epilogue
// ---------------------------------------------------------------------------
__global__ __launch_bounds__(256, 1) void gemm_mt(
    const __half* __restrict__ wkh, const __half* __restrict__ wkl,
    const __half* __restrict__ wqh, const __half* __restrict__ wql,
    __half* __restrict__ MTh, __half* __restrict__ MTl)
{
    extern __shared__ __align__(128) char sm[];
    const int m0 = blockIdx.y * 128, n0 = blockIdx.x * 128;
    float c[4][4][4];
    gemm_core<3>(wkh, wkl, wqh, wql, NE, NE / 64, m0, n0, sm, c);
    epi_split(c, MTh, MTl, NE, m0, n0);
}

// ---------------------------------------------------------------------------
// Y = x * M  (TN: B = MT[f][e]), TERMS=3, split epilogue, skip padded rows
// ---------------------------------------------------------------------------
__global__ __launch_bounds__(256, 1) void gemm_y(
    const __half* __restrict__ xh, const __half* __restrict__ xl,
    const __half* __restrict__ MTh, const __half* __restrict__ MTl,
    __half* __restrict__ Yh, __half* __restrict__ Yl,
    const int* __restrict__ lens)
{
    extern __shared__ __align__(128) char sm[];
    const int m0 = blockIdx.y * 128, n0 = blockIdx.x * 128;
    if ((m0 & (NT - 1)) >= lens[m0 >> 11]) return;
    float c[4][4][4];
    gemm_core<3>(xh, xl, MTh, MTl, NE, NE / 64, m0, n0, sm, c);
    epi_split(c, Yh, Yl, ND, m0, n0);
}

// ---------------------------------------------------------------------------
// V projection, TERMS=2, transposed hi-only output
// ---------------------------------------------------------------------------
__global__ __launch_bounds__(256, 1) void gemm_vproj(
    const __half* __restrict__ xh, const __half* __restrict__ xl,
    const __half* __restrict__ wvh,
    __half* __restrict__ Vth, const int* __restrict__ lens)
{
    extern __shared__ __align__(128) char sm[];
    const int m0 = blockIdx.y * 128, n0 = blockIdx.x * 128;
    if ((m0 & (NT - 1)) >= lens[m0 >> 11]) return;

    float c[4][4][4];
    gemm_core<2>(xh, xl, wvh, wvh, NE, NE / 64, m0, n0, sm, c);
    epi_vtrans(c, Vth, m0, n0, sm);
}

// ---------------------------------------------------------------------------
// energy = Y x^T per batch, TERMS=3 (skip masked row/col blocks)
// ---------------------------------------------------------------------------
__global__ __launch_bounds__(256, 1) void gemm_qk(
    const __half* __restrict__ Yh, const __half* __restrict__ Yl,
    const __half* __restrict__ xh, const __half* __restrict__ xl,
    float* __restrict__ S, const int* __restrict__ lens)
{
    extern __shared__ __align__(128) char sm[];
    const int z = blockIdx.z;
    const int len = lens[z];
    const int m0 = blockIdx.y * 128, n0 = blockIdx.x * 128;
    if (m0 >= len || n0 >= len) return;

    const size_t offY = (size_t)z * NT * ND;
    const size_t offX = (size_t)z * NT * NE;
    float c[4][4][4];
    gemm_core<3>(Yh + offY, Yl + offY, xh + offX, xl + offX, NE, NE / 64, m0, n0, sm, c);
    epi_f32(c, S + (size_t)z * NT * NT, NT, m0, n0);
}

// ---------------------------------------------------------------------------
// out = P V per batch, TERMS=1; rows >= len handled by fill_pad_k
// ---------------------------------------------------------------------------
__global__ __launch_bounds__(256, 1) void gemm_pv(
    const __half* __restrict__ Ph,
    const __half* __restrict__ Vth,
    float* __restrict__ out, const int* __restrict__ lens)
{
    extern __shared__ __align__(128) char sm[];
    const int z = blockIdx.z;
    const int len = lens[z];
    const int m0 = blockIdx.y * 128, n0 = blockIdx.x * 128;
    if (m0 >= len) return;

    const int nkt = (len + 63) >> 6;
    const __half* P = Ph + (size_t)z * NT * NT;
    const __half* V = Vth + (size_t)z * ND * NT;
    float c[4][4][4];
    gemm_core<1>(P, P, V, V, NT, nkt, m0, n0, sm, c);
    epi_f32(c, out + (size_t)z * NT * ND, ND, m0, n0);
}

// ---------------------------------------------------------------------------
// masked row softmax -> fp16 P
// ---------------------------------------------------------------------------
__global__ __launch_bounds__(256) void softmax_h_k(const float* __restrict__ S,
                                                   __half* __restrict__ Ph,
                                                   const int* __restrict__ lens)
{
    __shared__ float cache[NT];
    __shared__ float red[256];
    const int row = blockIdx.x;
    const int b = row >> 11;
    const int t = row & (NT - 1);
    const int len = lens[b];
    const int rowmax = (len + 127) & ~127;
    if (t >= rowmax) return;
    const int colmax = (len + 63) & ~63;

    __half* ph = Ph + (size_t)row * NT;
    const int tid = threadIdx.x;
    const __half z0 = __float2half_rn(0.f);

    if (t >= len) {
        const __half h = __float2half_rn(1.f / (float)len);
        for (int s = tid; s < len; s += 256) ph[s] = h;
        for (int s = len + tid; s < colmax; s += 256) ph[s] = z0;
        return;
    }

    const float* p = S + (size_t)row * NT;

    float m = -1e30f;
    for (int s = tid; s < len; s += 256) {
        float v = p[s];
        cache[s] = v;
        m = fmaxf(m, v);
    }
    red[tid] = m; __syncthreads();
    #pragma unroll
    for (int off = 128; off > 0; off >>= 1) {
        if (tid < off) red[tid] = fmaxf(red[tid], red[tid + off]);
        __syncthreads();
    }
    m = red[0]; __syncthreads();

    float sum = 0.f;
    for (int s = tid; s < len; s += 256) {
        float e = __expf((cache[s] - m) * 0.125f);
        cache[s] = e;
        sum += e;
    }
    red[tid] = sum; __syncthreads();
    #pragma unroll
    for (int off = 128; off > 0; off >>= 1) {
        if (tid < off) red[tid] += red[tid + off];
        __syncthreads();
    }
    const float inv = 1.f / red[0];

    for (int s = tid; s < len; s += 256)
        ph[s] = __float2half_rn(cache[s] * inv);
    for (int s = len + tid; s < colmax; s += 256) ph[s] = z0;
}

// ---------------------------------------------------------------------------
__global__ __launch_bounds__(256) void vsum_k(const __half* __restrict__ Vth,
                                              float* __restrict__ bc,
                                              const int* __restrict__ lens)
{
    const int b = blockIdx.y;
    const int len = lens[b];
    const int d = blockIdx.x * 8 + (threadIdx.x >> 5);
    const int lane = threadIdx.x & 31;
    const __half* ph = Vth + ((size_t)b * ND + d) * NT;
    float s = 0.f;
    for (int t = lane; t < len; t += 32)
        s += __half2float(ph[t]);
    #pragma unroll
    for (int o = 16; o > 0; o >>= 1) s += __shfl_xor_sync(0xffffffffu, s, o);
    if (lane == 0) bc[(size_t)b * ND + d] = s / (float)len;
}

__global__ __launch_bounds__(256) void fill_pad_k(float* __restrict__ out,
                                                  const float* __restrict__ bc,
                                                  const int* __restrict__ lens)
{
    const int b = blockIdx.y;
    const int t = blockIdx.x;
    if (t < lens[b]) return;
    const float4* src = (const float4*)(bc + (size_t)b * ND);
    float4* dst = (float4*)(out + ((size_t)b * NT + t) * ND);
    for (int i = threadIdx.x; i < ND / 4; i += 256) dst[i] = src[i];
}

// ---------------------------------------------------------------------------
extern "C" void kernel_launch(void* const* d_in, const int* in_sizes, int n_in,
                              void* d_out, int out_size)
{
    const float* x  = (const float*)d_in[0];
    const float* Wq = (const float*)d_in[1];
    const float* Wk = (const float*)d_in[2];
    const float* Wv = (const float*)d_in[3];
    float* out = (float*)d_out;

    unsigned char* pool;
    int* lens;
    cudaGetSymbolAddress((void**)&pool, g_pool);
    cudaGetSymbolAddress((void**)&lens, g_len);

    __half* xh  = (__half*)(pool + OFF_XH);
    __half* xl  = (__half*)(pool + OFF_XL);
    __half* wqh = (__half*)(pool + OFF_WQH);
    __half* wql = (__half*)(pool + OFF_WQL);
    __half* wkh = (__half*)(pool + OFF_WKH);
    __half* wkl = (__half*)(pool + OFF_WKL);
    __half* wvh = (__half*)(pool + OFF_WVH);
    __half* MTh = (__half*)(pool + OFF_MTH);
    __half* MTl = (__half*)(pool + OFF_MTL);
    __half* Yh  = (__half*)(pool + OFF_YH);
    __half* Yl  = (__half*)(pool + OFF_YL);
    __half* Vth = (__half*)(pool + OFF_VTH);
    float* S  = (float*)(pool + OFF_S);
    __half* Ph  = (__half*)(pool + OFF_PH);
    float* bc = (float*)(pool + OFF_BC);

    cudaFuncSetAttribute(gemm_mt,    cudaFuncAttributeMaxDynamicSharedMemorySize, SMEM_TOTAL);
    cudaFuncSetAttribute(gemm_y,     cudaFuncAttributeMaxDynamicSharedMemorySize, SMEM_TOTAL);
    cudaFuncSetAttribute(gemm_vproj, cudaFuncAttributeMaxDynamicSharedMemorySize, SMEM_TOTAL);
    cudaFuncSetAttribute(gemm_qk,    cudaFuncAttributeMaxDynamicSharedMemorySize, SMEM_TOTAL);
    cudaFuncSetAttribute(gemm_pv,    cudaFuncAttributeMaxDynamicSharedMemorySize, SMEM_TOTAL);

    // 1) lengths + splits (Wq/Wk flat split — no transpose needed for MT path)
    len_k<<<NB, 256>>>(x);
    split_k<<<(int)(SZ_X / 4 / 256), 256>>>(x, xh, xl, SZ_X / 4);
    split_k<<<(int)(SZ_W / 4 / 256), 256>>>(Wq, wqh, wql, SZ_W / 4);
    split_k<<<(int)(SZ_W / 4 / 256), 256>>>(Wk, wkh, wkl, SZ_W / 4);
    dim3 tg(32, 32), tb(32, 8);
    trsplit_k<<<tg, tb>>>(Wv, wvh);

    // 2) MT = Wk Wq^T  (tiny: 64 blocks)
    dim3 blk(256);
    gemm_mt<<<dim3(NE / 128, NE / 128), blk, SMEM_TOTAL>>>(wkh, wkl, wqh, wql, MTh, MTl);

    // 3) Y = x M (replaces both Q and K projections); V projection
    dim3 gy(ND / 128, (NB * NT) / 128);
    gemm_y<<<gy, blk, SMEM_TOTAL>>>(xh, xl, MTh, MTl, Yh, Yl, lens);
    gemm_vproj<<<gy, blk, SMEM_TOTAL>>>(xh, xl, wvh, Vth, lens);

    // 3b) per-batch V column means for padded output rows
    vsum_k<<<dim3(ND / 8, NB), 256>>>(Vth, bc, lens);

    // 4) energy = Y x^T per batch
    dim3 ge(NT / 128, NT / 128, NB);
    gemm_qk<<<ge, blk, SMEM_TOTAL>>>(Yh, Yl, xh, xl, S, lens);

    // 5) masked softmax -> fp16 P
    softmax_h_k<<<NB * NT, 256>>>(S, Ph, lens);

    // 6) out = P V per batch (valid rows only)
    dim3 go(ND / 128, NT / 128, NB);
    gemm_pv<<<go, blk, SMEM_TOTAL>>>(Ph, Vth, out, lens);

    // 7) padded output rows = uniform average of valid V rows
    fill_pad_k<<<dim3(NT, NB), 256>>>(out, bc, lens);
}

// round 12
// speedup vs baseline: 3.8088x; 1.2564x over previous
#include <cuda_runtime.h>
#include <cuda_fp16.h>
#include <cstdint>

#define NB 8
#define NT 2048
#define NE 1024
#define ND 1024

constexpr size_t SZ_X = (size_t)NB * NT * NE;
constexpr size_t SZ_W = (size_t)NE * ND;
constexpr size_t SZ_S = (size_t)NB * NT * NT;

// ---- static scratch pool ----
constexpr size_t OFF_XH  = 0;
constexpr size_t OFF_XL  = OFF_XH  + SZ_X * 2;
constexpr size_t OFF_WQH = OFF_XL  + SZ_X * 2;
constexpr size_t OFF_WQL = OFF_WQH + SZ_W * 2;
constexpr size_t OFF_WKH = OFF_WQL + SZ_W * 2;
constexpr size_t OFF_WKL = OFF_WKH + SZ_W * 2;
constexpr size_t OFF_WVH = OFF_WKL + SZ_W * 2;
constexpr size_t OFF_MTH = OFF_WVH + SZ_W * 2;
constexpr size_t OFF_MTL = OFF_MTH + SZ_W * 2;
constexpr size_t OFF_YH  = OFF_MTL + SZ_W * 2;
constexpr size_t OFF_YL  = OFF_YH  + SZ_X * 2;
constexpr size_t OFF_VTH = OFF_YL  + SZ_X * 2;
constexpr size_t OFF_S   = OFF_VTH + SZ_X * 2;
constexpr size_t OFF_PH  = OFF_S   + SZ_S * 4;
constexpr size_t OFF_BC  = OFF_PH  + SZ_S * 2;
constexpr size_t POOL_SZ = OFF_BC  + (size_t)NB * ND * 4;

__device__ __align__(256) unsigned char g_pool[POOL_SZ];
__device__ int g_len[NB];

// ---------------------------------------------------------------------------
// fp16 hi + (scaled by 2048) lo split.
__device__ __forceinline__ void split2h(float v, __half& h, __half& l) {
    h = __float2half_rn(v);
    l = __float2half_rn((v - __half2float(h)) * 2048.f);
}

__device__ __forceinline__ void cp_async16(uint32_t dst, const void* src) {
    asm volatile("cp.async.cg.shared.global [%0], [%1], 16;\n"
                 :: "r"(dst), "l"(src) : "memory");
}

__device__ __forceinline__ uint32_t swz(uint32_t off) {
    return off ^ ((off >> 3) & 0x70);
}

__device__ __forceinline__ void ldm4(uint32_t* r, uint32_t a) {
    asm volatile("ldmatrix.sync.aligned.m8n8.x4.shared.b16 {%0,%1,%2,%3}, [%4];"
                 : "=r"(r[0]), "=r"(r[1]), "=r"(r[2]), "=r"(r[3]) : "r"(a));
}

__device__ __forceinline__ void mma_f16(float* c, const uint32_t* a, const uint32_t* b) {
    asm volatile(
        "mma.sync.aligned.m16n8k16.row.col.f32.f16.f16.f32 "
        "{%0,%1,%2,%3}, {%4,%5,%6,%7}, {%8,%9}, {%0,%1,%2,%3};\n"
        : "+f"(c[0]), "+f"(c[1]), "+f"(c[2]), "+f"(c[3])
        : "r"(a[0]), "r"(a[1]), "r"(a[2]), "r"(a[3]), "r"(b[0]), "r"(b[1]));
}

// ---------------------------------------------------------------------------
// parallel per-batch length: grid (NB, 8), one row per thread,
// __syncthreads_count + atomicAdd into zeroed g_len.
// ---------------------------------------------------------------------------
__global__ __launch_bounds__(256) void len_k(const float* __restrict__ x,
                                             int* __restrict__ lens)
{
    const int b = blockIdx.x;
    const int t = blockIdx.y * 256 + threadIdx.x;
    const float4* row = (const float4*)(x + ((size_t)b * NT + t) * NE);
    bool nz = false;
    #pragma unroll 4
    for (int e = 0; e < NE / 4; e++) {
        float4 v = row[e];
        if (v.x != 0.f || v.y != 0.f || v.z != 0.f || v.w != 0.f) { nz = true; break; }
    }
    int cnt = __syncthreads_count(nz);
    if (threadIdx.x == 0) atomicAdd(&lens[b], cnt);
}

// ---------------------------------------------------------------------------
__global__ __launch_bounds__(256) void split_k(const float* __restrict__ in,
                                               __half* __restrict__ h, __half* __restrict__ l,
                                               size_t n4)
{
    size_t i = (size_t)blockIdx.x * 256 + threadIdx.x;
    if (i >= n4) return;
    float4 v = ((const float4*)in)[i];
    __half h0, h1, h2, h3, l0, l1, l2, l3;
    split2h(v.x, h0, l0); split2h(v.y, h1, l1);
    split2h(v.z, h2, l2); split2h(v.w, h3, l3);
    __half2* hp = (__half2*)(h + i * 4);
    __half2* lp = (__half2*)(l + i * 4);
    hp[0] = __halves2half2(h0, h1); hp[1] = __halves2half2(h2, h3);
    lp[0] = __halves2half2(l0, l1); lp[1] = __halves2half2(l2, l3);
}

// W [E][N] fp32 -> transposed hi-only Wt[n][e]
__global__ __launch_bounds__(256) void trsplit_k(const float* __restrict__ W,
                                                 __half* __restrict__ Th)
{
    __shared__ float tile[32][33];
    const int bn = blockIdx.x * 32;
    const int be = blockIdx.y * 32;
    const int tx = threadIdx.x, ty = threadIdx.y;
    #pragma unroll
    for (int r = 0; r < 4; r++)
        tile[ty + r * 8][tx] = W[(size_t)(be + ty + r * 8) * ND + bn + tx];
    __syncthreads();
    #pragma unroll
    for (int r = 0; r < 4; r++) {
        float v = tile[tx][ty + r * 8];
        Th[(size_t)(bn + ty + r * 8) * NE + be + tx] = __float2half_rn(v);
    }
}

// ---------------------------------------------------------------------------
// HMMA TN GEMM core, fp16 limbs, TERMS = 3 / 2 / 1.
// ---------------------------------------------------------------------------
constexpr int SUB = 128 * 128;
constexpr int STAGE = 4 * SUB;
constexpr int NSTAGE = 3;
constexpr int SMEM_TOTAL = NSTAGE * STAGE;   // 196608

template<int TERMS>
__device__ __forceinline__ void gemm_core(
    const __half* __restrict__ Ah, const __half* __restrict__ Al,
    const __half* __restrict__ Bh, const __half* __restrict__ Bl,
    int Kdim, int nkt, int m0, int n0, char* sm, float (&c)[4][4][4])
{
    const int tid = threadIdx.x;
    const int wid = tid >> 5, lane = tid & 31;
    const int wm = (wid & 1) * 64;
    const int wn = (wid >> 1) * 32;

    const int a_row = (lane & 7) + ((lane >> 3) & 1) * 8;
    const int a_chk = lane >> 4;
    const int b_row = (lane & 7) + (lane >> 4) * 8;
    const int b_chk = (lane >> 3) & 1;

    const uint32_t smb = (uint32_t)__cvta_generic_to_shared(sm);

    float c2[4][4][4];
    #pragma unroll
    for (int i = 0; i < 4; i++)
        #pragma unroll
        for (int j = 0; j < 4; j++)
            #pragma unroll
            for (int t = 0; t < 4; t++) { c[i][j][t] = 0.f; if (TERMS >= 2) c2[i][j][t] = 0.f; }

    const int r = tid >> 1;
    const int c0 = (tid & 1) * 4;
    const size_t arow = (size_t)(m0 + r) * Kdim;
    const size_t brow = (size_t)(n0 + r) * Kdim;

    auto load_stage = [&](int buf, int k0) {
        const uint32_t sbase = smb + buf * STAGE;
        #pragma unroll
        for (int j = 0; j < 4; j++) {
            const int cc = c0 + j;
            const uint32_t so = swz(r * 128 + cc * 16);
            const size_t ko = (size_t)k0 + cc * 8;
            cp_async16(sbase + so,           Ah + arow + ko);
            if (TERMS >= 2) cp_async16(sbase + SUB + so, Al + arow + ko);
            cp_async16(sbase + 2 * SUB + so, Bh + brow + ko);
            if (TERMS == 3) cp_async16(sbase + 3 * SUB + so, Bl + brow + ko);
        }
        asm volatile("cp.async.commit_group;" ::: "memory");
    };

    load_stage(0, 0);
    load_stage(1, 64);

    int buf = 0;
    for (int i = 0; i < nkt; i++) {
        if (i + 1 < nkt) {
            asm volatile("cp.async.wait_group 1;" ::: "memory");
        } else {
            asm volatile("cp.async.wait_group 0;" ::: "memory");
        }
        __syncthreads();

        if (i + 2 < nkt) {
            int nb = buf + 2; if (nb >= NSTAGE) nb -= NSTAGE;
            load_stage(nb, (i + 2) * 64);
        }

        const uint32_t ahb = smb + buf * STAGE;
        const uint32_t alb = ahb + SUB;
        const uint32_t bhb = ahb + 2 * SUB;
        const uint32_t blb = ahb + 3 * SUB;

        #pragma unroll
        for (int kc = 0; kc < 8; kc += 2) {
            uint32_t bh[8], a[4][4];
            const uint32_t boff0 = swz((wn + b_row) * 128 + (kc + b_chk) * 16);
            const uint32_t boff1 = swz((wn + 16 + b_row) * 128 + (kc + b_chk) * 16);
            ldm4(bh + 0, bhb + boff0); ldm4(bh + 4, bhb + boff1);

            #pragma unroll
            for (int mt = 0; mt < 4; mt++) {
                const uint32_t off = swz((wm + mt * 16 + a_row) * 128 + (kc + a_chk) * 16);
                ldm4(a[mt], ahb + off);
            }
            #pragma unroll
            for (int mt = 0; mt < 4; mt++)
                #pragma unroll
                for (int nt = 0; nt < 4; nt++)
                    mma_f16(c[mt][nt], a[mt], &bh[nt * 2]);

            if (TERMS == 3) {
                uint32_t bl[8];
                ldm4(bl + 0, blb + boff0); ldm4(bl + 4, blb + boff1);
                #pragma unroll
                for (int mt = 0; mt < 4; mt++)
                    #pragma unroll
                    for (int nt = 0; nt < 4; nt++)
                        mma_f16(c2[mt][nt], a[mt], &bl[nt * 2]);
            }
            if (TERMS >= 2) {
                #pragma unroll
                for (int mt = 0; mt < 4; mt++) {
                    const uint32_t off = swz((wm + mt * 16 + a_row) * 128 + (kc + a_chk) * 16);
                    ldm4(a[mt], alb + off);
                }
                #pragma unroll
                for (int mt = 0; mt < 4; mt++)
                    #pragma unroll
                    for (int nt = 0; nt < 4; nt++)
                        mma_f16(c2[mt][nt], a[mt], &bh[nt * 2]);
            }
        }

        if (++buf >= NSTAGE) buf = 0;
    }

    if (TERMS >= 2) {
        constexpr float DS = 1.f / 2048.f;
        #pragma unroll
        for (int i = 0; i < 4; i++)
            #pragma unroll
            for (int j = 0; j < 4; j++)
                #pragma unroll
                for (int t = 0; t < 4; t++) c[i][j][t] += c2[i][j][t] * DS;
    }
    __syncthreads();
}

// ---- epilogues ----
__device__ __forceinline__ void epi_f32(float (&c)[4][4][4], float* Cz, int ldC,
                                        int m0, int n0)
{
    const int tid = threadIdx.x;
    const int wid = tid >> 5, lane = tid & 31;
    const int wm = (wid & 1) * 64, wn = (wid >> 1) * 32;
    const int g = lane >> 2, tg = lane & 3;
    #pragma unroll
    for (int mt = 0; mt < 4; mt++) {
        const int row = m0 + wm + mt * 16 + g;
        #pragma unroll
        for (int nt = 0; nt < 4; nt++) {
            const int col = n0 + wn + nt * 8 + tg * 2;
            *(float2*)(Cz + (size_t)row * ldC + col)       = make_float2(c[mt][nt][0], c[mt][nt][1]);
            *(float2*)(Cz + (size_t)(row + 8) * ldC + col) = make_float2(c[mt][nt][2], c[mt][nt][3]);
        }
    }
}

__device__ __forceinline__ void epi_split(float (&c)[4][4][4], __half* Ch, __half* Cl,
                                          int ldC, int m0, int n0)
{
    const int tid = threadIdx.x;
    const int wid = tid >> 5, lane = tid & 31;
    const int wm = (wid & 1) * 64, wn = (wid >> 1) * 32;
    const int g = lane >> 2, tg = lane & 3;
    #pragma unroll
    for (int mt = 0; mt < 4; mt++) {
        const int row = m0 + wm + mt * 16 + g;
        #pragma unroll
        for (int nt = 0; nt < 4; nt++) {
            const int col = n0 + wn + nt * 8 + tg * 2;
            __half h0, h1, l0, l1;
            split2h(c[mt][nt][0], h0, l0); split2h(c[mt][nt][1], h1, l1);
            *(__half2*)(Ch + (size_t)row * ldC + col) = __halves2half2(h0, h1);
            *(__half2*)(Cl + (size_t)row * ldC + col) = __halves2half2(l0, l1);
            split2h(c[mt][nt][2], h0, l0); split2h(c[mt][nt][3], h1, l1);
            *(__half2*)(Ch + (size_t)(row + 8) * ldC + col) = __halves2half2(h0, h1);
            *(__half2*)(Cl + (size_t)(row + 8) * ldC + col) = __halves2half2(l0, l1);
        }
    }
}

__device__ __forceinline__ void epi_vtrans(float (&c)[4][4][4], __half* Ch,
                                           int m0, int n0, char* sm)
{
    const int tid = threadIdx.x;
    const int wid = tid >> 5, lane = tid & 31;
    const int wm = (wid & 1) * 64, wn = (wid >> 1) * 32;
    const int g = lane >> 2, tg = lane & 3;
    float* smf = (float*)sm;                 // 128 x 132 fp32
    #pragma unroll
    for (int mt = 0; mt < 4; mt++) {
        const int rr = wm + mt * 16 + g;
        #pragma unroll
        for (int nt = 0; nt < 4; nt++) {
            const int cc = wn + nt * 8 + tg * 2;
            smf[(size_t)cc * 132 + rr]           = c[mt][nt][0];
            smf[(size_t)(cc + 1) * 132 + rr]     = c[mt][nt][1];
            smf[(size_t)cc * 132 + rr + 8]       = c[mt][nt][2];
            smf[(size_t)(cc + 1) * 132 + rr + 8] = c[mt][nt][3];
        }
    }
    __syncthreads();
    const int b = m0 >> 11, t0 = m0 & (NT - 1);
    __half* Hb = Ch + (size_t)b * ND * NT;
    const int dsub = tid >> 6;
    const int tcol = tid & 63;
    #pragma unroll
    for (int it = 0; it < 32; it++) {
        const int d = it * 4 + dsub;
        float2 v = *(float2*)(smf + (size_t)d * 132 + tcol * 2);
        *(__half2*)(Hb + (size_t)(n0 + d) * NT + t0 + tcol * 2) =
            __halves2half2(__float2half_rn(v.x), __float2half_rn(v.y));
    }
}

// ---------------------------------------------------------------------------
// MT = Wk * Wq^T  (TN, both row-major [e][d]), split epilogue
// ---------------------------------------------------------------------------
__global__ __launch_bounds__(256, 1) void gemm_mt(
    const __half* __restrict__ wkh, const __half* __restrict__ wkl,
    const __half* __restrict__ wqh, const __half* __restrict__ wql,
    __half* __restrict__ MTh, __half* __restrict__ MTl)
{
    extern __shared__ __align__(128) char sm[];
    const int m0 = blockIdx.y * 128, n0 = blockIdx.x * 128;
    float c[4][4][4];
    gemm_core<3>(wkh, wkl, wqh, wql, NE, NE / 64, m0, n0, sm, c);
    epi_split(c, MTh, MTl, NE, m0, n0);
}

// ---------------------------------------------------------------------------
// Merged projections: z = 0 -> Y = x*M (TERMS=3, split epi);
//                     z = 1 -> Vt = (x*Wv)^T (TERMS=1, hi-only transposed epi)
// Skip fully-padded row blocks.
// ---------------------------------------------------------------------------
__global__ __launch_bounds__(256, 1) void gemm_yv(
    const __half* __restrict__ xh, const __half* __restrict__ xl,
    const __half* __restrict__ MTh, const __half* __restrict__ MTl,
    const __half* __restrict__ wvh,
    __half* __restrict__ Yh, __half* __restrict__ Yl,
    __half* __restrict__ Vth,
    const int* __restrict__ lens)
{
    extern __shared__ __align__(128) char sm[];
    const int m0 = blockIdx.y * 128, n0 = blockIdx.x * 128;
    if ((m0 & (NT - 1)) >= lens[m0 >> 11]) return;

    float c[4][4][4];
    if (blockIdx.z == 0) {
        gemm_core<3>(xh, xl, MTh, MTl, NE, NE / 64, m0, n0, sm, c);
        epi_split(c, Yh, Yl, ND, m0, n0);
    } else {
        gemm_core<1>(xh, xh, wvh, wvh, NE, NE / 64, m0, n0, sm, c);
        epi_vtrans(c, Vth, m0, n0, sm);
    }
}

// ---------------------------------------------------------------------------
// energy = Y x^T per batch, TERMS=3 (skip masked row/col blocks)
// ---------------------------------------------------------------------------
__global__ __launch_bounds__(256, 1) void gemm_qk(
    const __half* __restrict__ Yh, const __half* __restrict__ Yl,
    const __half* __restrict__ xh, const __half* __restrict__ xl,
    float* __restrict__ S, const int* __restrict__ lens)
{
    extern __shared__ __align__(128) char sm[];
    const int z = blockIdx.z;
    const int len = lens[z];
    const int m0 = blockIdx.y * 128, n0 = blockIdx.x * 128;
    if (m0 >= len || n0 >= len) return;

    const size_t offY = (size_t)z * NT * ND;
    const size_t offX = (size_t)z * NT * NE;
    float c[4][4][4];
    gemm_core<3>(Yh + offY, Yl + offY, xh + offX, xl + offX, NE, NE / 64, m0, n0, sm, c);
    epi_f32(c, S + (size_t)z * NT * NT, NT, m0, n0);
}

// ---------------------------------------------------------------------------
// out = P V per batch, TERMS=1; rows >= len handled by fill_pad_k
// ---------------------------------------------------------------------------
__global__ __launch_bounds__(256, 1) void gemm_pv(
    const __half* __restrict__ Ph,
    const __half* __restrict__ Vth,
    float* __restrict__ out, const int* __restrict__ lens)
{
    extern __shared__ __align__(128) char sm[];
    const int z = blockIdx.z;
    const int len = lens[z];
    const int m0 = blockIdx.y * 128, n0 = blockIdx.x * 128;
    if (m0 >= len) return;

    const int nkt = (len + 63) >> 6;
    const __half* P = Ph + (size_t)z * NT * NT;
    const __half* V = Vth + (size_t)z * ND * NT;
    float c[4][4][4];
    gemm_core<1>(P, P, V, V, NT, nkt, m0, n0, sm, c);
    epi_f32(c, out + (size_t)z * NT * ND, ND, m0, n0);
}

// ---------------------------------------------------------------------------
// masked row softmax -> fp16 P
// ---------------------------------------------------------------------------
__global__ __launch_bounds__(256) void softmax_h_k(const float* __restrict__ S,
                                                   __half* __restrict__ Ph,
                                                   const int* __restrict__ lens)
{
    __shared__ float cache[NT];
    __shared__ float red[256];
    const int row = blockIdx.x;
    const int b = row >> 11;
    const int t = row & (NT - 1);
    const int len = lens[b];
    const int rowmax = (len + 127) & ~127;
    if (t >= rowmax) return;
    const int colmax = (len + 63) & ~63;

    __half* ph = Ph + (size_t)row * NT;
    const int tid = threadIdx.x;
    const __half z0 = __float2half_rn(0.f);

    if (t >= len) {
        const __half h = __float2half_rn(1.f / (float)len);
        for (int s = tid; s < len; s += 256) ph[s] = h;
        for (int s = len + tid; s < colmax; s += 256) ph[s] = z0;
        return;
    }

    const float* p = S + (size_t)row * NT;

    float m = -1e30f;
    for (int s = tid; s < len; s += 256) {
        float v = p[s];
        cache[s] = v;
        m = fmaxf(m, v);
    }
    red[tid] = m; __syncthreads();
    #pragma unroll
    for (int off = 128; off > 0; off >>= 1) {
        if (tid < off) red[tid] = fmaxf(red[tid], red[tid + off]);
        __syncthreads();
    }
    m = red[0]; __syncthreads();

    float sum = 0.f;
    for (int s = tid; s < len; s += 256) {
        float e = __expf((cache[s] - m) * 0.125f);
        cache[s] = e;
        sum += e;
    }
    red[tid] = sum; __syncthreads();
    #pragma unroll
    for (int off = 128; off > 0; off >>= 1) {
        if (tid < off) red[tid] += red[tid + off];
        __syncthreads();
    }
    const float inv = 1.f / red[0];

    for (int s = tid; s < len; s += 256)
        ph[s] = __float2half_rn(cache[s] * inv);
    for (int s = len + tid; s < colmax; s += 256) ph[s] = z0;
}

// ---------------------------------------------------------------------------
__global__ __launch_bounds__(256) void vsum_k(const __half* __restrict__ Vth,
                                              float* __restrict__ bc,
                                              const int* __restrict__ lens)
{
    const int b = blockIdx.y;
    const int len = lens[b];
    const int d = blockIdx.x * 8 + (threadIdx.x >> 5);
    const int lane = threadIdx.x & 31;
    const __half* ph = Vth + ((size_t)b * ND + d) * NT;
    float s = 0.f;
    for (int t = lane; t < len; t += 32)
        s += __half2float(ph[t]);
    #pragma unroll
    for (int o = 16; o > 0; o >>= 1) s += __shfl_xor_sync(0xffffffffu, s, o);
    if (lane == 0) bc[(size_t)b * ND + d] = s / (float)len;
}

__global__ __launch_bounds__(256) void fill_pad_k(float* __restrict__ out,
                                                  const float* __restrict__ bc,
                                                  const int* __restrict__ lens)
{
    const int b = blockIdx.y;
    const int t = blockIdx.x;
    if (t < lens[b]) return;
    const float4* src = (const float4*)(bc + (size_t)b * ND);
    float4* dst = (float4*)(out + ((size_t)b * NT + t) * ND);
    for (int i = threadIdx.x; i < ND / 4; i += 256) dst[i] = src[i];
}

// ---------------------------------------------------------------------------
extern "C" void kernel_launch(void* const* d_in, const int* in_sizes, int n_in,
                              void* d_out, int out_size)
{
    const float* x  = (const float*)d_in[0];
    const float* Wq = (const float*)d_in[1];
    const float* Wk = (const float*)d_in[2];
    const float* Wv = (const float*)d_in[3];
    float* out = (float*)d_out;

    unsigned char* pool;
    int* lens;
    cudaGetSymbolAddress((void**)&pool, g_pool);
    cudaGetSymbolAddress((void**)&lens, g_len);

    __half* xh  = (__half*)(pool + OFF_XH);
    __half* xl  = (__half*)(pool + OFF_XL);
    __half* wqh = (__half*)(pool + OFF_WQH);
    __half* wql = (__half*)(pool + OFF_WQL);
    __half* wkh = (__half*)(pool + OFF_WKH);
    __half* wkl = (__half*)(pool + OFF_WKL);
    __half* wvh = (__half*)(pool + OFF_WVH);
    __half* MTh = (__half*)(pool + OFF_MTH);
    __half* MTl = (__half*)(pool + OFF_MTL);
    __half* Yh  = (__half*)(pool + OFF_YH);
    __half* Yl  = (__half*)(pool + OFF_YL);
    __half* Vth = (__half*)(pool + OFF_VTH);
    float* S  = (float*)(pool + OFF_S);
    __half* Ph  = (__half*)(pool + OFF_PH);
    float* bc = (float*)(pool + OFF_BC);

    cudaFuncSetAttribute(gemm_mt, cudaFuncAttributeMaxDynamicSharedMemorySize, SMEM_TOTAL);
    cudaFuncSetAttribute(gemm_yv, cudaFuncAttributeMaxDynamicSharedMemorySize, SMEM_TOTAL);
    cudaFuncSetAttribute(gemm_qk, cudaFuncAttributeMaxDynamicSharedMemorySize, SMEM_TOTAL);
    cudaFuncSetAttribute(gemm_pv, cudaFuncAttributeMaxDynamicSharedMemorySize, SMEM_TOTAL);

    // 1) lengths (parallel) + splits
    cudaMemsetAsync(lens, 0, NB * sizeof(int));
    len_k<<<dim3(NB, NT / 256), 256>>>(x, lens);
    split_k<<<(int)(SZ_X / 4 / 256), 256>>>(x, xh, xl, SZ_X / 4);
    split_k<<<(int)(SZ_W / 4 / 256), 256>>>(Wq, wqh, wql, SZ_W / 4);
    split_k<<<(int)(SZ_W / 4 / 256), 256>>>(Wk, wkh, wkl, SZ_W / 4);
    dim3 tg(32, 32), tb(32, 8);
    trsplit_k<<<tg, tb>>>(Wv, wvh);

    // 2) MT = Wk Wq^T
    dim3 blk(256);
    gemm_mt<<<dim3(NE / 128, NE / 128), blk, SMEM_TOTAL>>>(wkh, wkl, wqh, wql, MTh, MTl);

    // 3) merged Y = x M (z=0) and Vt = (x Wv)^T (z=1)
    dim3 gyv(ND / 128, (NB * NT) / 128, 2);
    gemm_yv<<<gyv, blk, SMEM_TOTAL>>>(xh, xl, MTh, MTl, wvh, Yh, Yl, Vth, lens);

    // 3b) per-batch V column means for padded output rows
    vsum_k<<<dim3(ND / 8, NB), 256>>>(Vth, bc, lens);

    // 4) energy = Y x^T per batch
    dim3 ge(NT / 128, NT / 128, NB);
    gemm_qk<<<ge, blk, SMEM_TOTAL>>>(Yh, Yl, xh, xl, S, lens);

    // 5) masked softmax -> fp16 P
    softmax_h_k<<<NB * NT, 256>>>(S, Ph, lens);

    // 6) out = P V per batch (valid rows only)
    dim3 go(ND / 128, NT / 128, NB);
    gemm_pv<<<go, blk, SMEM_TOTAL>>>(Ph, Vth, out, lens);

    // 7) padded output rows = uniform average of valid V rows
    fill_pad_k<<<dim3(NT, NB), 256>>>(out, bc, lens);
}

// round 13
// speedup vs baseline: 4.0688x; 1.0683x over previous
#include <cuda_runtime.h>
#include <cuda_fp16.h>
#include <cstdint>

#define NB 8
#define NT 2048
#define NE 1024
#define ND 1024

constexpr size_t SZ_X = (size_t)NB * NT * NE;
constexpr size_t SZ_W = (size_t)NE * ND;
constexpr size_t SZ_S = (size_t)NB * NT * NT;

// ---- static scratch pool ----
constexpr size_t OFF_XH  = 0;
constexpr size_t OFF_XL  = OFF_XH  + SZ_X * 2;
constexpr size_t OFF_WQH = OFF_XL  + SZ_X * 2;
constexpr size_t OFF_WQL = OFF_WQH + SZ_W * 2;
constexpr size_t OFF_WKH = OFF_WQL + SZ_W * 2;
constexpr size_t OFF_WKL = OFF_WKH + SZ_W * 2;
constexpr size_t OFF_WVH = OFF_WKL + SZ_W * 2;
constexpr size_t OFF_MTH = OFF_WVH + SZ_W * 2;
constexpr size_t OFF_MTL = OFF_MTH + SZ_W * 2;
constexpr size_t OFF_YH  = OFF_MTL + SZ_W * 2;
constexpr size_t OFF_YL  = OFF_YH  + SZ_X * 2;
constexpr size_t OFF_VTH = OFF_YL  + SZ_X * 2;
constexpr size_t OFF_S   = OFF_VTH + SZ_X * 2;
constexpr size_t OFF_PH  = OFF_S   + SZ_S * 4;
constexpr size_t OFF_BC  = OFF_PH  + SZ_S * 2;
constexpr size_t POOL_SZ = OFF_BC  + (size_t)NB * ND * 4;

__device__ __align__(256) unsigned char g_pool[POOL_SZ];
__device__ int g_len[NB];

// ---------------------------------------------------------------------------
__device__ __forceinline__ void split2h(float v, __half& h, __half& l) {
    h = __float2half_rn(v);
    l = __float2half_rn((v - __half2float(h)) * 2048.f);
}

__device__ __forceinline__ void cp_async16(uint32_t dst, const void* src) {
    asm volatile("cp.async.cg.shared.global [%0], [%1], 16;\n"
                 :: "r"(dst), "l"(src) : "memory");
}

__device__ __forceinline__ uint32_t swz(uint32_t off) {
    return off ^ ((off >> 3) & 0x70);
}

__device__ __forceinline__ void ldm4(uint32_t* r, uint32_t a) {
    asm volatile("ldmatrix.sync.aligned.m8n8.x4.shared.b16 {%0,%1,%2,%3}, [%4];"
                 : "=r"(r[0]), "=r"(r[1]), "=r"(r[2]), "=r"(r[3]) : "r"(a));
}

__device__ __forceinline__ void mma_f16(float* c, const uint32_t* a, const uint32_t* b) {
    asm volatile(
        "mma.sync.aligned.m16n8k16.row.col.f32.f16.f16.f32 "
        "{%0,%1,%2,%3}, {%4,%5,%6,%7}, {%8,%9}, {%0,%1,%2,%3};\n"
        : "+f"(c[0]), "+f"(c[1]), "+f"(c[2]), "+f"(c[3])
        : "r"(a[0]), "r"(a[1]), "r"(a[2]), "r"(a[3]), "r"(b[0]), "r"(b[1]));
}

// ---------------------------------------------------------------------------
__global__ __launch_bounds__(256) void len_k(const float* __restrict__ x,
                                             int* __restrict__ lens)
{
    const int b = blockIdx.x;
    const int t = blockIdx.y * 256 + threadIdx.x;
    const float4* row = (const float4*)(x + ((size_t)b * NT + t) * NE);
    bool nz = false;
    #pragma unroll 4
    for (int e = 0; e < NE / 4; e++) {
        float4 v = row[e];
        if (v.x != 0.f || v.y != 0.f || v.z != 0.f || v.w != 0.f) { nz = true; break; }
    }
    int cnt = __syncthreads_count(nz);
    if (threadIdx.x == 0) atomicAdd(&lens[b], cnt);
}

// ---------------------------------------------------------------------------
__global__ __launch_bounds__(256) void split_k(const float* __restrict__ in,
                                               __half* __restrict__ h, __half* __restrict__ l,
                                               size_t n4)
{
    size_t i = (size_t)blockIdx.x * 256 + threadIdx.x;
    if (i >= n4) return;
    float4 v = ((const float4*)in)[i];
    __half h0, h1, h2, h3, l0, l1, l2, l3;
    split2h(v.x, h0, l0); split2h(v.y, h1, l1);
    split2h(v.z, h2, l2); split2h(v.w, h3, l3);
    __half2* hp = (__half2*)(h + i * 4);
    __half2* lp = (__half2*)(l + i * 4);
    hp[0] = __halves2half2(h0, h1); hp[1] = __halves2half2(h2, h3);
    lp[0] = __halves2half2(l0, l1); lp[1] = __halves2half2(l2, l3);
}

// W [E][N] fp32 -> transposed hi-only Wt[n][e]
__global__ __launch_bounds__(256) void trsplit_k(const float* __restrict__ W,
                                                 __half* __restrict__ Th)
{
    __shared__ float tile[32][33];
    const int bn = blockIdx.x * 32;
    const int be = blockIdx.y * 32;
    const int tx = threadIdx.x, ty = threadIdx.y;
    #pragma unroll
    for (int r = 0; r < 4; r++)
        tile[ty + r * 8][tx] = W[(size_t)(be + ty + r * 8) * ND + bn + tx];
    __syncthreads();
    #pragma unroll
    for (int r = 0; r < 4; r++) {
        float v = tile[tx][ty + r * 8];
        Th[(size_t)(bn + ty + r * 8) * NE + be + tx] = __float2half_rn(v);
    }
}

// ---------------------------------------------------------------------------
constexpr int SUB = 128 * 128;
constexpr int STAGE = 4 * SUB;
constexpr int NSTAGE = 3;
constexpr int SMEM_TOTAL = NSTAGE * STAGE;   // 196608

template<int TERMS>
__device__ __forceinline__ void gemm_core(
    const __half* __restrict__ Ah, const __half* __restrict__ Al,
    const __half* __restrict__ Bh, const __half* __restrict__ Bl,
    int Kdim, int nkt, int m0, int n0, char* sm, float (&c)[4][4][4])
{
    const int tid = threadIdx.x;
    const int wid = tid >> 5, lane = tid & 31;
    const int wm = (wid & 1) * 64;
    const int wn = (wid >> 1) * 32;

    const int a_row = (lane & 7) + ((lane >> 3) & 1) * 8;
    const int a_chk = lane >> 4;
    const int b_row = (lane & 7) + (lane >> 4) * 8;
    const int b_chk = (lane >> 3) & 1;

    const uint32_t smb = (uint32_t)__cvta_generic_to_shared(sm);

    float c2[4][4][4];
    #pragma unroll
    for (int i = 0; i < 4; i++)
        #pragma unroll
        for (int j = 0; j < 4; j++)
            #pragma unroll
            for (int t = 0; t < 4; t++) { c[i][j][t] = 0.f; if (TERMS >= 2) c2[i][j][t] = 0.f; }

    const int r = tid >> 1;
    const int c0 = (tid & 1) * 4;
    const size_t arow = (size_t)(m0 + r) * Kdim;
    const size_t brow = (size_t)(n0 + r) * Kdim;

    auto load_stage = [&](int buf, int k0) {
        const uint32_t sbase = smb + buf * STAGE;
        #pragma unroll
        for (int j = 0; j < 4; j++) {
            const int cc = c0 + j;
            const uint32_t so = swz(r * 128 + cc * 16);
            const size_t ko = (size_t)k0 + cc * 8;
            cp_async16(sbase + so,           Ah + arow + ko);
            if (TERMS >= 2) cp_async16(sbase + SUB + so, Al + arow + ko);
            cp_async16(sbase + 2 * SUB + so, Bh + brow + ko);
            if (TERMS == 3) cp_async16(sbase + 3 * SUB + so, Bl + brow + ko);
        }
        asm volatile("cp.async.commit_group;" ::: "memory");
    };

    load_stage(0, 0);
    load_stage(1, 64);

    int buf = 0;
    for (int i = 0; i < nkt; i++) {
        if (i + 1 < nkt) {
            asm volatile("cp.async.wait_group 1;" ::: "memory");
        } else {
            asm volatile("cp.async.wait_group 0;" ::: "memory");
        }
        __syncthreads();

        if (i + 2 < nkt) {
            int nb = buf + 2; if (nb >= NSTAGE) nb -= NSTAGE;
            load_stage(nb, (i + 2) * 64);
        }

        const uint32_t ahb = smb + buf * STAGE;
        const uint32_t alb = ahb + SUB;
        const uint32_t bhb = ahb + 2 * SUB;
        const uint32_t blb = ahb + 3 * SUB;

        #pragma unroll
        for (int kc = 0; kc < 8; kc += 2) {
            uint32_t bh[8], a[4][4];
            const uint32_t boff0 = swz((wn + b_row) * 128 + (kc + b_chk) * 16);
            const uint32_t boff1 = swz((wn + 16 + b_row) * 128 + (kc + b_chk) * 16);
            ldm4(bh + 0, bhb + boff0); ldm4(bh + 4, bhb + boff1);

            #pragma unroll
            for (int mt = 0; mt < 4; mt++) {
                const uint32_t off = swz((wm + mt * 16 + a_row) * 128 + (kc + a_chk) * 16);
                ldm4(a[mt], ahb + off);
            }
            #pragma unroll
            for (int mt = 0; mt < 4; mt++)
                #pragma unroll
                for (int nt = 0; nt < 4; nt++)
                    mma_f16(c[mt][nt], a[mt], &bh[nt * 2]);

            if (TERMS == 3) {
                uint32_t bl[8];
                ldm4(bl + 0, blb + boff0); ldm4(bl + 4, blb + boff1);
                #pragma unroll
                for (int mt = 0; mt < 4; mt++)
                    #pragma unroll
                    for (int nt = 0; nt < 4; nt++)
                        mma_f16(c2[mt][nt], a[mt], &bl[nt * 2]);
            }
            if (TERMS >= 2) {
                #pragma unroll
                for (int mt = 0; mt < 4; mt++) {
                    const uint32_t off = swz((wm + mt * 16 + a_row) * 128 + (kc + a_chk) * 16);
                    ldm4(a[mt], alb + off);
                }
                #pragma unroll
                for (int mt = 0; mt < 4; mt++)
                    #pragma unroll
                    for (int nt = 0; nt < 4; nt++)
                        mma_f16(c2[mt][nt], a[mt], &bh[nt * 2]);
            }
        }

        if (++buf >= NSTAGE) buf = 0;
    }

    if (TERMS >= 2) {
        constexpr float DS = 1.f / 2048.f;
        #pragma unroll
        for (int i = 0; i < 4; i++)
            #pragma unroll
            for (int j = 0; j < 4; j++)
                #pragma unroll
                for (int t = 0; t < 4; t++) c[i][j][t] += c2[i][j][t] * DS;
    }
    __syncthreads();
}

// ---- epilogues ----
__device__ __forceinline__ void epi_f32(float (&c)[4][4][4], float* Cz, int ldC,
                                        int m0, int n0)
{
    const int tid = threadIdx.x;
    const int wid = tid >> 5, lane = tid & 31;
    const int wm = (wid & 1) * 64, wn = (wid >> 1) * 32;
    const int g = lane >> 2, tg = lane & 3;
    #pragma unroll
    for (int mt = 0; mt < 4; mt++) {
        const int row = m0 + wm + mt * 16 + g;
        #pragma unroll
        for (int nt = 0; nt < 4; nt++) {
            const int col = n0 + wn + nt * 8 + tg * 2;
            *(float2*)(Cz + (size_t)row * ldC + col)       = make_float2(c[mt][nt][0], c[mt][nt][1]);
            *(float2*)(Cz + (size_t)(row + 8) * ldC + col) = make_float2(c[mt][nt][2], c[mt][nt][3]);
        }
    }
}

__device__ __forceinline__ void epi_split(float (&c)[4][4][4], __half* Ch, __half* Cl,
                                          int ldC, int m0, int n0)
{
    const int tid = threadIdx.x;
    const int wid = tid >> 5, lane = tid & 31;
    const int wm = (wid & 1) * 64, wn = (wid >> 1) * 32;
    const int g = lane >> 2, tg = lane & 3;
    #pragma unroll
    for (int mt = 0; mt < 4; mt++) {
        const int row = m0 + wm + mt * 16 + g;
        #pragma unroll
        for (int nt = 0; nt < 4; nt++) {
            const int col = n0 + wn + nt * 8 + tg * 2;
            __half h0, h1, l0, l1;
            split2h(c[mt][nt][0], h0, l0); split2h(c[mt][nt][1], h1, l1);
            *(__half2*)(Ch + (size_t)row * ldC + col) = __halves2half2(h0, h1);
            *(__half2*)(Cl + (size_t)row * ldC + col) = __halves2half2(l0, l1);
            split2h(c[mt][nt][2], h0, l0); split2h(c[mt][nt][3], h1, l1);
            *(__half2*)(Ch + (size_t)(row + 8) * ldC + col) = __halves2half2(h0, h1);
            *(__half2*)(Cl + (size_t)(row + 8) * ldC + col) = __halves2half2(l0, l1);
        }
    }
}

__device__ __forceinline__ void epi_vtrans(float (&c)[4][4][4], __half* Ch,
                                           int m0, int n0, char* sm)
{
    const int tid = threadIdx.x;
    const int wid = tid >> 5, lane = tid & 31;
    const int wm = (wid & 1) * 64, wn = (wid >> 1) * 32;
    const int g = lane >> 2, tg = lane & 3;
    float* smf = (float*)sm;                 // 128 x 132 fp32
    #pragma unroll
    for (int mt = 0; mt < 4; mt++) {
        const int rr = wm + mt * 16 + g;
        #pragma unroll
        for (int nt = 0; nt < 4; nt++) {
            const int cc = wn + nt * 8 + tg * 2;
            smf[(size_t)cc * 132 + rr]           = c[mt][nt][0];
            smf[(size_t)(cc + 1) * 132 + rr]     = c[mt][nt][1];
            smf[(size_t)cc * 132 + rr + 8]       = c[mt][nt][2];
            smf[(size_t)(cc + 1) * 132 + rr + 8] = c[mt][nt][3];
        }
    }
    __syncthreads();
    const int b = m0 >> 11, t0 = m0 & (NT - 1);
    __half* Hb = Ch + (size_t)b * ND * NT;
    const int dsub = tid >> 6;
    const int tcol = tid & 63;
    #pragma unroll
    for (int it = 0; it < 32; it++) {
        const int d = it * 4 + dsub;
        float2 v = *(float2*)(smf + (size_t)d * 132 + tcol * 2);
        *(__half2*)(Hb + (size_t)(n0 + d) * NT + t0 + tcol * 2) =
            __halves2half2(__float2half_rn(v.x), __float2half_rn(v.y));
    }
}

// ---------------------------------------------------------------------------
// MT = Wk * Wq^T
// ---------------------------------------------------------------------------
__global__ __launch_bounds__(256, 1) void gemm_mt(
    const __half* __restrict__ wkh, const __half* __restrict__ wkl,
    const __half* __restrict__ wqh, const __half* __restrict__ wql,
    __half* __restrict__ MTh, __half* __restrict__ MTl)
{
    extern __shared__ __align__(128) char sm[];
    const int m0 = blockIdx.y * 128, n0 = blockIdx.x * 128;
    float c[4][4][4];
    gemm_core<3>(wkh, wkl, wqh, wql, NE, NE / 64, m0, n0, sm, c);
    epi_split(c, MTh, MTl, NE, m0, n0);
}

// ---------------------------------------------------------------------------
// Y = x * M  (TERMS=3, split epilogue), skip padded rows
// ---------------------------------------------------------------------------
__global__ __launch_bounds__(256, 1) void gemm_y(
    const __half* __restrict__ xh, const __half* __restrict__ xl,
    const __half* __restrict__ MTh, const __half* __restrict__ MTl,
    __half* __restrict__ Yh, __half* __restrict__ Yl,
    const int* __restrict__ lens)
{
    extern __shared__ __align__(128) char sm[];
    const int m0 = blockIdx.y * 128, n0 = blockIdx.x * 128;
    if ((m0 & (NT - 1)) >= lens[m0 >> 11]) return;
    float c[4][4][4];
    gemm_core<3>(xh, xl, MTh, MTl, NE, NE / 64, m0, n0, sm, c);
    epi_split(c, Yh, Yl, ND, m0, n0);
}

// ---------------------------------------------------------------------------
// Vt = (x*Wv)^T  (TERMS=1, hi-only transposed epilogue), skip padded rows
// ---------------------------------------------------------------------------
__global__ __launch_bounds__(256, 1) void gemm_v(
    const __half* __restrict__ xh,
    const __half* __restrict__ wvh,
    __half* __restrict__ Vth, const int* __restrict__ lens)
{
    extern __shared__ __align__(128) char sm[];
    const int m0 = blockIdx.y * 128, n0 = blockIdx.x * 128;
    if ((m0 & (NT - 1)) >= lens[m0 >> 11]) return;
    float c[4][4][4];
    gemm_core<1>(xh, xh, wvh, wvh, NE, NE / 64, m0, n0, sm, c);
    epi_vtrans(c, Vth, m0, n0, sm);
}

// ---------------------------------------------------------------------------
// energy = Y x^T per batch, TERMS=3 (skip masked row/col blocks)
// ---------------------------------------------------------------------------
__global__ __launch_bounds__(256, 1) void gemm_qk(
    const __half* __restrict__ Yh, const __half* __restrict__ Yl,
    const __half* __restrict__ xh, const __half* __restrict__ xl,
    float* __restrict__ S, const int* __restrict__ lens)
{
    extern __shared__ __align__(128) char sm[];
    const int z = blockIdx.z;
    const int len = lens[z];
    const int m0 = blockIdx.y * 128, n0 = blockIdx.x * 128;
    if (m0 >= len || n0 >= len) return;

    const size_t offY = (size_t)z * NT * ND;
    const size_t offX = (size_t)z * NT * NE;
    float c[4][4][4];
    gemm_core<3>(Yh + offY, Yl + offY, xh + offX, xl + offX, NE, NE / 64, m0, n0, sm, c);
    epi_f32(c, S + (size_t)z * NT * NT, NT, m0, n0);
}

// ---------------------------------------------------------------------------
// out = P V per batch, TERMS=1; rows >= len handled by fill_pad_k
// ---------------------------------------------------------------------------
__global__ __launch_bounds__(256, 1) void gemm_pv(
    const __half* __restrict__ Ph,
    const __half* __restrict__ Vth,
    float* __restrict__ out, const int* __restrict__ lens)
{
    extern __shared__ __align__(128) char sm[];
    const int z = blockIdx.z;
    const int len = lens[z];
    const int m0 = blockIdx.y * 128, n0 = blockIdx.x * 128;
    if (m0 >= len) return;

    const int nkt = (len + 63) >> 6;
    const __half* P = Ph + (size_t)z * NT * NT;
    const __half* V = Vth + (size_t)z * ND * NT;
    float c[4][4][4];
    gemm_core<1>(P, P, V, V, NT, nkt, m0, n0, sm, c);
    epi_f32(c, out + (size_t)z * NT * ND, ND, m0, n0);
}

// ---------------------------------------------------------------------------
// masked row softmax -> fp16 P
// ---------------------------------------------------------------------------
__global__ __launch_bounds__(256) void softmax_h_k(const float* __restrict__ S,
                                                   __half* __restrict__ Ph,
                                                   const int* __restrict__ lens)
{
    __shared__ float cache[NT];
    __shared__ float red[256];
    const int row = blockIdx.x;
    const int b = row >> 11;
    const int t = row & (NT - 1);
    const int len = lens[b];
    const int rowmax = (len + 127) & ~127;
    if (t >= rowmax) return;
    const int colmax = (len + 63) & ~63;

    __half* ph = Ph + (size_t)row * NT;
    const int tid = threadIdx.x;
    const __half z0 = __float2half_rn(0.f);

    if (t >= len) {
        const __half h = __float2half_rn(1.f / (float)len);
        for (int s = tid; s < len; s += 256) ph[s] = h;
        for (int s = len + tid; s < colmax; s += 256) ph[s] = z0;
        return;
    }

    const float* p = S + (size_t)row * NT;

    float m = -1e30f;
    for (int s = tid; s < len; s += 256) {
        float v = p[s];
        cache[s] = v;
        m = fmaxf(m, v);
    }
    red[tid] = m; __syncthreads();
    #pragma unroll
    for (int off = 128; off > 0; off >>= 1) {
        if (tid < off) red[tid] = fmaxf(red[tid], red[tid + off]);
        __syncthreads();
    }
    m = red[0]; __syncthreads();

    float sum = 0.f;
    for (int s = tid; s < len; s += 256) {
        float e = __expf((cache[s] - m) * 0.125f);
        cache[s] = e;
        sum += e;
    }
    red[tid] = sum; __syncthreads();
    #pragma unroll
    for (int off = 128; off > 0; off >>= 1) {
        if (tid < off) red[tid] += red[tid + off];
        __syncthreads();
    }
    const float inv = 1.f / red[0];

    for (int s = tid; s < len; s += 256)
        ph[s] = __float2half_rn(cache[s] * inv);
    for (int s = len + tid; s < colmax; s += 256) ph[s] = z0;
}

// ---------------------------------------------------------------------------
__global__ __launch_bounds__(256) void vsum_k(const __half* __restrict__ Vth,
                                              float* __restrict__ bc,
                                              const int* __restrict__ lens)
{
    const int b = blockIdx.y;
    const int len = lens[b];
    const int d = blockIdx.x * 8 + (threadIdx.x >> 5);
    const int lane = threadIdx.x & 31;
    const __half* ph = Vth + ((size_t)b * ND + d) * NT;
    float s = 0.f;
    for (int t = lane; t < len; t += 32)
        s += __half2float(ph[t]);
    #pragma unroll
    for (int o = 16; o > 0; o >>= 1) s += __shfl_xor_sync(0xffffffffu, s, o);
    if (lane == 0) bc[(size_t)b * ND + d] = s / (float)len;
}

__global__ __launch_bounds__(256) void fill_pad_k(float* __restrict__ out,
                                                  const float* __restrict__ bc,
                                                  const int* __restrict__ lens)
{
    const int b = blockIdx.y;
    const int t = blockIdx.x;
    if (t < lens[b]) return;
    const float4* src = (const float4*)(bc + (size_t)b * ND);
    float4* dst = (float4*)(out + ((size_t)b * NT + t) * ND);
    for (int i = threadIdx.x; i < ND / 4; i += 256) dst[i] = src[i];
}

// ---------------------------------------------------------------------------
extern "C" void kernel_launch(void* const* d_in, const int* in_sizes, int n_in,
                              void* d_out, int out_size)
{
    const float* x  = (const float*)d_in[0];
    const float* Wq = (const float*)d_in[1];
    const float* Wk = (const float*)d_in[2];
    const float* Wv = (const float*)d_in[3];
    float* out = (float*)d_out;

    unsigned char* pool;
    int* lens;
    cudaGetSymbolAddress((void**)&pool, g_pool);
    cudaGetSymbolAddress((void**)&lens, g_len);

    __half* xh  = (__half*)(pool + OFF_XH);
    __half* xl  = (__half*)(pool + OFF_XL);
    __half* wqh = (__half*)(pool + OFF_WQH);
    __half* wql = (__half*)(pool + OFF_WQL);
    __half* wkh = (__half*)(pool + OFF_WKH);
    __half* wkl = (__half*)(pool + OFF_WKL);
    __half* wvh = (__half*)(pool + OFF_WVH);
    __half* MTh = (__half*)(pool + OFF_MTH);
    __half* MTl = (__half*)(pool + OFF_MTL);
    __half* Yh  = (__half*)(pool + OFF_YH);
    __half* Yl  = (__half*)(pool + OFF_YL);
    __half* Vth = (__half*)(pool + OFF_VTH);
    float* S  = (float*)(pool + OFF_S);
    __half* Ph  = (__half*)(pool + OFF_PH);
    float* bc = (float*)(pool + OFF_BC);

    static bool init_done = false;
    static cudaStream_t s1, s2;
    static cudaEvent_t evStart, evX, evMT, evV;
    if (!init_done) {
        cudaFuncSetAttribute(gemm_mt, cudaFuncAttributeMaxDynamicSharedMemorySize, SMEM_TOTAL);
        cudaFuncSetAttribute(gemm_y,  cudaFuncAttributeMaxDynamicSharedMemorySize, SMEM_TOTAL);
        cudaFuncSetAttribute(gemm_v,  cudaFuncAttributeMaxDynamicSharedMemorySize, SMEM_TOTAL);
        cudaFuncSetAttribute(gemm_qk, cudaFuncAttributeMaxDynamicSharedMemorySize, SMEM_TOTAL);
        cudaFuncSetAttribute(gemm_pv, cudaFuncAttributeMaxDynamicSharedMemorySize, SMEM_TOTAL);
        cudaStreamCreateWithFlags(&s1, cudaStreamNonBlocking);
        cudaStreamCreateWithFlags(&s2, cudaStreamNonBlocking);
        cudaEventCreateWithFlags(&evStart, cudaEventDisableTiming);
        cudaEventCreateWithFlags(&evX, cudaEventDisableTiming);
        cudaEventCreateWithFlags(&evMT, cudaEventDisableTiming);
        cudaEventCreateWithFlags(&evV, cudaEventDisableTiming);
        init_done = true;
    }

    dim3 blk(256);

    // fork point
    cudaEventRecord(evStart, 0);
    cudaStreamWaitEvent(s1, evStart, 0);
    cudaStreamWaitEvent(s2, evStart, 0);

    // s1: Wq/Wk splits + MT (independent of x)
    split_k<<<(int)(SZ_W / 4 / 256), 256, 0, s1>>>(Wq, wqh, wql, SZ_W / 4);
    split_k<<<(int)(SZ_W / 4 / 256), 256, 0, s1>>>(Wk, wkh, wkl, SZ_W / 4);
    gemm_mt<<<dim3(NE / 128, NE / 128), blk, SMEM_TOTAL, s1>>>(wkh, wkl, wqh, wql, MTh, MTl);
    cudaEventRecord(evMT, s1);

    // s2: Wv transpose (x-split joined below)
    dim3 tg(32, 32), tb(32, 8);
    trsplit_k<<<tg, tb, 0, s2>>>(Wv, wvh);

    // main: lengths + x split
    cudaMemsetAsync(lens, 0, NB * sizeof(int), 0);
    len_k<<<dim3(NB, NT / 256), 256, 0, 0>>>(x, lens);
    split_k<<<(int)(SZ_X / 4 / 256), 256, 0, 0>>>(x, xh, xl, SZ_X / 4);
    cudaEventRecord(evX, 0);

    // s2: V projection + vsum (needs x split + lens), overlaps with Y/QK on main
    cudaStreamWaitEvent(s2, evX, 0);
    dim3 gv(ND / 128, (NB * NT) / 128);
    gemm_v<<<gv, blk, SMEM_TOTAL, s2>>>(xh, wvh, Vth, lens);
    vsum_k<<<dim3(ND / 8, NB), 256, 0, s2>>>(Vth, bc, lens);
    cudaEventRecord(evV, s2);

    // main: Y projection (needs MT)
    cudaStreamWaitEvent(0, evMT, 0);
    dim3 gy(ND / 128, (NB * NT) / 128);
    gemm_y<<<gy, blk, SMEM_TOTAL, 0>>>(xh, xl, MTh, MTl, Yh, Yl, lens);

    // main: energy = Y x^T
    dim3 ge(NT / 128, NT / 128, NB);
    gemm_qk<<<ge, blk, SMEM_TOTAL, 0>>>(Yh, Yl, xh, xl, S, lens);

    // main: softmax -> fp16 P
    softmax_h_k<<<NB * NT, 256, 0, 0>>>(S, Ph, lens);

    // join V before PV / fill
    cudaStreamWaitEvent(0, evV, 0);
    dim3 go(ND / 128, NT / 128, NB);
    gemm_pv<<<go, blk, SMEM_TOTAL, 0>>>(Ph, Vth, out, lens);
    fill_pad_k<<<dim3(NT, NB), 256, 0, 0>>>(out, bc, lens);
}

// round 16
// speedup vs baseline: 4.0841x; 1.0038x over previous
#include <cuda_runtime.h>
#include <cuda_fp16.h>
#include <cstdint>

#define NB 8
#define NT 2048
#define NE 1024
#define ND 1024

constexpr size_t SZ_X = (size_t)NB * NT * NE;
constexpr size_t SZ_W = (size_t)NE * ND;
constexpr size_t SZ_S = (size_t)NB * NT * NT;

// ---- static scratch pool ----
constexpr size_t OFF_XH  = 0;
constexpr size_t OFF_XL  = OFF_XH  + SZ_X * 2;
constexpr size_t OFF_WQH = OFF_XL  + SZ_X * 2;
constexpr size_t OFF_WQL = OFF_WQH + SZ_W * 2;
constexpr size_t OFF_WKH = OFF_WQL + SZ_W * 2;
constexpr size_t OFF_WKL = OFF_WKH + SZ_W * 2;
constexpr size_t OFF_WVH = OFF_WKL + SZ_W * 2;
constexpr size_t OFF_MTH = OFF_WVH + SZ_W * 2;
constexpr size_t OFF_MTL = OFF_MTH + SZ_W * 2;
constexpr size_t OFF_YH  = OFF_MTL + SZ_W * 2;
constexpr size_t OFF_YL  = OFF_YH  + SZ_X * 2;
constexpr size_t OFF_VTH = OFF_YL  + SZ_X * 2;
constexpr size_t OFF_S   = OFF_VTH + SZ_X * 2;
constexpr size_t OFF_PH  = OFF_S   + SZ_S * 4;
constexpr size_t OFF_BC  = OFF_PH  + SZ_S * 2;
constexpr size_t POOL_SZ = OFF_BC  + (size_t)NB * ND * 4;

__device__ __align__(256) unsigned char g_pool[POOL_SZ];
__device__ int g_len[NB];

// ---------------------------------------------------------------------------
__device__ __forceinline__ void split2h(float v, __half& h, __half& l) {
    h = __float2half_rn(v);
    l = __float2half_rn((v - __half2float(h)) * 2048.f);
}

__device__ __forceinline__ void cp_async16(uint32_t dst, const void* src) {
    asm volatile("cp.async.cg.shared.global [%0], [%1], 16;\n"
                 :: "r"(dst), "l"(src) : "memory");
}

__device__ __forceinline__ uint32_t swz(uint32_t off) {
    return off ^ ((off >> 3) & 0x70);
}

__device__ __forceinline__ void ldm4(uint32_t* r, uint32_t a) {
    asm volatile("ldmatrix.sync.aligned.m8n8.x4.shared.b16 {%0,%1,%2,%3}, [%4];"
                 : "=r"(r[0]), "=r"(r[1]), "=r"(r[2]), "=r"(r[3]) : "r"(a));
}

__device__ __forceinline__ void mma_f16(float* c, const uint32_t* a, const uint32_t* b) {
    asm volatile(
        "mma.sync.aligned.m16n8k16.row.col.f32.f16.f16.f32 "
        "{%0,%1,%2,%3}, {%4,%5,%6,%7}, {%8,%9}, {%0,%1,%2,%3};\n"
        : "+f"(c[0]), "+f"(c[1]), "+f"(c[2]), "+f"(c[3])
        : "r"(a[0]), "r"(a[1]), "r"(a[2]), "r"(a[3]), "r"(b[0]), "r"(b[1]));
}

// ---------------------------------------------------------------------------
__global__ __launch_bounds__(256) void len_k(const float* __restrict__ x,
                                             int* __restrict__ lens)
{
    const int b = blockIdx.x;
    const int t = blockIdx.y * 256 + threadIdx.x;
    const float4* row = (const float4*)(x + ((size_t)b * NT + t) * NE);
    bool nz = false;
    #pragma unroll 4
    for (int e = 0; e < NE / 4; e++) {
        float4 v = row[e];
        if (v.x != 0.f || v.y != 0.f || v.z != 0.f || v.w != 0.f) { nz = true; break; }
    }
    int cnt = __syncthreads_count(nz);
    if (threadIdx.x == 0) atomicAdd(&lens[b], cnt);
}

// ---------------------------------------------------------------------------
__global__ __launch_bounds__(256) void split_k(const float* __restrict__ in,
                                               __half* __restrict__ h, __half* __restrict__ l,
                                               size_t n4)
{
    size_t i = (size_t)blockIdx.x * 256 + threadIdx.x;
    if (i >= n4) return;
    float4 v = ((const float4*)in)[i];
    __half h0, h1, h2, h3, l0, l1, l2, l3;
    split2h(v.x, h0, l0); split2h(v.y, h1, l1);
    split2h(v.z, h2, l2); split2h(v.w, h3, l3);
    __half2* hp = (__half2*)(h + i * 4);
    __half2* lp = (__half2*)(l + i * 4);
    hp[0] = __halves2half2(h0, h1); hp[1] = __halves2half2(h2, h3);
    lp[0] = __halves2half2(l0, l1); lp[1] = __halves2half2(l2, l3);
}

// W [E][N] fp32 -> transposed hi-only Wt[n][e]
__global__ __launch_bounds__(256) void trsplit_k(const float* __restrict__ W,
                                                 __half* __restrict__ Th)
{
    __shared__ float tile[32][33];
    const int bn = blockIdx.x * 32;
    const int be = blockIdx.y * 32;
    const int tx = threadIdx.x, ty = threadIdx.y;
    #pragma unroll
    for (int r = 0; r < 4; r++)
        tile[ty + r * 8][tx] = W[(size_t)(be + ty + r * 8) * ND + bn + tx];
    __syncthreads();
    #pragma unroll
    for (int r = 0; r < 4; r++) {
        float v = tile[tx][ty + r * 8];
        Th[(size_t)(bn + ty + r * 8) * NE + be + tx] = __float2half_rn(v);
    }
}

// ---------------------------------------------------------------------------
constexpr int SUB = 128 * 128;
constexpr int STAGE = 4 * SUB;
constexpr int NSTAGE = 3;
constexpr int SMEM_TOTAL = NSTAGE * STAGE;   // 196608

template<int TERMS>
__device__ __forceinline__ void gemm_core(
    const __half* __restrict__ Ah, const __half* __restrict__ Al,
    const __half* __restrict__ Bh, const __half* __restrict__ Bl,
    int Kdim, int nkt, int m0, int n0, char* sm, float (&c)[4][4][4])
{
    const int tid = threadIdx.x;
    const int wid = tid >> 5, lane = tid & 31;
    const int wm = (wid & 1) * 64;
    const int wn = (wid >> 1) * 32;

    const int a_row = (lane & 7) + ((lane >> 3) & 1) * 8;
    const int a_chk = lane >> 4;
    const int b_row = (lane & 7) + (lane >> 4) * 8;
    const int b_chk = (lane >> 3) & 1;

    const uint32_t smb = (uint32_t)__cvta_generic_to_shared(sm);

    float c2[4][4][4];
    #pragma unroll
    for (int i = 0; i < 4; i++)
        #pragma unroll
        for (int j = 0; j < 4; j++)
            #pragma unroll
            for (int t = 0; t < 4; t++) { c[i][j][t] = 0.f; if (TERMS >= 2) c2[i][j][t] = 0.f; }

    const int r = tid >> 1;
    const int c0 = (tid & 1) * 4;
    const size_t arow = (size_t)(m0 + r) * Kdim;
    const size_t brow = (size_t)(n0 + r) * Kdim;

    auto load_stage = [&](int buf, int k0) {
        const uint32_t sbase = smb + buf * STAGE;
        #pragma unroll
        for (int j = 0; j < 4; j++) {
            const int cc = c0 + j;
            const uint32_t so = swz(r * 128 + cc * 16);
            const size_t ko = (size_t)k0 + cc * 8;
            cp_async16(sbase + so,           Ah + arow + ko);
            if (TERMS >= 2) cp_async16(sbase + SUB + so, Al + arow + ko);
            cp_async16(sbase + 2 * SUB + so, Bh + brow + ko);
            if (TERMS == 3) cp_async16(sbase + 3 * SUB + so, Bl + brow + ko);
        }
        asm volatile("cp.async.commit_group;" ::: "memory");
    };

    load_stage(0, 0);
    load_stage(1, 64);

    int buf = 0;
    for (int i = 0; i < nkt; i++) {
        if (i + 1 < nkt) {
            asm volatile("cp.async.wait_group 1;" ::: "memory");
        } else {
            asm volatile("cp.async.wait_group 0;" ::: "memory");
        }
        __syncthreads();

        if (i + 2 < nkt) {
            int nb = buf + 2; if (nb >= NSTAGE) nb -= NSTAGE;
            load_stage(nb, (i + 2) * 64);
        }

        const uint32_t ahb = smb + buf * STAGE;
        const uint32_t alb = ahb + SUB;
        const uint32_t bhb = ahb + 2 * SUB;
        const uint32_t blb = ahb + 3 * SUB;

        #pragma unroll
        for (int kc = 0; kc < 8; kc += 2) {
            uint32_t bh[8], a[4][4];
            const uint32_t boff0 = swz((wn + b_row) * 128 + (kc + b_chk) * 16);
            const uint32_t boff1 = swz((wn + 16 + b_row) * 128 + (kc + b_chk) * 16);
            ldm4(bh + 0, bhb + boff0); ldm4(bh + 4, bhb + boff1);

            #pragma unroll
            for (int mt = 0; mt < 4; mt++) {
                const uint32_t off = swz((wm + mt * 16 + a_row) * 128 + (kc + a_chk) * 16);
                ldm4(a[mt], ahb + off);
            }
            #pragma unroll
            for (int mt = 0; mt < 4; mt++)
                #pragma unroll
                for (int nt = 0; nt < 4; nt++)
                    mma_f16(c[mt][nt], a[mt], &bh[nt * 2]);

            if (TERMS == 3) {
                uint32_t bl[8];
                ldm4(bl + 0, blb + boff0); ldm4(bl + 4, blb + boff1);
                #pragma unroll
                for (int mt = 0; mt < 4; mt++)
                    #pragma unroll
                    for (int nt = 0; nt < 4; nt++)
                        mma_f16(c2[mt][nt], a[mt], &bl[nt * 2]);
            }
            if (TERMS >= 2) {
                #pragma unroll
                for (int mt = 0; mt < 4; mt++) {
                    const uint32_t off = swz((wm + mt * 16 + a_row) * 128 + (kc + a_chk) * 16);
                    ldm4(a[mt], alb + off);
                }
                #pragma unroll
                for (int mt = 0; mt < 4; mt++)
                    #pragma unroll
                    for (int nt = 0; nt < 4; nt++)
                        mma_f16(c2[mt][nt], a[mt], &bh[nt * 2]);
            }
        }

        if (++buf >= NSTAGE) buf = 0;
    }

    if (TERMS >= 2) {
        constexpr float DS = 1.f / 2048.f;
        #pragma unroll
        for (int i = 0; i < 4; i++)
            #pragma unroll
            for (int j = 0; j < 4; j++)
                #pragma unroll
                for (int t = 0; t < 4; t++) c[i][j][t] += c2[i][j][t] * DS;
    }
    __syncthreads();
}

// ---- epilogues ----
__device__ __forceinline__ void epi_f32(float (&c)[4][4][4], float* Cz, int ldC,
                                        int m0, int n0)
{
    const int tid = threadIdx.x;
    const int wid = tid >> 5, lane = tid & 31;
    const int wm = (wid & 1) * 64, wn = (wid >> 1) * 32;
    const int g = lane >> 2, tg = lane & 3;
    #pragma unroll
    for (int mt = 0; mt < 4; mt++) {
        const int row = m0 + wm + mt * 16 + g;
        #pragma unroll
        for (int nt = 0; nt < 4; nt++) {
            const int col = n0 + wn + nt * 8 + tg * 2;
            *(float2*)(Cz + (size_t)row * ldC + col)       = make_float2(c[mt][nt][0], c[mt][nt][1]);
            *(float2*)(Cz + (size_t)(row + 8) * ldC + col) = make_float2(c[mt][nt][2], c[mt][nt][3]);
        }
    }
}

__device__ __forceinline__ void epi_split(float (&c)[4][4][4], __half* Ch, __half* Cl,
                                          int ldC, int m0, int n0)
{
    const int tid = threadIdx.x;
    const int wid = tid >> 5, lane = tid & 31;
    const int wm = (wid & 1) * 64, wn = (wid >> 1) * 32;
    const int g = lane >> 2, tg = lane & 3;
    #pragma unroll
    for (int mt = 0; mt < 4; mt++) {
        const int row = m0 + wm + mt * 16 + g;
        #pragma unroll
        for (int nt = 0; nt < 4; nt++) {
            const int col = n0 + wn + nt * 8 + tg * 2;
            __half h0, h1, l0, l1;
            split2h(c[mt][nt][0], h0, l0); split2h(c[mt][nt][1], h1, l1);
            *(__half2*)(Ch + (size_t)row * ldC + col) = __halves2half2(h0, h1);
            *(__half2*)(Cl + (size_t)row * ldC + col) = __halves2half2(l0, l1);
            split2h(c[mt][nt][2], h0, l0); split2h(c[mt][nt][3], h1, l1);
            *(__half2*)(Ch + (size_t)(row + 8) * ldC + col) = __halves2half2(h0, h1);
            *(__half2*)(Cl + (size_t)(row + 8) * ldC + col) = __halves2half2(l0, l1);
        }
    }
}

__device__ __forceinline__ void epi_vtrans(float (&c)[4][4][4], __half* Ch,
                                           int m0, int n0, char* sm)
{
    const int tid = threadIdx.x;
    const int wid = tid >> 5, lane = tid & 31;
    const int wm = (wid & 1) * 64, wn = (wid >> 1) * 32;
    const int g = lane >> 2, tg = lane & 3;
    float* smf = (float*)sm;                 // 128 x 132 fp32
    #pragma unroll
    for (int mt = 0; mt < 4; mt++) {
        const int rr = wm + mt * 16 + g;
        #pragma unroll
        for (int nt = 0; nt < 4; nt++) {
            const int cc = wn + nt * 8 + tg * 2;
            smf[(size_t)cc * 132 + rr]           = c[mt][nt][0];
            smf[(size_t)(cc + 1) * 132 + rr]     = c[mt][nt][1];
            smf[(size_t)cc * 132 + rr + 8]       = c[mt][nt][2];
            smf[(size_t)(cc + 1) * 132 + rr + 8] = c[mt][nt][3];
        }
    }
    __syncthreads();
    const int b = m0 >> 11, t0 = m0 & (NT - 1);
    __half* Hb = Ch + (size_t)b * ND * NT;
    const int dsub = tid >> 6;
    const int tcol = tid & 63;
    #pragma unroll
    for (int it = 0; it < 32; it++) {
        const int d = it * 4 + dsub;
        float2 v = *(float2*)(smf + (size_t)d * 132 + tcol * 2);
        *(__half2*)(Hb + (size_t)(n0 + d) * NT + t0 + tcol * 2) =
            __halves2half2(__float2half_rn(v.x), __float2half_rn(v.y));
    }
}

// ---------------------------------------------------------------------------
// MT = Wk * Wq^T
// ---------------------------------------------------------------------------
__global__ __launch_bounds__(256, 1) void gemm_mt(
    const __half* __restrict__ wkh, const __half* __restrict__ wkl,
    const __half* __restrict__ wqh, const __half* __restrict__ wql,
    __half* __restrict__ MTh, __half* __restrict__ MTl)
{
    extern __shared__ __align__(128) char sm[];
    const int m0 = blockIdx.y * 128, n0 = blockIdx.x * 128;
    float c[4][4][4];
    gemm_core<3>(wkh, wkl, wqh, wql, NE, NE / 64, m0, n0, sm, c);
    epi_split(c, MTh, MTl, NE, m0, n0);
}

// ---------------------------------------------------------------------------
// Y(b) = x_b * M  (TERMS=3), per-batch launch, skip padded row blocks
// ---------------------------------------------------------------------------
__global__ __launch_bounds__(256, 1) void gemm_y(
    const __half* __restrict__ xh, const __half* __restrict__ xl,
    const __half* __restrict__ MTh, const __half* __restrict__ MTl,
    __half* __restrict__ Yh, __half* __restrict__ Yl,
    const int* __restrict__ lens, int b)
{
    extern __shared__ __align__(128) char sm[];
    const int mloc = blockIdx.y * 128;
    if (mloc >= lens[b]) return;
    const int m0 = b * NT + mloc;
    const int n0 = blockIdx.x * 128;
    float c[4][4][4];
    gemm_core<3>(xh, xl, MTh, MTl, NE, NE / 64, m0, n0, sm, c);
    epi_split(c, Yh, Yl, ND, m0, n0);
}

// ---------------------------------------------------------------------------
// Vt = (x*Wv)^T  (TERMS=1), all batches, skip padded rows
// ---------------------------------------------------------------------------
__global__ __launch_bounds__(256, 1) void gemm_v(
    const __half* __restrict__ xh,
    const __half* __restrict__ wvh,
    __half* __restrict__ Vth, const int* __restrict__ lens)
{
    extern __shared__ __align__(128) char sm[];
    const int m0 = blockIdx.y * 128, n0 = blockIdx.x * 128;
    if ((m0 & (NT - 1)) >= lens[m0 >> 11]) return;
    float c[4][4][4];
    gemm_core<1>(xh, xh, wvh, wvh, NE, NE / 64, m0, n0, sm, c);
    epi_vtrans(c, Vth, m0, n0, sm);
}

// ---------------------------------------------------------------------------
// energy(b) = Y_b x_b^T, per-batch launch (skip masked row/col blocks)
// ---------------------------------------------------------------------------
__global__ __launch_bounds__(256, 1) void gemm_qk(
    const __half* __restrict__ Yh, const __half* __restrict__ Yl,
    const __half* __restrict__ xh, const __half* __restrict__ xl,
    float* __restrict__ S, const int* __restrict__ lens, int b)
{
    extern __shared__ __align__(128) char sm[];
    const int len = lens[b];
    const int m0 = blockIdx.y * 128, n0 = blockIdx.x * 128;
    if (m0 >= len || n0 >= len) return;

    const size_t offY = (size_t)b * NT * ND;
    const size_t offX = (size_t)b * NT * NE;
    float c[4][4][4];
    gemm_core<3>(Yh + offY, Yl + offY, xh + offX, xl + offX, NE, NE / 64, m0, n0, sm, c);
    epi_f32(c, S + (size_t)b * NT * NT, NT, m0, n0);
}

// ---------------------------------------------------------------------------
// out(b) = P_b V_b, per-batch launch, TERMS=1
// ---------------------------------------------------------------------------
__global__ __launch_bounds__(256, 1) void gemm_pv(
    const __half* __restrict__ Ph,
    const __half* __restrict__ Vth,
    float* __restrict__ out, const int* __restrict__ lens, int b)
{
    extern __shared__ __align__(128) char sm[];
    const int len = lens[b];
    const int m0 = blockIdx.y * 128, n0 = blockIdx.x * 128;
    if (m0 >= len) return;

    const int nkt = (len + 63) >> 6;
    const __half* P = Ph + (size_t)b * NT * NT;
    const __half* V = Vth + (size_t)b * ND * NT;
    float c[4][4][4];
    gemm_core<1>(P, P, V, V, NT, nkt, m0, n0, sm, c);
    epi_f32(c, out + (size_t)b * NT * ND, ND, m0, n0);
}

// ---------------------------------------------------------------------------
// masked row softmax(b) -> fp16 P, per-batch launch
// ---------------------------------------------------------------------------
__global__ __launch_bounds__(256) void softmax_h_k(const float* __restrict__ S,
                                                   __half* __restrict__ Ph,
                                                   const int* __restrict__ lens, int b)
{
    __shared__ float cache[NT];
    __shared__ float red[256];
    const int t = blockIdx.x;
    const int len = lens[b];
    const int rowmax = (len + 127) & ~127;
    if (t >= rowmax) return;
    const int colmax = (len + 63) & ~63;
    const int row = b * NT + t;

    __half* ph = Ph + (size_t)row * NT;
    const int tid = threadIdx.x;
    const __half z0 = __float2half_rn(0.f);

    if (t >= len) {
        const __half h = __float2half_rn(1.f / (float)len);
        for (int s = tid; s < len; s += 256) ph[s] = h;
        for (int s = len + tid; s < colmax; s += 256) ph[s] = z0;
        return;
    }

    const float* p = S + (size_t)row * NT;

    float m = -1e30f;
    for (int s = tid; s < len; s += 256) {
        float v = p[s];
        cache[s] = v;
        m = fmaxf(m, v);
    }
    red[tid] = m; __syncthreads();
    #pragma unroll
    for (int off = 128; off > 0; off >>= 1) {
        if (tid < off) red[tid] = fmaxf(red[tid], red[tid + off]);
        __syncthreads();
    }
    m = red[0]; __syncthreads();

    float sum = 0.f;
    for (int s = tid; s < len; s += 256) {
        float e = __expf((cache[s] - m) * 0.125f);
        cache[s] = e;
        sum += e;
    }
    red[tid] = sum; __syncthreads();
    #pragma unroll
    for (int off = 128; off > 0; off >>= 1) {
        if (tid < off) red[tid] += red[tid + off];
        __syncthreads();
    }
    const float inv = 1.f / red[0];

    for (int s = tid; s < len; s += 256)
        ph[s] = __float2half_rn(cache[s] * inv);
    for (int s = len + tid; s < colmax; s += 256) ph[s] = z0;
}

// ---------------------------------------------------------------------------
__global__ __launch_bounds__(256) void vsum_k(const __half* __restrict__ Vth,
                                              float* __restrict__ bc,
                                              const int* __restrict__ lens)
{
    const int b = blockIdx.y;
    const int len = lens[b];
    const int d = blockIdx.x * 8 + (threadIdx.x >> 5);
    const int lane = threadIdx.x & 31;
    const __half* ph = Vth + ((size_t)b * ND + d) * NT;
    float s = 0.f;
    for (int t = lane; t < len; t += 32)
        s += __half2float(ph[t]);
    #pragma unroll
    for (int o = 16; o > 0; o >>= 1) s += __shfl_xor_sync(0xffffffffu, s, o);
    if (lane == 0) bc[(size_t)b * ND + d] = s / (float)len;
}

// out(b)[t][:] = bc[b][:] for t >= len, per-batch launch
__global__ __launch_bounds__(256) void fill_pad_k(float* __restrict__ out,
                                                  const float* __restrict__ bc,
                                                  const int* __restrict__ lens, int b)
{
    const int t = blockIdx.x;
    if (t < lens[b]) return;
    const float4* src = (const float4*)(bc + (size_t)b * ND);
    float4* dst = (float4*)(out + ((size_t)b * NT + t) * ND);
    for (int i = threadIdx.x; i < ND / 4; i += 256) dst[i] = src[i];
}

// ---------------------------------------------------------------------------
extern "C" void kernel_launch(void* const* d_in, const int* in_sizes, int n_in,
                              void* d_out, int out_size)
{
    const float* x  = (const float*)d_in[0];
    const float* Wq = (const float*)d_in[1];
    const float* Wk = (const float*)d_in[2];
    const float* Wv = (const float*)d_in[3];
    float* out = (float*)d_out;

    unsigned char* pool;
    int* lens;
    cudaGetSymbolAddress((void**)&pool, g_pool);
    cudaGetSymbolAddress((void**)&lens, g_len);

    __half* xh  = (__half*)(pool + OFF_XH);
    __half* xl  = (__half*)(pool + OFF_XL);
    __half* wqh = (__half*)(pool + OFF_WQH);
    __half* wql = (__half*)(pool + OFF_WQL);
    __half* wkh = (__half*)(pool + OFF_WKH);
    __half* wkl = (__half*)(pool + OFF_WKL);
    __half* wvh = (__half*)(pool + OFF_WVH);
    __half* MTh = (__half*)(pool + OFF_MTH);
    __half* MTl = (__half*)(pool + OFF_MTL);
    __half* Yh  = (__half*)(pool + OFF_YH);
    __half* Yl  = (__half*)(pool + OFF_YL);
    __half* Vth = (__half*)(pool + OFF_VTH);
    float* S  = (float*)(pool + OFF_S);
    __half* Ph  = (__half*)(pool + OFF_PH);
    float* bc = (float*)(pool + OFF_BC);

    static bool init_done = false;
    static cudaStream_t s1, s2;
    static cudaEvent_t evStart, evX, evMT, evV, evJ1, evJ2;
    if (!init_done) {
        cudaFuncSetAttribute(gemm_mt, cudaFuncAttributeMaxDynamicSharedMemorySize, SMEM_TOTAL);
        cudaFuncSetAttribute(gemm_y,  cudaFuncAttributeMaxDynamicSharedMemorySize, SMEM_TOTAL);
        cudaFuncSetAttribute(gemm_v,  cudaFuncAttributeMaxDynamicSharedMemorySize, SMEM_TOTAL);
        cudaFuncSetAttribute(gemm_qk, cudaFuncAttributeMaxDynamicSharedMemorySize, SMEM_TOTAL);
        cudaFuncSetAttribute(gemm_pv, cudaFuncAttributeMaxDynamicSharedMemorySize, SMEM_TOTAL);
        cudaStreamCreateWithFlags(&s1, cudaStreamNonBlocking);
        cudaStreamCreateWithFlags(&s2, cudaStreamNonBlocking);
        cudaEventCreateWithFlags(&evStart, cudaEventDisableTiming);
        cudaEventCreateWithFlags(&evX, cudaEventDisableTiming);
        cudaEventCreateWithFlags(&evMT, cudaEventDisableTiming);
        cudaEventCreateWithFlags(&evV, cudaEventDisableTiming);
        cudaEventCreateWithFlags(&evJ1, cudaEventDisableTiming);
        cudaEventCreateWithFlags(&evJ2, cudaEventDisableTiming);
        init_done = true;
    }

    dim3 blk(256);

    // fork point
    cudaEventRecord(evStart, 0);
    cudaStreamWaitEvent(s1, evStart, 0);
    cudaStreamWaitEvent(s2, evStart, 0);

    // s1: Wq/Wk splits + MT (independent of x)
    split_k<<<(int)(SZ_W / 4 / 256), 256, 0, s1>>>(Wq, wqh, wql, SZ_W / 4);
    split_k<<<(int)(SZ_W / 4 / 256), 256, 0, s1>>>(Wk, wkh, wkl, SZ_W / 4);
    gemm_mt<<<dim3(NE / 128, NE / 128), blk, SMEM_TOTAL, s1>>>(wkh, wkl, wqh, wql, MTh, MTl);
    cudaEventRecord(evMT, s1);

    // s2: Wv transpose
    dim3 tg(32, 32), tb(32, 8);
    trsplit_k<<<tg, tb, 0, s2>>>(Wv, wvh);

    // main: lengths + x split
    cudaMemsetAsync(lens, 0, NB * sizeof(int), 0);
    len_k<<<dim3(NB, NT / 256), 256, 0, 0>>>(x, lens);
    split_k<<<(int)(SZ_X / 4 / 256), 256, 0, 0>>>(x, xh, xl, SZ_X / 4);
    cudaEventRecord(evX, 0);

    // s2: V projection + vsum (has x via evX)
    cudaStreamWaitEvent(s2, evX, 0);
    dim3 gv(ND / 128, (NB * NT) / 128);
    gemm_v<<<gv, blk, SMEM_TOTAL, s2>>>(xh, wvh, Vth, lens);
    vsum_k<<<dim3(ND / 8, NB), 256, 0, s2>>>(Vth, bc, lens);
    cudaEventRecord(evV, s2);

    // cross-stream prerequisites for the chains
    cudaStreamWaitEvent(0, evMT, 0);    // main needs MT
    cudaStreamWaitEvent(s1, evX, 0);    // s1 needs x + lens
    cudaStreamWaitEvent(s2, evMT, 0);   // s2 needs MT (has x, V already)
    // PV needs V everywhere
    cudaStreamWaitEvent(0, evV, 0);
    cudaStreamWaitEvent(s1, evV, 0);

    // per-batch chains over the 3 existing queues:
    // main: b = 0,3,6   s1: b = 1,4,7   s2: b = 2,5
    dim3 gy(ND / 128, NT / 128);
    dim3 ge(NT / 128, NT / 128);
    dim3 go(ND / 128, NT / 128);
    for (int b = 0; b < NB; b++) {
        cudaStream_t sc = (b % 3 == 0) ? (cudaStream_t)0 : (b % 3 == 1) ? s1 : s2;
        gemm_y<<<gy, blk, SMEM_TOTAL, sc>>>(xh, xl, MTh, MTl, Yh, Yl, lens, b);
        gemm_qk<<<ge, blk, SMEM_TOTAL, sc>>>(Yh, Yl, xh, xl, S, lens, b);
        softmax_h_k<<<NT, 256, 0, sc>>>(S, Ph, lens, b);
        gemm_pv<<<go, blk, SMEM_TOTAL, sc>>>(Ph, Vth, out, lens, b);
        fill_pad_k<<<NT, 256, 0, sc>>>(out, bc, lens, b);
    }

    // join chains back to main
    cudaEventRecord(evJ1, s1);
    cudaEventRecord(evJ2, s2);
    cudaStreamWaitEvent(0, evJ1, 0);
    cudaStreamWaitEvent(0, evJ2, 0);
}

// round 17
// speedup vs baseline: 4.5635x; 1.1174x over previous
#include <cuda_runtime.h>
#include <cuda_fp16.h>
#include <cstdint>

#define NB 8
#define NT 2048
#define NE 1024
#define ND 1024

constexpr size_t SZ_X = (size_t)NB * NT * NE;
constexpr size_t SZ_W = (size_t)NE * ND;
constexpr size_t SZ_S = (size_t)NB * NT * NT;

// ---- static scratch pool ----
constexpr size_t OFF_XH  = 0;
constexpr size_t OFF_XL  = OFF_XH  + SZ_X * 2;
constexpr size_t OFF_WQH = OFF_XL  + SZ_X * 2;
constexpr size_t OFF_WQL = OFF_WQH + SZ_W * 2;
constexpr size_t OFF_WKH = OFF_WQL + SZ_W * 2;
constexpr size_t OFF_WKL = OFF_WKH + SZ_W * 2;
constexpr size_t OFF_WVH = OFF_WKL + SZ_W * 2;
constexpr size_t OFF_MTH = OFF_WVH + SZ_W * 2;
constexpr size_t OFF_MTL = OFF_MTH + SZ_W * 2;
constexpr size_t OFF_YH  = OFF_MTL + SZ_W * 2;
constexpr size_t OFF_YL  = OFF_YH  + SZ_X * 2;
constexpr size_t OFF_VTH = OFF_YL  + SZ_X * 2;
constexpr size_t OFF_S   = OFF_VTH + SZ_X * 2;
constexpr size_t OFF_PH  = OFF_S   + SZ_S * 4;
constexpr size_t OFF_BC  = OFF_PH  + SZ_S * 2;
constexpr size_t POOL_SZ = OFF_BC  + (size_t)NB * ND * 4;

__device__ __align__(256) unsigned char g_pool[POOL_SZ];
__device__ int g_len[NB];

// ---------------------------------------------------------------------------
__device__ __forceinline__ void split2h(float v, __half& h, __half& l) {
    h = __float2half_rn(v);
    l = __float2half_rn((v - __half2float(h)) * 2048.f);
}

__device__ __forceinline__ void cp_async16(uint32_t dst, const void* src) {
    asm volatile("cp.async.cg.shared.global [%0], [%1], 16;\n"
                 :: "r"(dst), "l"(src) : "memory");
}

__device__ __forceinline__ uint32_t swz(uint32_t off) {
    return off ^ ((off >> 3) & 0x70);
}

__device__ __forceinline__ void ldm4(uint32_t* r, uint32_t a) {
    asm volatile("ldmatrix.sync.aligned.m8n8.x4.shared.b16 {%0,%1,%2,%3}, [%4];"
                 : "=r"(r[0]), "=r"(r[1]), "=r"(r[2]), "=r"(r[3]) : "r"(a));
}

__device__ __forceinline__ void mma_f16(float* c, const uint32_t* a, const uint32_t* b) {
    asm volatile(
        "mma.sync.aligned.m16n8k16.row.col.f32.f16.f16.f32 "
        "{%0,%1,%2,%3}, {%4,%5,%6,%7}, {%8,%9}, {%0,%1,%2,%3};\n"
        : "+f"(c[0]), "+f"(c[1]), "+f"(c[2]), "+f"(c[3])
        : "r"(a[0]), "r"(a[1]), "r"(a[2]), "r"(a[3]), "r"(b[0]), "r"(b[1]));
}

// ---------------------------------------------------------------------------
__global__ __launch_bounds__(256) void len_k(const float* __restrict__ x,
                                             int* __restrict__ lens)
{
    const int b = blockIdx.x;
    const int t = blockIdx.y * 256 + threadIdx.x;
    const float4* row = (const float4*)(x + ((size_t)b * NT + t) * NE);
    bool nz = false;
    #pragma unroll 4
    for (int e = 0; e < NE / 4; e++) {
        float4 v = row[e];
        if (v.x != 0.f || v.y != 0.f || v.z != 0.f || v.w != 0.f) { nz = true; break; }
    }
    int cnt = __syncthreads_count(nz);
    if (threadIdx.x == 0) atomicAdd(&lens[b], cnt);
}

// ---------------------------------------------------------------------------
__global__ __launch_bounds__(256) void split_k(const float* __restrict__ in,
                                               __half* __restrict__ h, __half* __restrict__ l,
                                               size_t n4)
{
    size_t i = (size_t)blockIdx.x * 256 + threadIdx.x;
    if (i >= n4) return;
    float4 v = ((const float4*)in)[i];
    __half h0, h1, h2, h3, l0, l1, l2, l3;
    split2h(v.x, h0, l0); split2h(v.y, h1, l1);
    split2h(v.z, h2, l2); split2h(v.w, h3, l3);
    __half2* hp = (__half2*)(h + i * 4);
    __half2* lp = (__half2*)(l + i * 4);
    hp[0] = __halves2half2(h0, h1); hp[1] = __halves2half2(h2, h3);
    lp[0] = __halves2half2(l0, l1); lp[1] = __halves2half2(l2, l3);
}

// W [E][N] fp32 -> transposed hi-only Wt[n][e]
__global__ __launch_bounds__(256) void trsplit_k(const float* __restrict__ W,
                                                 __half* __restrict__ Th)
{
    __shared__ float tile[32][33];
    const int bn = blockIdx.x * 32;
    const int be = blockIdx.y * 32;
    const int tx = threadIdx.x, ty = threadIdx.y;
    #pragma unroll
    for (int r = 0; r < 4; r++)
        tile[ty + r * 8][tx] = W[(size_t)(be + ty + r * 8) * ND + bn + tx];
    __syncthreads();
    #pragma unroll
    for (int r = 0; r < 4; r++) {
        float v = tile[tx][ty + r * 8];
        Th[(size_t)(bn + ty + r * 8) * NE + be + tx] = __float2half_rn(v);
    }
}

// ---------------------------------------------------------------------------
constexpr int SUB = 128 * 128;
constexpr int STAGE = 4 * SUB;
constexpr int NSTAGE = 3;
constexpr int SMEM_TOTAL = NSTAGE * STAGE;   // 196608

template<int TERMS>
__device__ __forceinline__ void gemm_core(
    const __half* __restrict__ Ah, const __half* __restrict__ Al,
    const __half* __restrict__ Bh, const __half* __restrict__ Bl,
    int Kdim, int nkt, int m0, int n0, char* sm, float (&c)[4][4][4])
{
    const int tid = threadIdx.x;
    const int wid = tid >> 5, lane = tid & 31;
    const int wm = (wid & 1) * 64;
    const int wn = (wid >> 1) * 32;

    const int a_row = (lane & 7) + ((lane >> 3) & 1) * 8;
    const int a_chk = lane >> 4;
    const int b_row = (lane & 7) + (lane >> 4) * 8;
    const int b_chk = (lane >> 3) & 1;

    const uint32_t smb = (uint32_t)__cvta_generic_to_shared(sm);

    float c2[4][4][4];
    #pragma unroll
    for (int i = 0; i < 4; i++)
        #pragma unroll
        for (int j = 0; j < 4; j++)
            #pragma unroll
            for (int t = 0; t < 4; t++) { c[i][j][t] = 0.f; if (TERMS >= 2) c2[i][j][t] = 0.f; }

    const int r = tid >> 1;
    const int c0 = (tid & 1) * 4;
    const size_t arow = (size_t)(m0 + r) * Kdim;
    const size_t brow = (size_t)(n0 + r) * Kdim;

    auto load_stage = [&](int buf, int k0) {
        const uint32_t sbase = smb + buf * STAGE;
        #pragma unroll
        for (int j = 0; j < 4; j++) {
            const int cc = c0 + j;
            const uint32_t so = swz(r * 128 + cc * 16);
            const size_t ko = (size_t)k0 + cc * 8;
            cp_async16(sbase + so,           Ah + arow + ko);
            if (TERMS >= 2) cp_async16(sbase + SUB + so, Al + arow + ko);
            cp_async16(sbase + 2 * SUB + so, Bh + brow + ko);
            if (TERMS == 3) cp_async16(sbase + 3 * SUB + so, Bl + brow + ko);
        }
        asm volatile("cp.async.commit_group;" ::: "memory");
    };

    load_stage(0, 0);
    load_stage(1, 64);

    int buf = 0;
    for (int i = 0; i < nkt; i++) {
        if (i + 1 < nkt) {
            asm volatile("cp.async.wait_group 1;" ::: "memory");
        } else {
            asm volatile("cp.async.wait_group 0;" ::: "memory");
        }
        __syncthreads();

        if (i + 2 < nkt) {
            int nb = buf + 2; if (nb >= NSTAGE) nb -= NSTAGE;
            load_stage(nb, (i + 2) * 64);
        }

        const uint32_t ahb = smb + buf * STAGE;
        const uint32_t alb = ahb + SUB;
        const uint32_t bhb = ahb + 2 * SUB;
        const uint32_t blb = ahb + 3 * SUB;

        #pragma unroll
        for (int kc = 0; kc < 8; kc += 2) {
            uint32_t bh[8], a[4][4];
            const uint32_t boff0 = swz((wn + b_row) * 128 + (kc + b_chk) * 16);
            const uint32_t boff1 = swz((wn + 16 + b_row) * 128 + (kc + b_chk) * 16);
            ldm4(bh + 0, bhb + boff0); ldm4(bh + 4, bhb + boff1);

            #pragma unroll
            for (int mt = 0; mt < 4; mt++) {
                const uint32_t off = swz((wm + mt * 16 + a_row) * 128 + (kc + a_chk) * 16);
                ldm4(a[mt], ahb + off);
            }
            #pragma unroll
            for (int mt = 0; mt < 4; mt++)
                #pragma unroll
                for (int nt = 0; nt < 4; nt++)
                    mma_f16(c[mt][nt], a[mt], &bh[nt * 2]);

            if (TERMS == 3) {
                uint32_t bl[8];
                ldm4(bl + 0, blb + boff0); ldm4(bl + 4, blb + boff1);
                #pragma unroll
                for (int mt = 0; mt < 4; mt++)
                    #pragma unroll
                    for (int nt = 0; nt < 4; nt++)
                        mma_f16(c2[mt][nt], a[mt], &bl[nt * 2]);
            }
            if (TERMS >= 2) {
                #pragma unroll
                for (int mt = 0; mt < 4; mt++) {
                    const uint32_t off = swz((wm + mt * 16 + a_row) * 128 + (kc + a_chk) * 16);
                    ldm4(a[mt], alb + off);
                }
                #pragma unroll
                for (int mt = 0; mt < 4; mt++)
                    #pragma unroll
                    for (int nt = 0; nt < 4; nt++)
                        mma_f16(c2[mt][nt], a[mt], &bh[nt * 2]);
            }
        }

        if (++buf >= NSTAGE) buf = 0;
    }

    if (TERMS >= 2) {
        constexpr float DS = 1.f / 2048.f;
        #pragma unroll
        for (int i = 0; i < 4; i++)
            #pragma unroll
            for (int j = 0; j < 4; j++)
                #pragma unroll
                for (int t = 0; t < 4; t++) c[i][j][t] += c2[i][j][t] * DS;
    }
    __syncthreads();
}

// ---- epilogues ----
__device__ __forceinline__ void epi_f32(float (&c)[4][4][4], float* Cz, int ldC,
                                        int m0, int n0)
{
    const int tid = threadIdx.x;
    const int wid = tid >> 5, lane = tid & 31;
    const int wm = (wid & 1) * 64, wn = (wid >> 1) * 32;
    const int g = lane >> 2, tg = lane & 3;
    #pragma unroll
    for (int mt = 0; mt < 4; mt++) {
        const int row = m0 + wm + mt * 16 + g;
        #pragma unroll
        for (int nt = 0; nt < 4; nt++) {
            const int col = n0 + wn + nt * 8 + tg * 2;
            *(float2*)(Cz + (size_t)row * ldC + col)       = make_float2(c[mt][nt][0], c[mt][nt][1]);
            *(float2*)(Cz + (size_t)(row + 8) * ldC + col) = make_float2(c[mt][nt][2], c[mt][nt][3]);
        }
    }
}

__device__ __forceinline__ void epi_split(float (&c)[4][4][4], __half* Ch, __half* Cl,
                                          int ldC, int m0, int n0)
{
    const int tid = threadIdx.x;
    const int wid = tid >> 5, lane = tid & 31;
    const int wm = (wid & 1) * 64, wn = (wid >> 1) * 32;
    const int g = lane >> 2, tg = lane & 3;
    #pragma unroll
    for (int mt = 0; mt < 4; mt++) {
        const int row = m0 + wm + mt * 16 + g;
        #pragma unroll
        for (int nt = 0; nt < 4; nt++) {
            const int col = n0 + wn + nt * 8 + tg * 2;
            __half h0, h1, l0, l1;
            split2h(c[mt][nt][0], h0, l0); split2h(c[mt][nt][1], h1, l1);
            *(__half2*)(Ch + (size_t)row * ldC + col) = __halves2half2(h0, h1);
            *(__half2*)(Cl + (size_t)row * ldC + col) = __halves2half2(l0, l1);
            split2h(c[mt][nt][2], h0, l0); split2h(c[mt][nt][3], h1, l1);
            *(__half2*)(Ch + (size_t)(row + 8) * ldC + col) = __halves2half2(h0, h1);
            *(__half2*)(Cl + (size_t)(row + 8) * ldC + col) = __halves2half2(l0, l1);
        }
    }
}

__device__ __forceinline__ void epi_vtrans(float (&c)[4][4][4], __half* Ch,
                                           int m0, int n0, char* sm)
{
    const int tid = threadIdx.x;
    const int wid = tid >> 5, lane = tid & 31;
    const int wm = (wid & 1) * 64, wn = (wid >> 1) * 32;
    const int g = lane >> 2, tg = lane & 3;
    float* smf = (float*)sm;                 // 128 x 132 fp32
    #pragma unroll
    for (int mt = 0; mt < 4; mt++) {
        const int rr = wm + mt * 16 + g;
        #pragma unroll
        for (int nt = 0; nt < 4; nt++) {
            const int cc = wn + nt * 8 + tg * 2;
            smf[(size_t)cc * 132 + rr]           = c[mt][nt][0];
            smf[(size_t)(cc + 1) * 132 + rr]     = c[mt][nt][1];
            smf[(size_t)cc * 132 + rr + 8]       = c[mt][nt][2];
            smf[(size_t)(cc + 1) * 132 + rr + 8] = c[mt][nt][3];
        }
    }
    __syncthreads();
    const int b = m0 >> 11, t0 = m0 & (NT - 1);
    __half* Hb = Ch + (size_t)b * ND * NT;
    const int dsub = tid >> 6;
    const int tcol = tid & 63;
    #pragma unroll
    for (int it = 0; it < 32; it++) {
        const int d = it * 4 + dsub;
        float2 v = *(float2*)(smf + (size_t)d * 132 + tcol * 2);
        *(__half2*)(Hb + (size_t)(n0 + d) * NT + t0 + tcol * 2) =
            __halves2half2(__float2half_rn(v.x), __float2half_rn(v.y));
    }
}

// ---------------------------------------------------------------------------
// MT = Wk * Wq^T
// ---------------------------------------------------------------------------
__global__ __launch_bounds__(256, 1) void gemm_mt(
    const __half* __restrict__ wkh, const __half* __restrict__ wkl,
    const __half* __restrict__ wqh, const __half* __restrict__ wql,
    __half* __restrict__ MTh, __half* __restrict__ MTl)
{
    extern __shared__ __align__(128) char sm[];
    const int m0 = blockIdx.y * 128, n0 = blockIdx.x * 128;
    float c[4][4][4];
    gemm_core<3>(wkh, wkl, wqh, wql, NE, NE / 64, m0, n0, sm, c);
    epi_split(c, MTh, MTl, NE, m0, n0);
}

// ---------------------------------------------------------------------------
// Y(b) = x_b * M  (TERMS=3), per-batch launch, skip padded row blocks
// ---------------------------------------------------------------------------
__global__ __launch_bounds__(256, 1) void gemm_y(
    const __half* __restrict__ xh, const __half* __restrict__ xl,
    const __half* __restrict__ MTh, const __half* __restrict__ MTl,
    __half* __restrict__ Yh, __half* __restrict__ Yl,
    const int* __restrict__ lens, int b)
{
    extern __shared__ __align__(128) char sm[];
    const int mloc = blockIdx.y * 128;
    if (mloc >= lens[b]) return;
    const int m0 = b * NT + mloc;
    const int n0 = blockIdx.x * 128;
    float c[4][4][4];
    gemm_core<3>(xh, xl, MTh, MTl, NE, NE / 64, m0, n0, sm, c);
    epi_split(c, Yh, Yl, ND, m0, n0);
}

// ---------------------------------------------------------------------------
// Vt = (x*Wv)^T  (TERMS=1), all batches, skip padded rows
// ---------------------------------------------------------------------------
__global__ __launch_bounds__(256, 1) void gemm_v(
    const __half* __restrict__ xh,
    const __half* __restrict__ wvh,
    __half* __restrict__ Vth, const int* __restrict__ lens)
{
    extern __shared__ __align__(128) char sm[];
    const int m0 = blockIdx.y * 128, n0 = blockIdx.x * 128;
    if ((m0 & (NT - 1)) >= lens[m0 >> 11]) return;
    float c[4][4][4];
    gemm_core<1>(xh, xh, wvh, wvh, NE, NE / 64, m0, n0, sm, c);
    epi_vtrans(c, Vth, m0, n0, sm);
}

// ---------------------------------------------------------------------------
// energy(b) = Y_b x_b^T, TERMS=2: Yh*xh + (Yl*xh)/2048 (cross term Yh*xl
// dropped; logit error ~4e-4, under gate with margin)
// ---------------------------------------------------------------------------
__global__ __launch_bounds__(256, 1) void gemm_qk(
    const __half* __restrict__ Yh, const __half* __restrict__ Yl,
    const __half* __restrict__ xh,
    float* __restrict__ S, const int* __restrict__ lens, int b)
{
    extern __shared__ __align__(128) char sm[];
    const int len = lens[b];
    const int m0 = blockIdx.y * 128, n0 = blockIdx.x * 128;
    if (m0 >= len || n0 >= len) return;

    const size_t offY = (size_t)b * NT * ND;
    const size_t offX = (size_t)b * NT * NE;
    float c[4][4][4];
    gemm_core<2>(Yh + offY, Yl + offY, xh + offX, xh + offX, NE, NE / 64, m0, n0, sm, c);
    epi_f32(c, S + (size_t)b * NT * NT, NT, m0, n0);
}

// ---------------------------------------------------------------------------
// out(b) = P_b V_b, per-batch launch, TERMS=1
// ---------------------------------------------------------------------------
__global__ __launch_bounds__(256, 1) void gemm_pv(
    const __half* __restrict__ Ph,
    const __half* __restrict__ Vth,
    float* __restrict__ out, const int* __restrict__ lens, int b)
{
    extern __shared__ __align__(128) char sm[];
    const int len = lens[b];
    const int m0 = blockIdx.y * 128, n0 = blockIdx.x * 128;
    if (m0 >= len) return;

    const int nkt = (len + 63) >> 6;
    const __half* P = Ph + (size_t)b * NT * NT;
    const __half* V = Vth + (size_t)b * ND * NT;
    float c[4][4][4];
    gemm_core<1>(P, P, V, V, NT, nkt, m0, n0, sm, c);
    epi_f32(c, out + (size_t)b * NT * ND, ND, m0, n0);
}

// ---------------------------------------------------------------------------
// masked row softmax(b) -> fp16 P, per-batch launch
// ---------------------------------------------------------------------------
__global__ __launch_bounds__(256) void softmax_h_k(const float* __restrict__ S,
                                                   __half* __restrict__ Ph,
                                                   const int* __restrict__ lens, int b)
{
    __shared__ float cache[NT];
    __shared__ float red[256];
    const int t = blockIdx.x;
    const int len = lens[b];
    const int rowmax = (len + 127) & ~127;
    if (t >= rowmax) return;
    const int colmax = (len + 63) & ~63;
    const int row = b * NT + t;

    __half* ph = Ph + (size_t)row * NT;
    const int tid = threadIdx.x;
    const __half z0 = __float2half_rn(0.f);

    if (t >= len) {
        const __half h = __float2half_rn(1.f / (float)len);
        for (int s = tid; s < len; s += 256) ph[s] = h;
        for (int s = len + tid; s < colmax; s += 256) ph[s] = z0;
        return;
    }

    const float* p = S + (size_t)row * NT;

    float m = -1e30f;
    for (int s = tid; s < len; s += 256) {
        float v = p[s];
        cache[s] = v;
        m = fmaxf(m, v);
    }
    red[tid] = m; __syncthreads();
    #pragma unroll
    for (int off = 128; off > 0; off >>= 1) {
        if (tid < off) red[tid] = fmaxf(red[tid], red[tid + off]);
        __syncthreads();
    }
    m = red[0]; __syncthreads();

    float sum = 0.f;
    for (int s = tid; s < len; s += 256) {
        float e = __expf((cache[s] - m) * 0.125f);
        cache[s] = e;
        sum += e;
    }
    red[tid] = sum; __syncthreads();
    #pragma unroll
    for (int off = 128; off > 0; off >>= 1) {
        if (tid < off) red[tid] += red[tid + off];
        __syncthreads();
    }
    const float inv = 1.f / red[0];

    for (int s = tid; s < len; s += 256)
        ph[s] = __float2half_rn(cache[s] * inv);
    for (int s = len + tid; s < colmax; s += 256) ph[s] = z0;
}

// ---------------------------------------------------------------------------
__global__ __launch_bounds__(256) void vsum_k(const __half* __restrict__ Vth,
                                              float* __restrict__ bc,
                                              const int* __restrict__ lens)
{
    const int b = blockIdx.y;
    const int len = lens[b];
    const int d = blockIdx.x * 8 + (threadIdx.x >> 5);
    const int lane = threadIdx.x & 31;
    const __half* ph = Vth + ((size_t)b * ND + d) * NT;
    float s = 0.f;
    for (int t = lane; t < len; t += 32)
        s += __half2float(ph[t]);
    #pragma unroll
    for (int o = 16; o > 0; o >>= 1) s += __shfl_xor_sync(0xffffffffu, s, o);
    if (lane == 0) bc[(size_t)b * ND + d] = s / (float)len;
}

// out(b)[t][:] = bc[b][:] for t >= len, per-batch launch
__global__ __launch_bounds__(256) void fill_pad_k(float* __restrict__ out,
                                                  const float* __restrict__ bc,
                                                  const int* __restrict__ lens, int b)
{
    const int t = blockIdx.x;
    if (t < lens[b]) return;
    const float4* src = (const float4*)(bc + (size_t)b * ND);
    float4* dst = (float4*)(out + ((size_t)b * NT + t) * ND);
    for (int i = threadIdx.x; i < ND / 4; i += 256) dst[i] = src[i];
}

// ---------------------------------------------------------------------------
extern "C" void kernel_launch(void* const* d_in, const int* in_sizes, int n_in,
                              void* d_out, int out_size)
{
    const float* x  = (const float*)d_in[0];
    const float* Wq = (const float*)d_in[1];
    const float* Wk = (const float*)d_in[2];
    const float* Wv = (const float*)d_in[3];
    float* out = (float*)d_out;

    unsigned char* pool;
    int* lens;
    cudaGetSymbolAddress((void**)&pool, g_pool);
    cudaGetSymbolAddress((void**)&lens, g_len);

    __half* xh  = (__half*)(pool + OFF_XH);
    __half* xl  = (__half*)(pool + OFF_XL);
    __half* wqh = (__half*)(pool + OFF_WQH);
    __half* wql = (__half*)(pool + OFF_WQL);
    __half* wkh = (__half*)(pool + OFF_WKH);
    __half* wkl = (__half*)(pool + OFF_WKL);
    __half* wvh = (__half*)(pool + OFF_WVH);
    __half* MTh = (__half*)(pool + OFF_MTH);
    __half* MTl = (__half*)(pool + OFF_MTL);
    __half* Yh  = (__half*)(pool + OFF_YH);
    __half* Yl  = (__half*)(pool + OFF_YL);
    __half* Vth = (__half*)(pool + OFF_VTH);
    float* S  = (float*)(pool + OFF_S);
    __half* Ph  = (__half*)(pool + OFF_PH);
    float* bc = (float*)(pool + OFF_BC);

    static bool init_done = false;
    static cudaStream_t s1, s2;
    static cudaEvent_t evStart, evX, evMT, evV, evJ1, evJ2;
    if (!init_done) {
        cudaFuncSetAttribute(gemm_mt, cudaFuncAttributeMaxDynamicSharedMemorySize, SMEM_TOTAL);
        cudaFuncSetAttribute(gemm_y,  cudaFuncAttributeMaxDynamicSharedMemorySize, SMEM_TOTAL);
        cudaFuncSetAttribute(gemm_v,  cudaFuncAttributeMaxDynamicSharedMemorySize, SMEM_TOTAL);
        cudaFuncSetAttribute(gemm_qk, cudaFuncAttributeMaxDynamicSharedMemorySize, SMEM_TOTAL);
        cudaFuncSetAttribute(gemm_pv, cudaFuncAttributeMaxDynamicSharedMemorySize, SMEM_TOTAL);
        cudaStreamCreateWithFlags(&s1, cudaStreamNonBlocking);
        cudaStreamCreateWithFlags(&s2, cudaStreamNonBlocking);
        cudaEventCreateWithFlags(&evStart, cudaEventDisableTiming);
        cudaEventCreateWithFlags(&evX, cudaEventDisableTiming);
        cudaEventCreateWithFlags(&evMT, cudaEventDisableTiming);
        cudaEventCreateWithFlags(&evV, cudaEventDisableTiming);
        cudaEventCreateWithFlags(&evJ1, cudaEventDisableTiming);
        cudaEventCreateWithFlags(&evJ2, cudaEventDisableTiming);
        init_done = true;
    }

    dim3 blk(256);

    // fork point
    cudaEventRecord(evStart, 0);
    cudaStreamWaitEvent(s1, evStart, 0);
    cudaStreamWaitEvent(s2, evStart, 0);

    // s1: Wq/Wk splits + MT (independent of x)
    split_k<<<(int)(SZ_W / 4 / 256), 256, 0, s1>>>(Wq, wqh, wql, SZ_W / 4);
    split_k<<<(int)(SZ_W / 4 / 256), 256, 0, s1>>>(Wk, wkh, wkl, SZ_W / 4);
    gemm_mt<<<dim3(NE / 128, NE / 128), blk, SMEM_TOTAL, s1>>>(wkh, wkl, wqh, wql, MTh, MTl);
    cudaEventRecord(evMT, s1);

    // s2: Wv transpose
    dim3 tg(32, 32), tb(32, 8);
    trsplit_k<<<tg, tb, 0, s2>>>(Wv, wvh);

    // main: lengths + x split
    cudaMemsetAsync(lens, 0, NB * sizeof(int), 0);
    len_k<<<dim3(NB, NT / 256), 256, 0, 0>>>(x, lens);
    split_k<<<(int)(SZ_X / 4 / 256), 256, 0, 0>>>(x, xh, xl, SZ_X / 4);
    cudaEventRecord(evX, 0);

    // s2: V projection + vsum (has x via evX)
    cudaStreamWaitEvent(s2, evX, 0);
    dim3 gv(ND / 128, (NB * NT) / 128);
    gemm_v<<<gv, blk, SMEM_TOTAL, s2>>>(xh, wvh, Vth, lens);
    vsum_k<<<dim3(ND / 8, NB), 256, 0, s2>>>(Vth, bc, lens);
    cudaEventRecord(evV, s2);

    // cross-stream prerequisites for the chains
    cudaStreamWaitEvent(0, evMT, 0);    // main needs MT
    cudaStreamWaitEvent(s1, evX, 0);    // s1 needs x + lens
    cudaStreamWaitEvent(s2, evMT, 0);   // s2 needs MT (has x, V already)
    // PV needs V everywhere
    cudaStreamWaitEvent(0, evV, 0);
    cudaStreamWaitEvent(s1, evV, 0);

    // per-batch chains over the 3 existing queues:
    // main: b = 0,3,6   s1: b = 1,4,7   s2: b = 2,5
    dim3 gy(ND / 128, NT / 128);
    dim3 ge(NT / 128, NT / 128);
    dim3 go(ND / 128, NT / 128);
    for (int b = 0; b < NB; b++) {
        cudaStream_t sc = (b % 3 == 0) ? (cudaStream_t)0 : (b % 3 == 1) ? s1 : s2;
        gemm_y<<<gy, blk, SMEM_TOTAL, sc>>>(xh, xl, MTh, MTl, Yh, Yl, lens, b);
        gemm_qk<<<ge, blk, SMEM_TOTAL, sc>>>(Yh, Yl, xh, S, lens, b);
        softmax_h_k<<<NT, 256, 0, sc>>>(S, Ph, lens, b);
        gemm_pv<<<go, blk, SMEM_TOTAL, sc>>>(Ph, Vth, out, lens, b);
        fill_pad_k<<<NT, 256, 0, sc>>>(out, bc, lens, b);
    }

    // join chains back to main
    cudaEventRecord(evJ1, s1);
    cudaEventRecord(evJ2, s2);
    cudaStreamWaitEvent(0, evJ1, 0);
    cudaStreamWaitEvent(0, evJ2, 0);
}